// round 1
// baseline (speedup 1.0000x reference)
#include <cuda_runtime.h>
#include <math.h>

#define S_LEN 2048
#define BATCH 4
#define HEADS 16
#define DKH 64
#define DMODEL 1024
#define MROWS (BATCH * S_LEN)  /* 8192 */
#define NEGV -1000000000.0f

// Scratch (device globals; no allocation allowed)
__device__ float g_q[MROWS * DMODEL];
__device__ float g_k[MROWS * DMODEL];
__device__ float g_v[MROWS * DMODEL];
__device__ float g_ao[MROWS * DMODEL];

// ---------------------------------------------------------------------------
// GEMM: C[m,n] = sum_k A[m,k] * W[n,k] + bias[n]
// A: [M, K] row-major, W: [N, K] row-major (i.e. computes A @ W^T + b)
// MODE 0: C written [M, N] row-major
// MODE 1: C written head-split: [(b*H + h)*S + s]*64 + dk  (b=m/S, s=m%S,
//         h=n/64, dk=n%64)
// Fixed M=8192, N=K=1024. Tiles 128x128x8, 256 threads, 8x8 per thread.
// ---------------------------------------------------------------------------
template <int MODE>
__global__ void __launch_bounds__(256)
gemm_bias_kernel(const float* __restrict__ A, const float* __restrict__ W,
                 const float* __restrict__ bias, float* __restrict__ C)
{
    const int K = DMODEL;
    const int N = DMODEL;
    __shared__ float As[8][128];
    __shared__ float Bs[8][128];

    float acc[8][8];
#pragma unroll
    for (int i = 0; i < 8; i++)
#pragma unroll
        for (int j = 0; j < 8; j++) acc[i][j] = 0.0f;

    const int tid = threadIdx.x;
    const int tm = (tid >> 4) * 8;   // 0..120
    const int tn = (tid & 15) * 8;   // 0..120
    const int m0 = blockIdx.y * 128;
    const int n0 = blockIdx.x * 128;

    const int lr = tid >> 1;         // 0..127
    const int lc = (tid & 1) * 4;    // 0 or 4

    const float* Ap = A + (size_t)(m0 + lr) * K + lc;
    const float* Wp = W + (size_t)(n0 + lr) * K + lc;

    for (int k0 = 0; k0 < K; k0 += 8) {
        float4 a4 = *(const float4*)(Ap + k0);
        float4 w4 = *(const float4*)(Wp + k0);
        As[lc + 0][lr] = a4.x; As[lc + 1][lr] = a4.y;
        As[lc + 2][lr] = a4.z; As[lc + 3][lr] = a4.w;
        Bs[lc + 0][lr] = w4.x; Bs[lc + 1][lr] = w4.y;
        Bs[lc + 2][lr] = w4.z; Bs[lc + 3][lr] = w4.w;
        __syncthreads();
#pragma unroll
        for (int kk = 0; kk < 8; kk++) {
            float a[8], b[8];
            float4 t0 = *(const float4*)&As[kk][tm];
            float4 t1 = *(const float4*)&As[kk][tm + 4];
            a[0]=t0.x; a[1]=t0.y; a[2]=t0.z; a[3]=t0.w;
            a[4]=t1.x; a[5]=t1.y; a[6]=t1.z; a[7]=t1.w;
            float4 u0 = *(const float4*)&Bs[kk][tn];
            float4 u1 = *(const float4*)&Bs[kk][tn + 4];
            b[0]=u0.x; b[1]=u0.y; b[2]=u0.z; b[3]=u0.w;
            b[4]=u1.x; b[5]=u1.y; b[6]=u1.z; b[7]=u1.w;
#pragma unroll
            for (int i = 0; i < 8; i++)
#pragma unroll
                for (int j = 0; j < 8; j++)
                    acc[i][j] = fmaf(a[i], b[j], acc[i][j]);
        }
        __syncthreads();
    }

    // bias for this thread's 8 columns
    float bvals[8];
    {
        float4 b0 = *(const float4*)&bias[n0 + tn];
        float4 b1 = *(const float4*)&bias[n0 + tn + 4];
        bvals[0]=b0.x; bvals[1]=b0.y; bvals[2]=b0.z; bvals[3]=b0.w;
        bvals[4]=b1.x; bvals[5]=b1.y; bvals[6]=b1.z; bvals[7]=b1.w;
    }

#pragma unroll
    for (int i = 0; i < 8; i++) {
        const int m = m0 + tm + i;
        float4 r0, r1;
        r0.x = acc[i][0] + bvals[0]; r0.y = acc[i][1] + bvals[1];
        r0.z = acc[i][2] + bvals[2]; r0.w = acc[i][3] + bvals[3];
        r1.x = acc[i][4] + bvals[4]; r1.y = acc[i][5] + bvals[5];
        r1.z = acc[i][6] + bvals[6]; r1.w = acc[i][7] + bvals[7];
        if (MODE == 0) {
            float* dst = &C[(size_t)m * N + n0 + tn];
            *(float4*)(dst)     = r0;
            *(float4*)(dst + 4) = r1;
        } else {
            const int bi = m >> 11;       // / 2048
            const int srow = m & 2047;
            const int n = n0 + tn;
            const int h = n >> 6;
            const int dk = n & 63;
            float* dst = &C[(((size_t)(bi * HEADS + h) * S_LEN + srow)) * DKH + dk];
            *(float4*)(dst)     = r0;
            *(float4*)(dst + 4) = r1;
        }
    }
}

// ---------------------------------------------------------------------------
// Flash attention (fp32, online softmax).
// Q/K/V layout: [(b*H + h)*S + s]*64 + d.
// Block: 256 threads, handles one (b,h) and 64 query rows; iterates over
// 32 key tiles of 64. Output written [b, s, h*64 + d] for final GEMM.
// smem: q_s [d][row], kp_s: K as [d][col] then reused for P as [col][row],
// v_s [row][d].  3 * 16KB = 48KB exactly.
// ---------------------------------------------------------------------------
__global__ void __launch_bounds__(256)
flash_attn_kernel(const float* __restrict__ Q, const float* __restrict__ K,
                  const float* __restrict__ V, const int* __restrict__ mask,
                  float* __restrict__ O)
{
    __shared__ float q_s[64][64];   // [d][row]
    __shared__ float kp_s[64][64];  // K: [d][col]  / later P: [col][row]
    __shared__ float v_s[64][64];   // [row][d]

    const int tid = threadIdx.x;
    const int tx = tid & 15;        // column group (4 cols)
    const int ty = tid >> 4;        // row group (4 rows)
    const int bh = blockIdx.y;
    const int b  = bh >> 4;
    const int h  = bh & 15;
    const int q0 = blockIdx.x * 64;

    const float* Qb = Q + (size_t)bh * S_LEN * DKH + (size_t)q0 * DKH;
    const float* Kb = K + (size_t)bh * S_LEN * DKH;
    const float* Vb = V + (size_t)bh * S_LEN * DKH;
    const int* mb = mask + b * S_LEN;

    // Load Q tile transposed: q_s[d][row]
#pragma unroll
    for (int i = 0; i < 4; i++) {
        int idx = tid + i * 256;          // float4 index, 1024 total
        int r = idx >> 4;
        int c4 = (idx & 15) * 4;
        float4 v4 = *(const float4*)(Qb + r * DKH + c4);
        q_s[c4 + 0][r] = v4.x; q_s[c4 + 1][r] = v4.y;
        q_s[c4 + 2][r] = v4.z; q_s[c4 + 3][r] = v4.w;
    }

    float o[4][4];
#pragma unroll
    for (int i = 0; i < 4; i++)
#pragma unroll
        for (int j = 0; j < 4; j++) o[i][j] = 0.0f;
    float m_r[4], l_r[4];
#pragma unroll
    for (int i = 0; i < 4; i++) { m_r[i] = -INFINITY; l_r[i] = 0.0f; }

    __syncthreads();

    for (int kb = 0; kb < S_LEN; kb += 64) {
        // Load K tile transposed -> kp_s[d][col]; V natural -> v_s[row][d]
#pragma unroll
        for (int i = 0; i < 4; i++) {
            int idx = tid + i * 256;
            int r = idx >> 4;
            int c4 = (idx & 15) * 4;
            float4 kv = *(const float4*)(Kb + (size_t)(kb + r) * DKH + c4);
            kp_s[c4 + 0][r] = kv.x; kp_s[c4 + 1][r] = kv.y;
            kp_s[c4 + 2][r] = kv.z; kp_s[c4 + 3][r] = kv.w;
            float4 vv = *(const float4*)(Vb + (size_t)(kb + r) * DKH + c4);
            *(float4*)&v_s[r][c4] = vv;
        }
        __syncthreads();

        // S = Q K^T (64x64, 4x4 per thread)
        float s[4][4];
#pragma unroll
        for (int i = 0; i < 4; i++)
#pragma unroll
            for (int j = 0; j < 4; j++) s[i][j] = 0.0f;
#pragma unroll
        for (int d = 0; d < 64; d++) {
            float4 aq = *(const float4*)&q_s[d][ty * 4];
            float4 bk = *(const float4*)&kp_s[d][tx * 4];
            float a_[4] = {aq.x, aq.y, aq.z, aq.w};
            float b_[4] = {bk.x, bk.y, bk.z, bk.w};
#pragma unroll
            for (int i = 0; i < 4; i++)
#pragma unroll
                for (int j = 0; j < 4; j++)
                    s[i][j] = fmaf(a_[i], b_[j], s[i][j]);
        }

        // mask + scale + row max
        float rm[4];
#pragma unroll
        for (int i = 0; i < 4; i++) {
            rm[i] = -INFINITY;
#pragma unroll
            for (int j = 0; j < 4; j++) {
                int kc = kb + tx * 4 + j;
                float sv = (mb[kc] == 0) ? NEGV : s[i][j] * 0.125f;
                s[i][j] = sv;
                rm[i] = fmaxf(rm[i], sv);
            }
        }
#pragma unroll
        for (int off = 1; off < 16; off <<= 1) {
#pragma unroll
            for (int i = 0; i < 4; i++)
                rm[i] = fmaxf(rm[i], __shfl_xor_sync(0xffffffffu, rm[i], off));
        }

        // online softmax update
        float c[4], rs[4];
#pragma unroll
        for (int i = 0; i < 4; i++) {
            float mn = fmaxf(m_r[i], rm[i]);
            c[i] = __expf(m_r[i] - mn);
            m_r[i] = mn;
        }
        float p[4][4];
#pragma unroll
        for (int i = 0; i < 4; i++) {
            rs[i] = 0.0f;
#pragma unroll
            for (int j = 0; j < 4; j++) {
                p[i][j] = __expf(s[i][j] - m_r[i]);
                rs[i] += p[i][j];
            }
        }
#pragma unroll
        for (int off = 1; off < 16; off <<= 1) {
#pragma unroll
            for (int i = 0; i < 4; i++)
                rs[i] += __shfl_xor_sync(0xffffffffu, rs[i], off);
        }
#pragma unroll
        for (int i = 0; i < 4; i++) {
            l_r[i] = l_r[i] * c[i] + rs[i];
#pragma unroll
            for (int j = 0; j < 4; j++) o[i][j] *= c[i];
        }

        __syncthreads();   // everyone done reading kp_s as K

        // store P transposed: kp_s[col][row]
#pragma unroll
        for (int j = 0; j < 4; j++)
#pragma unroll
            for (int i = 0; i < 4; i++)
                kp_s[tx * 4 + j][ty * 4 + i] = p[i][j];
        __syncthreads();

        // O += P V  (inner over 64 key rows)
#pragma unroll
        for (int j = 0; j < 64; j++) {
            float4 ap = *(const float4*)&kp_s[j][ty * 4];
            float4 av = *(const float4*)&v_s[j][tx * 4];
            float pa[4] = {ap.x, ap.y, ap.z, ap.w};
            float vb[4] = {av.x, av.y, av.z, av.w};
#pragma unroll
            for (int i = 0; i < 4; i++)
#pragma unroll
                for (int jj = 0; jj < 4; jj++)
                    o[i][jj] = fmaf(pa[i], vb[jj], o[i][jj]);
        }
        __syncthreads();   // before next tile overwrites kp_s / v_s
    }

    // epilogue: normalize and write [b, s, h*64+d]
#pragma unroll
    for (int i = 0; i < 4; i++) {
        float inv = 1.0f / l_r[i];
        int qrow = q0 + ty * 4 + i;
        float4 w;
        w.x = o[i][0] * inv; w.y = o[i][1] * inv;
        w.z = o[i][2] * inv; w.w = o[i][3] * inv;
        *(float4*)&O[((size_t)(b * S_LEN + qrow)) * DMODEL + h * DKH + tx * 4] = w;
    }
}

// ---------------------------------------------------------------------------
extern "C" void kernel_launch(void* const* d_in, const int* in_sizes, int n_in,
                              void* d_out, int out_size)
{
    const float* query = (const float*)d_in[0];
    const float* key   = (const float*)d_in[1];
    const float* value = (const float*)d_in[2];
    const int*   mask  = (const int*)d_in[3];
    const float* Wq = (const float*)d_in[4];
    const float* bq = (const float*)d_in[5];
    const float* Wk = (const float*)d_in[6];
    const float* bk = (const float*)d_in[7];
    const float* Wv = (const float*)d_in[8];
    const float* bv = (const float*)d_in[9];
    const float* Wo = (const float*)d_in[10];
    const float* bo = (const float*)d_in[11];
    float* out = (float*)d_out;

    float *q, *k, *v, *ao;
    cudaGetSymbolAddress((void**)&q,  g_q);
    cudaGetSymbolAddress((void**)&k,  g_k);
    cudaGetSymbolAddress((void**)&v,  g_v);
    cudaGetSymbolAddress((void**)&ao, g_ao);

    dim3 gg(DMODEL / 128, MROWS / 128);   // (8, 64)
    gemm_bias_kernel<1><<<gg, 256>>>(query, Wq, bq, q);
    gemm_bias_kernel<1><<<gg, 256>>>(key,   Wk, bk, k);
    gemm_bias_kernel<1><<<gg, 256>>>(value, Wv, bv, v);

    dim3 fg(S_LEN / 64, BATCH * HEADS);   // (32, 64)
    flash_attn_kernel<<<fg, 256>>>(q, k, v, mask, ao);

    gemm_bias_kernel<0><<<gg, 256>>>(ao, Wo, bo, out);
}

// round 4
// speedup vs baseline: 1.2894x; 1.2894x over previous
#include <cuda_runtime.h>
#include <cuda_bf16.h>
#include <math.h>
#include <stdint.h>

#define S_LEN 2048
#define BATCH 4
#define HEADS 16
#define DKH 64
#define DMODEL 1024
#define MROWS (BATCH * S_LEN)  /* 8192 */
#define NEGV -1000000000.0f

// ---------------------------------------------------------------------------
// Scratch (device globals; no allocation allowed)
// ---------------------------------------------------------------------------
__device__ float g_q[MROWS * DMODEL];
__device__ float g_k[MROWS * DMODEL];
__device__ float g_v[MROWS * DMODEL];
__device__ float g_ao[MROWS * DMODEL];
__device__ __nv_bfloat16 g_ahi[MROWS * DMODEL];
__device__ __nv_bfloat16 g_alo[MROWS * DMODEL];
__device__ __nv_bfloat16 g_whi[4][DMODEL * DMODEL];
__device__ __nv_bfloat16 g_wlo[4][DMODEL * DMODEL];

__device__ __forceinline__ uint32_t smem_u32(const void* p) {
    uint32_t addr;
    asm("{ .reg .u64 tmp; cvta.to.shared.u64 tmp, %1; cvt.u32.u64 %0, tmp; }"
        : "=r"(addr) : "l"(p));
    return addr;
}

__device__ __forceinline__ uint32_t pack2(__nv_bfloat16 a, __nv_bfloat16 b) {
    return (uint32_t)__bfloat16_as_ushort(a) |
           ((uint32_t)__bfloat16_as_ushort(b) << 16);
}

// ---------------------------------------------------------------------------
// Split fp32 -> hi/lo bf16 planes. in: n4 float4s.
// ---------------------------------------------------------------------------
__global__ void __launch_bounds__(256)
split_kernel(const float4* __restrict__ in, uint2* __restrict__ hi,
             uint2* __restrict__ lo, int n4)
{
    int i = blockIdx.x * blockDim.x + threadIdx.x;
    if (i >= n4) return;
    float4 f = in[i];
    float fs[4] = {f.x, f.y, f.z, f.w};
    __nv_bfloat16 h[4], l[4];
#pragma unroll
    for (int j = 0; j < 4; j++) {
        h[j] = __float2bfloat16_rn(fs[j]);
        l[j] = __float2bfloat16_rn(fs[j] - __bfloat162float(h[j]));
    }
    hi[i] = make_uint2(pack2(h[0], h[1]), pack2(h[2], h[3]));
    lo[i] = make_uint2(pack2(l[0], l[1]), pack2(l[2], l[3]));
}

// ---------------------------------------------------------------------------
// Tensor-core GEMM: C[m,n] = sum_k A[m,k]*W[n,k] + bias[n]
// A,W given as bf16 hi/lo planes. mma.sync m16n8k16, 3 MMAs per hi/lo pair.
// Block 128x128x(k32), 512 threads, 16 warps (4x4), warp tile 32x32.
// 2-stage cp.async pipeline. Dynamic smem 81920B.
// MODE 0: row-major out. MODE 1: head-split out.
// ---------------------------------------------------------------------------
#define BK 32
#define PAD 40                 /* row stride in bf16 elems */
#define TILE_E (128 * PAD)     /* elems per tile plane */
#define STAGE_E (4 * TILE_E)   /* A_hi, A_lo, B_hi, B_lo */
#define GEMM_SMEM (2 * STAGE_E * 2)

__device__ __forceinline__ void ldm_x4(uint32_t* r, uint32_t addr) {
    asm volatile("ldmatrix.sync.aligned.m8n8.x4.shared.b16 {%0,%1,%2,%3}, [%4];"
                 : "=r"(r[0]), "=r"(r[1]), "=r"(r[2]), "=r"(r[3]) : "r"(addr));
}

__device__ __forceinline__ void mma_bf16(float* c, const uint32_t* a, const uint32_t* b) {
    asm volatile(
        "mma.sync.aligned.m16n8k16.row.col.f32.bf16.bf16.f32 "
        "{%0,%1,%2,%3}, {%4,%5,%6,%7}, {%8,%9}, {%0,%1,%2,%3};"
        : "+f"(c[0]), "+f"(c[1]), "+f"(c[2]), "+f"(c[3])
        : "r"(a[0]), "r"(a[1]), "r"(a[2]), "r"(a[3]), "r"(b[0]), "r"(b[1]));
}

__device__ __forceinline__ void cp16(uint32_t saddr, const void* gaddr) {
    asm volatile("cp.async.cg.shared.global [%0], [%1], 16;"
                 :: "r"(saddr), "l"(gaddr));
}

template <int MODE>
__global__ void __launch_bounds__(512)
gemm_mma_kernel(const __nv_bfloat16* __restrict__ Ahi,
                const __nv_bfloat16* __restrict__ Alo,
                const __nv_bfloat16* __restrict__ Whi,
                const __nv_bfloat16* __restrict__ Wlo,
                const float* __restrict__ bias, float* __restrict__ C)
{
    extern __shared__ char dsm[];
    const uint32_t sb = smem_u32(dsm);
    const int tid = threadIdx.x;
    const int wid = tid >> 5;
    const int lane = tid & 31;
    const int m0 = blockIdx.y * 128;
    const int n0 = blockIdx.x * 128;
    const int wm = wid & 3;          // warp row
    const int wn = wid >> 2;         // warp col

    float acc[2][4][4];
#pragma unroll
    for (int a = 0; a < 2; a++)
#pragma unroll
        for (int b = 0; b < 4; b++)
#pragma unroll
            for (int c = 0; c < 4; c++) acc[a][b][c] = 0.0f;

    // prefetch lambda: 4 cp.async 16B chunks per thread per stage
    auto prefetch = [&](int iter) {
        if (iter < DMODEL / BK) {
            const int k0 = iter * BK;
            const uint32_t stage_base = sb + (uint32_t)((iter & 1) * STAGE_E * 2);
#pragma unroll
            for (int t = 0; t < 4; t++) {
                const int c = tid + t * 512;        // 0..2047
                const int tile = c >> 9;            // 0..3
                const int w = c & 511;
                const int row = w >> 2;
                const int kc = (w & 3) * 8;
                const uint32_t saddr =
                    stage_base + (uint32_t)((tile * TILE_E + row * PAD + kc) * 2);
                const __nv_bfloat16* gp;
                if (tile == 0)      gp = Ahi + (size_t)(m0 + row) * DMODEL + k0 + kc;
                else if (tile == 1) gp = Alo + (size_t)(m0 + row) * DMODEL + k0 + kc;
                else if (tile == 2) gp = Whi + (size_t)(n0 + row) * DMODEL + k0 + kc;
                else                gp = Wlo + (size_t)(n0 + row) * DMODEL + k0 + kc;
                cp16(saddr, gp);
            }
        }
        asm volatile("cp.async.commit_group;");
    };

    // ldmatrix lane offsets
    const int a_row = lane & 15;
    const int a_k   = (lane >> 4) << 3;
    const int b_n   = ((lane >> 4) << 3) + (lane & 7);
    const int b_k   = lane & 8;

    prefetch(0);

    for (int iter = 0; iter < DMODEL / BK; iter++) {
        prefetch(iter + 1);
        asm volatile("cp.async.wait_group 1;");
        __syncthreads();

        const uint32_t st = sb + (uint32_t)((iter & 1) * STAGE_E * 2);
#pragma unroll
        for (int ks = 0; ks < BK; ks += 16) {
            uint32_t ah[2][4], al[2][4];
#pragma unroll
            for (int mt = 0; mt < 2; mt++) {
                const int row = wm * 32 + mt * 16 + a_row;
                const uint32_t off = (uint32_t)((row * PAD + ks + a_k) * 2);
                ldm_x4(ah[mt], st + 0 * TILE_E * 2 + off);
                ldm_x4(al[mt], st + 1 * TILE_E * 2 + off);
            }
            uint32_t bh[4][2], bl[4][2];
#pragma unroll
            for (int np = 0; np < 2; np++) {
                const int n = wn * 32 + np * 16 + b_n;
                const uint32_t off = (uint32_t)((n * PAD + ks + b_k) * 2);
                uint32_t r[4];
                ldm_x4(r, st + 2 * TILE_E * 2 + off);
                bh[2 * np][0] = r[0]; bh[2 * np][1] = r[1];
                bh[2 * np + 1][0] = r[2]; bh[2 * np + 1][1] = r[3];
                ldm_x4(r, st + 3 * TILE_E * 2 + off);
                bl[2 * np][0] = r[0]; bl[2 * np][1] = r[1];
                bl[2 * np + 1][0] = r[2]; bl[2 * np + 1][1] = r[3];
            }
#pragma unroll
            for (int mt = 0; mt < 2; mt++)
#pragma unroll
                for (int nt = 0; nt < 4; nt++) {
                    mma_bf16(acc[mt][nt], ah[mt], bh[nt]);
                    mma_bf16(acc[mt][nt], al[mt], bh[nt]);
                    mma_bf16(acc[mt][nt], ah[mt], bl[nt]);
                }
        }
        __syncthreads();
    }

    // epilogue
    const int qrow = lane >> 2;
    const int qcol = (lane & 3) * 2;
#pragma unroll
    for (int mt = 0; mt < 2; mt++) {
#pragma unroll
        for (int nt = 0; nt < 4; nt++) {
            const int m = m0 + wm * 32 + mt * 16 + qrow;
            const int n = n0 + wn * 32 + nt * 8 + qcol;
            const float b0 = bias[n], b1 = bias[n + 1];
            float2 r0 = make_float2(acc[mt][nt][0] + b0, acc[mt][nt][1] + b1);
            float2 r1 = make_float2(acc[mt][nt][2] + b0, acc[mt][nt][3] + b1);
            if (MODE == 0) {
                *(float2*)&C[(size_t)m * DMODEL + n] = r0;
                *(float2*)&C[(size_t)(m + 8) * DMODEL + n] = r1;
            } else {
                const int h = n >> 6, dk = n & 63;
                {
                    const int b = m >> 11, s = m & 2047;
                    *(float2*)&C[(((size_t)(b * HEADS + h) * S_LEN + s)) * DKH + dk] = r0;
                }
                {
                    const int m2 = m + 8;
                    const int b = m2 >> 11, s = m2 & 2047;
                    *(float2*)&C[(((size_t)(b * HEADS + h) * S_LEN + s)) * DKH + dk] = r1;
                }
            }
        }
    }
}

// ---------------------------------------------------------------------------
// Flash attention (fp32, online softmax) — unchanged from R1.
// ---------------------------------------------------------------------------
__global__ void __launch_bounds__(256)
flash_attn_kernel(const float* __restrict__ Q, const float* __restrict__ K,
                  const float* __restrict__ V, const int* __restrict__ mask,
                  float* __restrict__ O)
{
    __shared__ float q_s[64][64];
    __shared__ float kp_s[64][64];
    __shared__ float v_s[64][64];

    const int tid = threadIdx.x;
    const int tx = tid & 15;
    const int ty = tid >> 4;
    const int bh = blockIdx.y;
    const int b  = bh >> 4;
    const int h  = bh & 15;
    const int q0 = blockIdx.x * 64;

    const float* Qb = Q + (size_t)bh * S_LEN * DKH + (size_t)q0 * DKH;
    const float* Kb = K + (size_t)bh * S_LEN * DKH;
    const float* Vb = V + (size_t)bh * S_LEN * DKH;
    const int* mb = mask + b * S_LEN;

#pragma unroll
    for (int i = 0; i < 4; i++) {
        int idx = tid + i * 256;
        int r = idx >> 4;
        int c4 = (idx & 15) * 4;
        float4 v4 = *(const float4*)(Qb + r * DKH + c4);
        q_s[c4 + 0][r] = v4.x; q_s[c4 + 1][r] = v4.y;
        q_s[c4 + 2][r] = v4.z; q_s[c4 + 3][r] = v4.w;
    }

    float o[4][4];
#pragma unroll
    for (int i = 0; i < 4; i++)
#pragma unroll
        for (int j = 0; j < 4; j++) o[i][j] = 0.0f;
    float m_r[4], l_r[4];
#pragma unroll
    for (int i = 0; i < 4; i++) { m_r[i] = -INFINITY; l_r[i] = 0.0f; }

    __syncthreads();

    for (int kb = 0; kb < S_LEN; kb += 64) {
#pragma unroll
        for (int i = 0; i < 4; i++) {
            int idx = tid + i * 256;
            int r = idx >> 4;
            int c4 = (idx & 15) * 4;
            float4 kv = *(const float4*)(Kb + (size_t)(kb + r) * DKH + c4);
            kp_s[c4 + 0][r] = kv.x; kp_s[c4 + 1][r] = kv.y;
            kp_s[c4 + 2][r] = kv.z; kp_s[c4 + 3][r] = kv.w;
            float4 vv = *(const float4*)(Vb + (size_t)(kb + r) * DKH + c4);
            *(float4*)&v_s[r][c4] = vv;
        }
        __syncthreads();

        float s[4][4];
#pragma unroll
        for (int i = 0; i < 4; i++)
#pragma unroll
            for (int j = 0; j < 4; j++) s[i][j] = 0.0f;
#pragma unroll
        for (int d = 0; d < 64; d++) {
            float4 aq = *(const float4*)&q_s[d][ty * 4];
            float4 bk = *(const float4*)&kp_s[d][tx * 4];
            float a_[4] = {aq.x, aq.y, aq.z, aq.w};
            float b_[4] = {bk.x, bk.y, bk.z, bk.w};
#pragma unroll
            for (int i = 0; i < 4; i++)
#pragma unroll
                for (int j = 0; j < 4; j++)
                    s[i][j] = fmaf(a_[i], b_[j], s[i][j]);
        }

        float rm[4];
#pragma unroll
        for (int i = 0; i < 4; i++) {
            rm[i] = -INFINITY;
#pragma unroll
            for (int j = 0; j < 4; j++) {
                int kc = kb + tx * 4 + j;
                float sv = (mb[kc] == 0) ? NEGV : s[i][j] * 0.125f;
                s[i][j] = sv;
                rm[i] = fmaxf(rm[i], sv);
            }
        }
#pragma unroll
        for (int off = 1; off < 16; off <<= 1) {
#pragma unroll
            for (int i = 0; i < 4; i++)
                rm[i] = fmaxf(rm[i], __shfl_xor_sync(0xffffffffu, rm[i], off));
        }

        float c[4], rs[4];
#pragma unroll
        for (int i = 0; i < 4; i++) {
            float mn = fmaxf(m_r[i], rm[i]);
            c[i] = __expf(m_r[i] - mn);
            m_r[i] = mn;
        }
        float p[4][4];
#pragma unroll
        for (int i = 0; i < 4; i++) {
            rs[i] = 0.0f;
#pragma unroll
            for (int j = 0; j < 4; j++) {
                p[i][j] = __expf(s[i][j] - m_r[i]);
                rs[i] += p[i][j];
            }
        }
#pragma unroll
        for (int off = 1; off < 16; off <<= 1) {
#pragma unroll
            for (int i = 0; i < 4; i++)
                rs[i] += __shfl_xor_sync(0xffffffffu, rs[i], off);
        }
#pragma unroll
        for (int i = 0; i < 4; i++) {
            l_r[i] = l_r[i] * c[i] + rs[i];
#pragma unroll
            for (int j = 0; j < 4; j++) o[i][j] *= c[i];
        }

        __syncthreads();

#pragma unroll
        for (int j = 0; j < 4; j++)
#pragma unroll
            for (int i = 0; i < 4; i++)
                kp_s[tx * 4 + j][ty * 4 + i] = p[i][j];
        __syncthreads();

#pragma unroll
        for (int j = 0; j < 64; j++) {
            float4 ap = *(const float4*)&kp_s[j][ty * 4];
            float4 av = *(const float4*)&v_s[j][tx * 4];
            float pa[4] = {ap.x, ap.y, ap.z, ap.w};
            float vb[4] = {av.x, av.y, av.z, av.w};
#pragma unroll
            for (int i = 0; i < 4; i++)
#pragma unroll
                for (int jj = 0; jj < 4; jj++)
                    o[i][jj] = fmaf(pa[i], vb[jj], o[i][jj]);
        }
        __syncthreads();
    }

#pragma unroll
    for (int i = 0; i < 4; i++) {
        float inv = 1.0f / l_r[i];
        int qrow = q0 + ty * 4 + i;
        float4 w;
        w.x = o[i][0] * inv; w.y = o[i][1] * inv;
        w.z = o[i][2] * inv; w.w = o[i][3] * inv;
        *(float4*)&O[((size_t)(b * S_LEN + qrow)) * DMODEL + h * DKH + tx * 4] = w;
    }
}

// ---------------------------------------------------------------------------
extern "C" void kernel_launch(void* const* d_in, const int* in_sizes, int n_in,
                              void* d_out, int out_size)
{
    const float* query = (const float*)d_in[0];
    const float* key   = (const float*)d_in[1];
    const float* value = (const float*)d_in[2];
    const int*   mask  = (const int*)d_in[3];
    const float* Wmat[4] = {(const float*)d_in[4], (const float*)d_in[6],
                            (const float*)d_in[8], (const float*)d_in[10]};
    const float* bvec[4] = {(const float*)d_in[5], (const float*)d_in[7],
                            (const float*)d_in[9], (const float*)d_in[11]};
    float* out = (float*)d_out;

    float *q, *k, *v, *ao;
    __nv_bfloat16 *ahi, *alo, *whi, *wlo;
    cudaGetSymbolAddress((void**)&q,  g_q);
    cudaGetSymbolAddress((void**)&k,  g_k);
    cudaGetSymbolAddress((void**)&v,  g_v);
    cudaGetSymbolAddress((void**)&ao, g_ao);
    cudaGetSymbolAddress((void**)&ahi, g_ahi);
    cudaGetSymbolAddress((void**)&alo, g_alo);
    cudaGetSymbolAddress((void**)&whi, g_whi);
    cudaGetSymbolAddress((void**)&wlo, g_wlo);

    cudaFuncSetAttribute(gemm_mma_kernel<0>,
                         cudaFuncAttributeMaxDynamicSharedMemorySize, GEMM_SMEM);
    cudaFuncSetAttribute(gemm_mma_kernel<1>,
                         cudaFuncAttributeMaxDynamicSharedMemorySize, GEMM_SMEM);

    const int nw4 = DMODEL * DMODEL / 4;
    const int na4 = MROWS * DMODEL / 4;

    // split all 4 weight matrices
    for (int i = 0; i < 4; i++) {
        split_kernel<<<(nw4 + 255) / 256, 256>>>(
            (const float4*)Wmat[i], (uint2*)(whi + (size_t)i * DMODEL * DMODEL),
            (uint2*)(wlo + (size_t)i * DMODEL * DMODEL), nw4);
    }

    dim3 gg(DMODEL / 128, MROWS / 128);   // (8, 64)

    // Q projection
    split_kernel<<<(na4 + 255) / 256, 256>>>((const float4*)query, (uint2*)ahi,
                                             (uint2*)alo, na4);
    gemm_mma_kernel<1><<<gg, 512, GEMM_SMEM>>>(ahi, alo, whi, wlo, bvec[0], q);
    // K projection
    split_kernel<<<(na4 + 255) / 256, 256>>>((const float4*)key, (uint2*)ahi,
                                             (uint2*)alo, na4);
    gemm_mma_kernel<1><<<gg, 512, GEMM_SMEM>>>(
        ahi, alo, whi + (size_t)1 * DMODEL * DMODEL,
        wlo + (size_t)1 * DMODEL * DMODEL, bvec[1], k);
    // V projection
    split_kernel<<<(na4 + 255) / 256, 256>>>((const float4*)value, (uint2*)ahi,
                                             (uint2*)alo, na4);
    gemm_mma_kernel<1><<<gg, 512, GEMM_SMEM>>>(
        ahi, alo, whi + (size_t)2 * DMODEL * DMODEL,
        wlo + (size_t)2 * DMODEL * DMODEL, bvec[2], v);

    // attention
    dim3 fg(S_LEN / 64, BATCH * HEADS);   // (32, 64)
    flash_attn_kernel<<<fg, 256>>>(q, k, v, mask, ao);

    // output projection
    split_kernel<<<(na4 + 255) / 256, 256>>>((const float4*)ao, (uint2*)ahi,
                                             (uint2*)alo, na4);
    gemm_mma_kernel<0><<<gg, 512, GEMM_SMEM>>>(
        ahi, alo, whi + (size_t)3 * DMODEL * DMODEL,
        wlo + (size_t)3 * DMODEL * DMODEL, bvec[3], out);
}

// round 5
// speedup vs baseline: 2.7596x; 2.1402x over previous
#include <cuda_runtime.h>
#include <cuda_bf16.h>
#include <math.h>
#include <stdint.h>

#define S_LEN 2048
#define BATCH 4
#define HEADS 16
#define DKH 64
#define DMODEL 1024
#define MROWS (BATCH * S_LEN)  /* 8192 */
#define NEGV -1000000000.0f

// ---------------------------------------------------------------------------
// Scratch (device globals; no allocation allowed)
// ---------------------------------------------------------------------------
__device__ __nv_bfloat16 g_ahi[MROWS * DMODEL];
__device__ __nv_bfloat16 g_alo[MROWS * DMODEL];
__device__ __nv_bfloat16 g_qhi[MROWS * DMODEL];
__device__ __nv_bfloat16 g_qlo[MROWS * DMODEL];
__device__ __nv_bfloat16 g_khi[MROWS * DMODEL];
__device__ __nv_bfloat16 g_klo[MROWS * DMODEL];
__device__ __nv_bfloat16 g_vhi[MROWS * DMODEL];
__device__ __nv_bfloat16 g_vlo[MROWS * DMODEL];
__device__ __nv_bfloat16 g_whi[4][DMODEL * DMODEL];
__device__ __nv_bfloat16 g_wlo[4][DMODEL * DMODEL];

__device__ __forceinline__ uint32_t smem_u32(const void* p) {
    uint32_t addr;
    asm("{ .reg .u64 tmp; cvta.to.shared.u64 tmp, %1; cvt.u32.u64 %0, tmp; }"
        : "=r"(addr) : "l"(p));
    return addr;
}

__device__ __forceinline__ uint32_t pack2(__nv_bfloat16 a, __nv_bfloat16 b) {
    return (uint32_t)__bfloat16_as_ushort(a) |
           ((uint32_t)__bfloat16_as_ushort(b) << 16);
}

__device__ __forceinline__ void ldm_x4(uint32_t* r, uint32_t addr) {
    asm volatile("ldmatrix.sync.aligned.m8n8.x4.shared.b16 {%0,%1,%2,%3}, [%4];"
                 : "=r"(r[0]), "=r"(r[1]), "=r"(r[2]), "=r"(r[3]) : "r"(addr));
}

__device__ __forceinline__ void ldm_x4_t(uint32_t* r, uint32_t addr) {
    asm volatile("ldmatrix.sync.aligned.m8n8.x4.trans.shared.b16 {%0,%1,%2,%3}, [%4];"
                 : "=r"(r[0]), "=r"(r[1]), "=r"(r[2]), "=r"(r[3]) : "r"(addr));
}

__device__ __forceinline__ void mma_bf16(float* c, const uint32_t* a, const uint32_t* b) {
    asm volatile(
        "mma.sync.aligned.m16n8k16.row.col.f32.bf16.bf16.f32 "
        "{%0,%1,%2,%3}, {%4,%5,%6,%7}, {%8,%9}, {%0,%1,%2,%3};"
        : "+f"(c[0]), "+f"(c[1]), "+f"(c[2]), "+f"(c[3])
        : "r"(a[0]), "r"(a[1]), "r"(a[2]), "r"(a[3]), "r"(b[0]), "r"(b[1]));
}

__device__ __forceinline__ void cp16(uint32_t saddr, const void* gaddr) {
    asm volatile("cp.async.cg.shared.global [%0], [%1], 16;"
                 :: "r"(saddr), "l"(gaddr));
}

// ---------------------------------------------------------------------------
// Split fp32 -> hi/lo bf16 planes.
// ---------------------------------------------------------------------------
__global__ void __launch_bounds__(256)
split_kernel(const float4* __restrict__ in, uint2* __restrict__ hi,
             uint2* __restrict__ lo, int n4)
{
    int i = blockIdx.x * blockDim.x + threadIdx.x;
    if (i >= n4) return;
    float4 f = in[i];
    float fs[4] = {f.x, f.y, f.z, f.w};
    __nv_bfloat16 h[4], l[4];
#pragma unroll
    for (int j = 0; j < 4; j++) {
        h[j] = __float2bfloat16_rn(fs[j]);
        l[j] = __float2bfloat16_rn(fs[j] - __bfloat162float(h[j]));
    }
    hi[i] = make_uint2(pack2(h[0], h[1]), pack2(h[2], h[3]));
    lo[i] = make_uint2(pack2(l[0], l[1]), pack2(l[2], l[3]));
}

// ---------------------------------------------------------------------------
// Tensor-core GEMM: C[m,n] = sum_k A[m,k]*W[n,k] + bias[n]
// MODE 0: fp32 row-major out (C).
// MODE 2: bf16 hi/lo planes, head-split layout (Chi/Clo).
// ---------------------------------------------------------------------------
#define BK 32
#define PAD 40
#define TILE_E (128 * PAD)
#define STAGE_E (4 * TILE_E)
#define GEMM_SMEM (2 * STAGE_E * 2)

template <int MODE>
__global__ void __launch_bounds__(512)
gemm_mma_kernel(const __nv_bfloat16* __restrict__ Ahi,
                const __nv_bfloat16* __restrict__ Alo,
                const __nv_bfloat16* __restrict__ Whi,
                const __nv_bfloat16* __restrict__ Wlo,
                const float* __restrict__ bias, float* __restrict__ C,
                __nv_bfloat16* __restrict__ Chi, __nv_bfloat16* __restrict__ Clo)
{
    extern __shared__ char dsm[];
    const uint32_t sb = smem_u32(dsm);
    const int tid = threadIdx.x;
    const int wid = tid >> 5;
    const int lane = tid & 31;
    const int m0 = blockIdx.y * 128;
    const int n0 = blockIdx.x * 128;
    const int wm = wid & 3;
    const int wn = wid >> 2;

    float acc[2][4][4];
#pragma unroll
    for (int a = 0; a < 2; a++)
#pragma unroll
        for (int b = 0; b < 4; b++)
#pragma unroll
            for (int c = 0; c < 4; c++) acc[a][b][c] = 0.0f;

    auto prefetch = [&](int iter) {
        if (iter < DMODEL / BK) {
            const int k0 = iter * BK;
            const uint32_t stage_base = sb + (uint32_t)((iter & 1) * STAGE_E * 2);
#pragma unroll
            for (int t = 0; t < 4; t++) {
                const int c = tid + t * 512;
                const int tile = c >> 9;
                const int w = c & 511;
                const int row = w >> 2;
                const int kc = (w & 3) * 8;
                const uint32_t saddr =
                    stage_base + (uint32_t)((tile * TILE_E + row * PAD + kc) * 2);
                const __nv_bfloat16* gp;
                if (tile == 0)      gp = Ahi + (size_t)(m0 + row) * DMODEL + k0 + kc;
                else if (tile == 1) gp = Alo + (size_t)(m0 + row) * DMODEL + k0 + kc;
                else if (tile == 2) gp = Whi + (size_t)(n0 + row) * DMODEL + k0 + kc;
                else                gp = Wlo + (size_t)(n0 + row) * DMODEL + k0 + kc;
                cp16(saddr, gp);
            }
        }
        asm volatile("cp.async.commit_group;");
    };

    const int a_row = lane & 15;
    const int a_k   = (lane >> 4) << 3;
    const int b_n   = ((lane >> 4) << 3) + (lane & 7);
    const int b_k   = lane & 8;

    prefetch(0);

    for (int iter = 0; iter < DMODEL / BK; iter++) {
        prefetch(iter + 1);
        asm volatile("cp.async.wait_group 1;");
        __syncthreads();

        const uint32_t st = sb + (uint32_t)((iter & 1) * STAGE_E * 2);
#pragma unroll
        for (int ks = 0; ks < BK; ks += 16) {
            uint32_t ah[2][4], al[2][4];
#pragma unroll
            for (int mt = 0; mt < 2; mt++) {
                const int row = wm * 32 + mt * 16 + a_row;
                const uint32_t off = (uint32_t)((row * PAD + ks + a_k) * 2);
                ldm_x4(ah[mt], st + 0 * TILE_E * 2 + off);
                ldm_x4(al[mt], st + 1 * TILE_E * 2 + off);
            }
            uint32_t bh[4][2], bl[4][2];
#pragma unroll
            for (int np = 0; np < 2; np++) {
                const int n = wn * 32 + np * 16 + b_n;
                const uint32_t off = (uint32_t)((n * PAD + ks + b_k) * 2);
                uint32_t r[4];
                ldm_x4(r, st + 2 * TILE_E * 2 + off);
                bh[2 * np][0] = r[0]; bh[2 * np][1] = r[1];
                bh[2 * np + 1][0] = r[2]; bh[2 * np + 1][1] = r[3];
                ldm_x4(r, st + 3 * TILE_E * 2 + off);
                bl[2 * np][0] = r[0]; bl[2 * np][1] = r[1];
                bl[2 * np + 1][0] = r[2]; bl[2 * np + 1][1] = r[3];
            }
#pragma unroll
            for (int mt = 0; mt < 2; mt++)
#pragma unroll
                for (int nt = 0; nt < 4; nt++) {
                    mma_bf16(acc[mt][nt], ah[mt], bh[nt]);
                    mma_bf16(acc[mt][nt], al[mt], bh[nt]);
                    mma_bf16(acc[mt][nt], ah[mt], bl[nt]);
                }
        }
        __syncthreads();
    }

    const int qrow = lane >> 2;
    const int qcol = (lane & 3) * 2;
#pragma unroll
    for (int mt = 0; mt < 2; mt++) {
#pragma unroll
        for (int nt = 0; nt < 4; nt++) {
            const int n = n0 + wn * 32 + nt * 8 + qcol;
            const float b0 = bias[n], b1 = bias[n + 1];
#pragma unroll
            for (int rp = 0; rp < 2; rp++) {
                const int m = m0 + wm * 32 + mt * 16 + qrow + rp * 8;
                float x0 = acc[mt][nt][2 * rp + 0] + b0;
                float x1 = acc[mt][nt][2 * rp + 1] + b1;
                if (MODE == 0) {
                    *(float2*)&C[(size_t)m * DMODEL + n] = make_float2(x0, x1);
                } else {
                    const int h = n >> 6, dk = n & 63;
                    const int b = m >> 11, s = m & 2047;
                    const size_t idx =
                        (((size_t)(b * HEADS + h) * S_LEN + s)) * DKH + dk;
                    __nv_bfloat16 h0 = __float2bfloat16_rn(x0);
                    __nv_bfloat16 h1 = __float2bfloat16_rn(x1);
                    __nv_bfloat16 l0 = __float2bfloat16_rn(x0 - __bfloat162float(h0));
                    __nv_bfloat16 l1 = __float2bfloat16_rn(x1 - __bfloat162float(h1));
                    *(uint32_t*)(Chi + idx) = pack2(h0, h1);
                    *(uint32_t*)(Clo + idx) = pack2(l0, l1);
                }
            }
        }
    }
}

// ---------------------------------------------------------------------------
// Tensor-core flash attention.
// 4 warps, 64 q-rows per block; warp w -> rows 16w..16w+15.
// Q/K/V as bf16 hi/lo planes in head-split layout [(bh)*S + s][64].
// K tile: B-operand [key][dkh] natural. V tile: B-operand via ldmatrix.trans.
// Output written as bf16 hi/lo planes row-major [b*S+s][DMODEL].
// smem rows padded to 72 elems (144B) -> conflict-free ldmatrix.
// ---------------------------------------------------------------------------
#define FPAD 144              /* bytes per smem row */
#define FPLANE 9216           /* 64 rows * 144B */
#define FQ_HI 0
#define FQ_LO FPLANE
#define FSTG (2 * FPLANE)     /* 18432 */
#define FSSTRIDE (4 * FPLANE + 256)   /* k_hi,k_lo,v_hi,v_lo,mask */
#define FLASH_SMEM (FSTG + 2 * FSSTRIDE)  /* 92672 */

__global__ void __launch_bounds__(128)
flash_mma_kernel(const __nv_bfloat16* __restrict__ Qh,
                 const __nv_bfloat16* __restrict__ Ql,
                 const __nv_bfloat16* __restrict__ Kh,
                 const __nv_bfloat16* __restrict__ Kl,
                 const __nv_bfloat16* __restrict__ Vh,
                 const __nv_bfloat16* __restrict__ Vl,
                 const int* __restrict__ mask,
                 __nv_bfloat16* __restrict__ Ohi,
                 __nv_bfloat16* __restrict__ Olo)
{
    extern __shared__ char fsm[];
    const uint32_t sb = smem_u32(fsm);
    const int tid = threadIdx.x;
    const int wid = tid >> 5;
    const int lane = tid & 31;
    const int bh = blockIdx.y;
    const int b = bh >> 4;
    const int h = bh & 15;
    const int q0 = blockIdx.x * 64;
    const int* mb = mask + b * S_LEN;

    auto prefetch_t = [&](int t, uint32_t stbase) {
        const int kb = t * 64;
#pragma unroll
        for (int i = 0; i < 16; i++) {
            const int c = tid + i * 128;     // 0..2047
            const int pl = c >> 9;
            const int w = c & 511;
            const int row = w >> 3;
            const int col = w & 7;
            const __nv_bfloat16* base =
                (pl == 0) ? Kh : (pl == 1) ? Kl : (pl == 2) ? Vh : Vl;
            cp16(stbase + (uint32_t)(pl * FPLANE + row * FPAD + col * 16),
                 base + ((size_t)bh * S_LEN + kb + row) * DKH + col * 8);
        }
        if (tid < 16)
            cp16(stbase + (uint32_t)(4 * FPLANE + tid * 16), mb + kb + tid * 4);
        asm volatile("cp.async.commit_group;");
    };

    // --- Q prefetch (group 0)
#pragma unroll
    for (int i = 0; i < 8; i++) {
        const int c = tid + i * 128;         // 0..1023
        const int pl = c >> 9;
        const int w = c & 511;
        const int row = w >> 3;
        const int col = w & 7;
        const __nv_bfloat16* base = pl ? Ql : Qh;
        cp16(sb + (uint32_t)(pl * FPLANE + row * FPAD + col * 16),
             base + ((size_t)bh * S_LEN + q0 + row) * DKH + col * 8);
    }
    asm volatile("cp.async.commit_group;");

    prefetch_t(0, sb + FSTG);

    asm volatile("cp.async.wait_group 1;");
    __syncthreads();

    // --- Q fragments (A-operand), all 4 k-steps, hi+lo
    const int a_row = lane & 15;
    const int a_k8  = (lane >> 4) << 3;      // 0 or 8 elems
    uint32_t qh[4][4], ql[4][4];
#pragma unroll
    for (int ks = 0; ks < 4; ks++) {
        const uint32_t off =
            (uint32_t)((wid * 16 + a_row) * FPAD + (ks * 16 + a_k8) * 2);
        ldm_x4(qh[ks], sb + FQ_HI + off);
        ldm_x4(ql[ks], sb + FQ_LO + off);
    }

    prefetch_t(1, sb + FSTG + FSSTRIDE);

    float o[8][4];
#pragma unroll
    for (int j = 0; j < 8; j++)
#pragma unroll
        for (int c = 0; c < 4; c++) o[j][c] = 0.0f;
    float mrow0 = -INFINITY, mrow1 = -INFINITY;
    float lrow0 = 0.0f, lrow1 = 0.0f;

    const int b_n = ((lane >> 4) << 3) + (lane & 7);
    const int b_k = lane & 8;

    for (int t = 0; t < S_LEN / 64; t++) {
        asm volatile("cp.async.wait_group 1;");
        __syncthreads();
        const uint32_t st = sb + FSTG + (uint32_t)((t & 1) * FSSTRIDE);

        // ---- S = Q K^T
        float s[8][4];
#pragma unroll
        for (int j = 0; j < 8; j++)
#pragma unroll
            for (int c = 0; c < 4; c++) s[j][c] = 0.0f;
#pragma unroll
        for (int ks = 0; ks < 4; ks++) {
#pragma unroll
            for (int ng = 0; ng < 4; ng++) {
                const uint32_t kaddr =
                    st + (uint32_t)((ng * 16 + b_n) * FPAD + (ks * 16 + b_k) * 2);
                uint32_t kh[4], kl[4];
                ldm_x4(kh, kaddr);
                ldm_x4(kl, kaddr + FPLANE);
                mma_bf16(s[2 * ng],     qh[ks], kh);
                mma_bf16(s[2 * ng],     ql[ks], kh);
                mma_bf16(s[2 * ng],     qh[ks], kl);
                mma_bf16(s[2 * ng + 1], qh[ks], kh + 2);
                mma_bf16(s[2 * ng + 1], ql[ks], kh + 2);
                mma_bf16(s[2 * ng + 1], qh[ks], kl + 2);
            }
        }

        // ---- mask + scale + row max
        float rm0 = -INFINITY, rm1 = -INFINITY;
#pragma unroll
        for (int j = 0; j < 8; j++) {
            const int2 mk = *(const int2*)(fsm + (st - sb) + 4 * FPLANE +
                                           (j * 8 + 2 * (lane & 3)) * 4);
            s[j][0] = mk.x ? s[j][0] * 0.125f : NEGV;
            s[j][1] = mk.y ? s[j][1] * 0.125f : NEGV;
            s[j][2] = mk.x ? s[j][2] * 0.125f : NEGV;
            s[j][3] = mk.y ? s[j][3] * 0.125f : NEGV;
            rm0 = fmaxf(rm0, fmaxf(s[j][0], s[j][1]));
            rm1 = fmaxf(rm1, fmaxf(s[j][2], s[j][3]));
        }
#pragma unroll
        for (int off = 1; off < 4; off <<= 1) {
            rm0 = fmaxf(rm0, __shfl_xor_sync(0xffffffffu, rm0, off));
            rm1 = fmaxf(rm1, __shfl_xor_sync(0xffffffffu, rm1, off));
        }

        const float mn0 = fmaxf(mrow0, rm0);
        const float mn1 = fmaxf(mrow1, rm1);
        const float cor0 = __expf(mrow0 - mn0);
        const float cor1 = __expf(mrow1 - mn1);
        mrow0 = mn0; mrow1 = mn1;

        float rs0 = 0.0f, rs1 = 0.0f;
        uint32_t ph[4][4], pl[4][4];
#pragma unroll
        for (int j = 0; j < 8; j++) {
            const float p0 = __expf(s[j][0] - mn0);
            const float p1 = __expf(s[j][1] - mn0);
            const float p2 = __expf(s[j][2] - mn1);
            const float p3 = __expf(s[j][3] - mn1);
            rs0 += p0 + p1;
            rs1 += p2 + p3;
            const __nv_bfloat16 h0 = __float2bfloat16_rn(p0);
            const __nv_bfloat16 h1 = __float2bfloat16_rn(p1);
            const __nv_bfloat16 h2 = __float2bfloat16_rn(p2);
            const __nv_bfloat16 h3 = __float2bfloat16_rn(p3);
            const __nv_bfloat16 l0 = __float2bfloat16_rn(p0 - __bfloat162float(h0));
            const __nv_bfloat16 l1 = __float2bfloat16_rn(p1 - __bfloat162float(h1));
            const __nv_bfloat16 l2 = __float2bfloat16_rn(p2 - __bfloat162float(h2));
            const __nv_bfloat16 l3 = __float2bfloat16_rn(p3 - __bfloat162float(h3));
            const int kc = j >> 1;
            const int hf = (j & 1) * 2;
            ph[kc][hf + 0] = pack2(h0, h1);
            ph[kc][hf + 1] = pack2(h2, h3);
            pl[kc][hf + 0] = pack2(l0, l1);
            pl[kc][hf + 1] = pack2(l2, l3);
        }
#pragma unroll
        for (int off = 1; off < 4; off <<= 1) {
            rs0 += __shfl_xor_sync(0xffffffffu, rs0, off);
            rs1 += __shfl_xor_sync(0xffffffffu, rs1, off);
        }
        lrow0 = lrow0 * cor0 + rs0;
        lrow1 = lrow1 * cor1 + rs1;
#pragma unroll
        for (int j = 0; j < 8; j++) {
            o[j][0] *= cor0; o[j][1] *= cor0;
            o[j][2] *= cor1; o[j][3] *= cor1;
        }

        // ---- O += P V  (V via trans ldmatrix; B-frag n=dkh, k=key)
#pragma unroll
        for (int kc = 0; kc < 4; kc++) {
#pragma unroll
            for (int vg = 0; vg < 4; vg++) {
                const uint32_t vaddr =
                    st + (uint32_t)(2 * FPLANE + (kc * 16 + (lane & 15)) * FPAD +
                                    (vg * 16 + a_k8) * 2);
                uint32_t vh[4], vl[4];
                ldm_x4_t(vh, vaddr);
                ldm_x4_t(vl, vaddr + FPLANE);
                mma_bf16(o[2 * vg],     ph[kc], vh);
                mma_bf16(o[2 * vg],     pl[kc], vh);
                mma_bf16(o[2 * vg],     ph[kc], vl);
                mma_bf16(o[2 * vg + 1], ph[kc], vh + 2);
                mma_bf16(o[2 * vg + 1], pl[kc], vh + 2);
                mma_bf16(o[2 * vg + 1], ph[kc], vl + 2);
            }
        }

        __syncthreads();
        if (t + 2 < S_LEN / 64)
            prefetch_t(t + 2, sb + FSTG + (uint32_t)((t & 1) * FSSTRIDE));
        else
            asm volatile("cp.async.commit_group;");
    }

    // ---- epilogue: normalize, split to hi/lo, write row-major planes
    const float inv0 = 1.0f / lrow0;
    const float inv1 = 1.0f / lrow1;
    const int r0 = q0 + wid * 16 + (lane >> 2);
    const size_t row0 = (size_t)(b * S_LEN + r0) * DMODEL;
    const size_t row1 = (size_t)(b * S_LEN + r0 + 8) * DMODEL;
#pragma unroll
    for (int j = 0; j < 8; j++) {
        const int col = h * DKH + j * 8 + 2 * (lane & 3);
        {
            const float x0 = o[j][0] * inv0, x1 = o[j][1] * inv0;
            const __nv_bfloat16 h0 = __float2bfloat16_rn(x0);
            const __nv_bfloat16 h1 = __float2bfloat16_rn(x1);
            const __nv_bfloat16 l0 = __float2bfloat16_rn(x0 - __bfloat162float(h0));
            const __nv_bfloat16 l1 = __float2bfloat16_rn(x1 - __bfloat162float(h1));
            *(uint32_t*)(Ohi + row0 + col) = pack2(h0, h1);
            *(uint32_t*)(Olo + row0 + col) = pack2(l0, l1);
        }
        {
            const float x2 = o[j][2] * inv1, x3 = o[j][3] * inv1;
            const __nv_bfloat16 h2 = __float2bfloat16_rn(x2);
            const __nv_bfloat16 h3 = __float2bfloat16_rn(x3);
            const __nv_bfloat16 l2 = __float2bfloat16_rn(x2 - __bfloat162float(h2));
            const __nv_bfloat16 l3 = __float2bfloat16_rn(x3 - __bfloat162float(h3));
            *(uint32_t*)(Ohi + row1 + col) = pack2(h2, h3);
            *(uint32_t*)(Olo + row1 + col) = pack2(l2, l3);
        }
    }
}

// ---------------------------------------------------------------------------
extern "C" void kernel_launch(void* const* d_in, const int* in_sizes, int n_in,
                              void* d_out, int out_size)
{
    const float* query = (const float*)d_in[0];
    const float* key   = (const float*)d_in[1];
    const float* value = (const float*)d_in[2];
    const int*   mask  = (const int*)d_in[3];
    const float* Wmat[4] = {(const float*)d_in[4], (const float*)d_in[6],
                            (const float*)d_in[8], (const float*)d_in[10]};
    const float* bvec[4] = {(const float*)d_in[5], (const float*)d_in[7],
                            (const float*)d_in[9], (const float*)d_in[11]};
    float* out = (float*)d_out;

    __nv_bfloat16 *ahi, *alo, *qhi, *qlo, *khi, *klo, *vhi, *vlo, *whi, *wlo;
    cudaGetSymbolAddress((void**)&ahi, g_ahi);
    cudaGetSymbolAddress((void**)&alo, g_alo);
    cudaGetSymbolAddress((void**)&qhi, g_qhi);
    cudaGetSymbolAddress((void**)&qlo, g_qlo);
    cudaGetSymbolAddress((void**)&khi, g_khi);
    cudaGetSymbolAddress((void**)&klo, g_klo);
    cudaGetSymbolAddress((void**)&vhi, g_vhi);
    cudaGetSymbolAddress((void**)&vlo, g_vlo);
    cudaGetSymbolAddress((void**)&whi, g_whi);
    cudaGetSymbolAddress((void**)&wlo, g_wlo);

    cudaFuncSetAttribute(gemm_mma_kernel<0>,
                         cudaFuncAttributeMaxDynamicSharedMemorySize, GEMM_SMEM);
    cudaFuncSetAttribute(gemm_mma_kernel<2>,
                         cudaFuncAttributeMaxDynamicSharedMemorySize, GEMM_SMEM);
    cudaFuncSetAttribute(flash_mma_kernel,
                         cudaFuncAttributeMaxDynamicSharedMemorySize, FLASH_SMEM);

    const int nw4 = DMODEL * DMODEL / 4;
    const int na4 = MROWS * DMODEL / 4;

    for (int i = 0; i < 4; i++) {
        split_kernel<<<(nw4 + 255) / 256, 256>>>(
            (const float4*)Wmat[i], (uint2*)(whi + (size_t)i * DMODEL * DMODEL),
            (uint2*)(wlo + (size_t)i * DMODEL * DMODEL), nw4);
    }

    dim3 gg(DMODEL / 128, MROWS / 128);

    // Q projection -> bf16 planes
    split_kernel<<<(na4 + 255) / 256, 256>>>((const float4*)query, (uint2*)ahi,
                                             (uint2*)alo, na4);
    gemm_mma_kernel<2><<<gg, 512, GEMM_SMEM>>>(ahi, alo, whi, wlo, bvec[0],
                                               nullptr, qhi, qlo);
    // K projection
    split_kernel<<<(na4 + 255) / 256, 256>>>((const float4*)key, (uint2*)ahi,
                                             (uint2*)alo, na4);
    gemm_mma_kernel<2><<<gg, 512, GEMM_SMEM>>>(
        ahi, alo, whi + (size_t)1 * DMODEL * DMODEL,
        wlo + (size_t)1 * DMODEL * DMODEL, bvec[1], nullptr, khi, klo);
    // V projection
    split_kernel<<<(na4 + 255) / 256, 256>>>((const float4*)value, (uint2*)ahi,
                                             (uint2*)alo, na4);
    gemm_mma_kernel<2><<<gg, 512, GEMM_SMEM>>>(
        ahi, alo, whi + (size_t)2 * DMODEL * DMODEL,
        wlo + (size_t)2 * DMODEL * DMODEL, bvec[2], nullptr, vhi, vlo);

    // attention -> writes ahi/alo planes
    dim3 fg(S_LEN / 64, BATCH * HEADS);
    flash_mma_kernel<<<fg, 128, FLASH_SMEM>>>(qhi, qlo, khi, klo, vhi, vlo,
                                              mask, ahi, alo);

    // output projection (fp32 out)
    gemm_mma_kernel<0><<<gg, 512, GEMM_SMEM>>>(
        ahi, alo, whi + (size_t)3 * DMODEL * DMODEL,
        wlo + (size_t)3 * DMODEL * DMODEL, bvec[3], out, nullptr, nullptr);
}

// round 6
// speedup vs baseline: 3.1779x; 1.1516x over previous
#include <cuda_runtime.h>
#include <cuda_bf16.h>
#include <math.h>
#include <stdint.h>

#define S_LEN 2048
#define BATCH 4
#define HEADS 16
#define DKH 64
#define DMODEL 1024
#define MROWS (BATCH * S_LEN)  /* 8192 */
#define NEGV -1000000000.0f

// ---------------------------------------------------------------------------
// Scratch (device globals; no allocation allowed)
// ---------------------------------------------------------------------------
__device__ __nv_bfloat16 g_ahi[MROWS * DMODEL];
__device__ __nv_bfloat16 g_alo[MROWS * DMODEL];
__device__ __nv_bfloat16 g_qhi[MROWS * DMODEL];
__device__ __nv_bfloat16 g_qlo[MROWS * DMODEL];
__device__ __nv_bfloat16 g_khi[MROWS * DMODEL];
__device__ __nv_bfloat16 g_klo[MROWS * DMODEL];
__device__ __nv_bfloat16 g_vhi[MROWS * DMODEL];
__device__ __nv_bfloat16 g_vlo[MROWS * DMODEL];
__device__ __nv_bfloat16 g_whi[4][DMODEL * DMODEL];
__device__ __nv_bfloat16 g_wlo[4][DMODEL * DMODEL];

__device__ __forceinline__ uint32_t smem_u32(const void* p) {
    uint32_t addr;
    asm("{ .reg .u64 tmp; cvta.to.shared.u64 tmp, %1; cvt.u32.u64 %0, tmp; }"
        : "=r"(addr) : "l"(p));
    return addr;
}

__device__ __forceinline__ uint32_t pack2(__nv_bfloat16 a, __nv_bfloat16 b) {
    return (uint32_t)__bfloat16_as_ushort(a) |
           ((uint32_t)__bfloat16_as_ushort(b) << 16);
}

__device__ __forceinline__ void ldm_x4(uint32_t* r, uint32_t addr) {
    asm volatile("ldmatrix.sync.aligned.m8n8.x4.shared.b16 {%0,%1,%2,%3}, [%4];"
                 : "=r"(r[0]), "=r"(r[1]), "=r"(r[2]), "=r"(r[3]) : "r"(addr));
}

__device__ __forceinline__ void ldm_x4_t(uint32_t* r, uint32_t addr) {
    asm volatile("ldmatrix.sync.aligned.m8n8.x4.trans.shared.b16 {%0,%1,%2,%3}, [%4];"
                 : "=r"(r[0]), "=r"(r[1]), "=r"(r[2]), "=r"(r[3]) : "r"(addr));
}

__device__ __forceinline__ void mma_bf16(float* c, const uint32_t* a, const uint32_t* b) {
    asm volatile(
        "mma.sync.aligned.m16n8k16.row.col.f32.bf16.bf16.f32 "
        "{%0,%1,%2,%3}, {%4,%5,%6,%7}, {%8,%9}, {%0,%1,%2,%3};"
        : "+f"(c[0]), "+f"(c[1]), "+f"(c[2]), "+f"(c[3])
        : "r"(a[0]), "r"(a[1]), "r"(a[2]), "r"(a[3]), "r"(b[0]), "r"(b[1]));
}

__device__ __forceinline__ void cp16(uint32_t saddr, const void* gaddr) {
    asm volatile("cp.async.cg.shared.global [%0], [%1], 16;"
                 :: "r"(saddr), "l"(gaddr));
}

// ---------------------------------------------------------------------------
// Split fp32 -> hi/lo bf16 planes.
// ---------------------------------------------------------------------------
__global__ void __launch_bounds__(256)
split_kernel(const float4* __restrict__ in, uint2* __restrict__ hi,
             uint2* __restrict__ lo, int n4)
{
    int i = blockIdx.x * blockDim.x + threadIdx.x;
    if (i >= n4) return;
    float4 f = in[i];
    float fs[4] = {f.x, f.y, f.z, f.w};
    __nv_bfloat16 h[4], l[4];
#pragma unroll
    for (int j = 0; j < 4; j++) {
        h[j] = __float2bfloat16_rn(fs[j]);
        l[j] = __float2bfloat16_rn(fs[j] - __bfloat162float(h[j]));
    }
    hi[i] = make_uint2(pack2(h[0], h[1]), pack2(h[2], h[3]));
    lo[i] = make_uint2(pack2(l[0], l[1]), pack2(l[2], l[3]));
}

// ---------------------------------------------------------------------------
// Tensor-core GEMM: C[m,n] = sum_k A[m,k]*W[n,k] + bias[n]
// MODE 0: fp32 row-major out (C).
// MODE 2: bf16 hi/lo planes, head-split layout (Chi/Clo).
// 3-stage cp.async pipeline.
// ---------------------------------------------------------------------------
#define BK 32
#define PAD 40
#define TILE_E (128 * PAD)
#define STAGE_E (4 * TILE_E)
#define STAGE_B (STAGE_E * 2)        /* 40960 */
#define NSTAGE 3
#define GEMM_SMEM (NSTAGE * STAGE_B) /* 122880 */

template <int MODE>
__global__ void __launch_bounds__(512)
gemm_mma_kernel(const __nv_bfloat16* __restrict__ Ahi,
                const __nv_bfloat16* __restrict__ Alo,
                const __nv_bfloat16* __restrict__ Whi,
                const __nv_bfloat16* __restrict__ Wlo,
                const float* __restrict__ bias, float* __restrict__ C,
                __nv_bfloat16* __restrict__ Chi, __nv_bfloat16* __restrict__ Clo)
{
    extern __shared__ char dsm[];
    const uint32_t sb = smem_u32(dsm);
    const int tid = threadIdx.x;
    const int wid = tid >> 5;
    const int lane = tid & 31;
    const int m0 = blockIdx.y * 128;
    const int n0 = blockIdx.x * 128;
    const int wm = wid & 3;
    const int wn = wid >> 2;

    float acc[2][4][4];
#pragma unroll
    for (int a = 0; a < 2; a++)
#pragma unroll
        for (int b = 0; b < 4; b++)
#pragma unroll
            for (int c = 0; c < 4; c++) acc[a][b][c] = 0.0f;

    auto prefetch = [&](int iter) {
        if (iter < DMODEL / BK) {
            const int k0 = iter * BK;
            const uint32_t stage_base = sb + (uint32_t)((iter % NSTAGE) * STAGE_B);
#pragma unroll
            for (int t = 0; t < 4; t++) {
                const int c = tid + t * 512;
                const int tile = c >> 9;
                const int w = c & 511;
                const int row = w >> 2;
                const int kc = (w & 3) * 8;
                const uint32_t saddr =
                    stage_base + (uint32_t)((tile * TILE_E + row * PAD + kc) * 2);
                const __nv_bfloat16* gp;
                if (tile == 0)      gp = Ahi + (size_t)(m0 + row) * DMODEL + k0 + kc;
                else if (tile == 1) gp = Alo + (size_t)(m0 + row) * DMODEL + k0 + kc;
                else if (tile == 2) gp = Whi + (size_t)(n0 + row) * DMODEL + k0 + kc;
                else                gp = Wlo + (size_t)(n0 + row) * DMODEL + k0 + kc;
                cp16(saddr, gp);
            }
        }
        asm volatile("cp.async.commit_group;");
    };

    const int a_row = lane & 15;
    const int a_k   = (lane >> 4) << 3;
    const int b_n   = ((lane >> 4) << 3) + (lane & 7);
    const int b_k   = lane & 8;

    prefetch(0);
    prefetch(1);

    for (int iter = 0; iter < DMODEL / BK; iter++) {
        asm volatile("cp.async.wait_group 1;");
        __syncthreads();
        prefetch(iter + 2);

        const uint32_t st = sb + (uint32_t)((iter % NSTAGE) * STAGE_B);
#pragma unroll
        for (int ks = 0; ks < BK; ks += 16) {
            uint32_t ah[2][4], al[2][4];
#pragma unroll
            for (int mt = 0; mt < 2; mt++) {
                const int row = wm * 32 + mt * 16 + a_row;
                const uint32_t off = (uint32_t)((row * PAD + ks + a_k) * 2);
                ldm_x4(ah[mt], st + 0 * TILE_E * 2 + off);
                ldm_x4(al[mt], st + 1 * TILE_E * 2 + off);
            }
            uint32_t bh[4][2], bl[4][2];
#pragma unroll
            for (int np = 0; np < 2; np++) {
                const int n = wn * 32 + np * 16 + b_n;
                const uint32_t off = (uint32_t)((n * PAD + ks + b_k) * 2);
                uint32_t r[4];
                ldm_x4(r, st + 2 * TILE_E * 2 + off);
                bh[2 * np][0] = r[0]; bh[2 * np][1] = r[1];
                bh[2 * np + 1][0] = r[2]; bh[2 * np + 1][1] = r[3];
                ldm_x4(r, st + 3 * TILE_E * 2 + off);
                bl[2 * np][0] = r[0]; bl[2 * np][1] = r[1];
                bl[2 * np + 1][0] = r[2]; bl[2 * np + 1][1] = r[3];
            }
#pragma unroll
            for (int mt = 0; mt < 2; mt++)
#pragma unroll
                for (int nt = 0; nt < 4; nt++) {
                    mma_bf16(acc[mt][nt], ah[mt], bh[nt]);
                    mma_bf16(acc[mt][nt], al[mt], bh[nt]);
                    mma_bf16(acc[mt][nt], ah[mt], bl[nt]);
                }
        }
    }

    const int qrow = lane >> 2;
    const int qcol = (lane & 3) * 2;
#pragma unroll
    for (int mt = 0; mt < 2; mt++) {
#pragma unroll
        for (int nt = 0; nt < 4; nt++) {
            const int n = n0 + wn * 32 + nt * 8 + qcol;
            const float b0 = bias[n], b1 = bias[n + 1];
#pragma unroll
            for (int rp = 0; rp < 2; rp++) {
                const int m = m0 + wm * 32 + mt * 16 + qrow + rp * 8;
                float x0 = acc[mt][nt][2 * rp + 0] + b0;
                float x1 = acc[mt][nt][2 * rp + 1] + b1;
                if (MODE == 0) {
                    *(float2*)&C[(size_t)m * DMODEL + n] = make_float2(x0, x1);
                } else {
                    const int h = n >> 6, dk = n & 63;
                    const int b = m >> 11, s = m & 2047;
                    const size_t idx =
                        (((size_t)(b * HEADS + h) * S_LEN + s)) * DKH + dk;
                    __nv_bfloat16 h0 = __float2bfloat16_rn(x0);
                    __nv_bfloat16 h1 = __float2bfloat16_rn(x1);
                    __nv_bfloat16 l0 = __float2bfloat16_rn(x0 - __bfloat162float(h0));
                    __nv_bfloat16 l1 = __float2bfloat16_rn(x1 - __bfloat162float(h1));
                    *(uint32_t*)(Chi + idx) = pack2(h0, h1);
                    *(uint32_t*)(Clo + idx) = pack2(l0, l1);
                }
            }
        }
    }
}

// ---------------------------------------------------------------------------
// Tensor-core flash attention.
// 8 warps, 128 q-rows per block; warp w -> rows 16w..16w+15.
// K tiles of 64 keys, 2-stage cp.async double buffering.
// Q/K/V as bf16 hi/lo planes, head-split layout. Output bf16 hi/lo row-major.
// smem rows padded to 144B -> conflict-free ldmatrix.
// ---------------------------------------------------------------------------
#define FPAD 144
#define QPLANE (128 * FPAD)            /* 18432 */
#define KVPLANE (64 * FPAD)            /* 9216  */
#define FQ_HI 0
#define FQ_LO QPLANE
#define FSTG (2 * QPLANE)              /* 36864 */
#define FSSTRIDE (4 * KVPLANE + 256)   /* 37120 */
#define FLASH_SMEM (FSTG + 2 * FSSTRIDE)  /* 111104 */

__global__ void __launch_bounds__(256)
flash_mma_kernel(const __nv_bfloat16* __restrict__ Qh,
                 const __nv_bfloat16* __restrict__ Ql,
                 const __nv_bfloat16* __restrict__ Kh,
                 const __nv_bfloat16* __restrict__ Kl,
                 const __nv_bfloat16* __restrict__ Vh,
                 const __nv_bfloat16* __restrict__ Vl,
                 const int* __restrict__ mask,
                 __nv_bfloat16* __restrict__ Ohi,
                 __nv_bfloat16* __restrict__ Olo)
{
    extern __shared__ char fsm[];
    const uint32_t sb = smem_u32(fsm);
    const int tid = threadIdx.x;
    const int wid = tid >> 5;
    const int lane = tid & 31;
    const int bh = blockIdx.y;
    const int b = bh >> 4;
    const int h = bh & 15;
    const int q0 = blockIdx.x * 128;
    const int* mb = mask + b * S_LEN;

    auto prefetch_t = [&](int t, uint32_t stbase) {
        const int kb = t * 64;
#pragma unroll
        for (int i = 0; i < 8; i++) {
            const int c = tid + i * 256;     // 0..2047
            const int pl = c >> 9;           // plane 0..3
            const int w = c & 511;
            const int row = w >> 3;
            const int col = w & 7;
            const __nv_bfloat16* base =
                (pl == 0) ? Kh : (pl == 1) ? Kl : (pl == 2) ? Vh : Vl;
            cp16(stbase + (uint32_t)(pl * KVPLANE + row * FPAD + col * 16),
                 base + ((size_t)bh * S_LEN + kb + row) * DKH + col * 8);
        }
        if (tid < 16)
            cp16(stbase + (uint32_t)(4 * KVPLANE + tid * 16), mb + kb + tid * 4);
        asm volatile("cp.async.commit_group;");
    };

    // --- Q prefetch (2 planes x 128 rows)
#pragma unroll
    for (int i = 0; i < 8; i++) {
        const int c = tid + i * 256;         // 0..2047
        const int pl = c >> 10;              // 0..1
        const int w = c & 1023;
        const int row = w >> 3;
        const int col = w & 7;
        const __nv_bfloat16* base = pl ? Ql : Qh;
        cp16(sb + (uint32_t)(pl * QPLANE + row * FPAD + col * 16),
             base + ((size_t)bh * S_LEN + q0 + row) * DKH + col * 8);
    }
    asm volatile("cp.async.commit_group;");

    prefetch_t(0, sb + FSTG);

    asm volatile("cp.async.wait_group 1;");
    __syncthreads();

    // --- Q fragments (A-operand), all 4 k-steps, hi+lo
    const int a_row = lane & 15;
    const int a_k8  = (lane >> 4) << 3;
    uint32_t qh[4][4], ql[4][4];
#pragma unroll
    for (int ks = 0; ks < 4; ks++) {
        const uint32_t off =
            (uint32_t)((wid * 16 + a_row) * FPAD + (ks * 16 + a_k8) * 2);
        ldm_x4(qh[ks], sb + FQ_HI + off);
        ldm_x4(ql[ks], sb + FQ_LO + off);
    }

    prefetch_t(1, sb + FSTG + FSSTRIDE);

    float o[8][4];
#pragma unroll
    for (int j = 0; j < 8; j++)
#pragma unroll
        for (int c = 0; c < 4; c++) o[j][c] = 0.0f;
    float mrow0 = -INFINITY, mrow1 = -INFINITY;
    float lrow0 = 0.0f, lrow1 = 0.0f;

    const int b_n = ((lane >> 4) << 3) + (lane & 7);
    const int b_k = lane & 8;

    for (int t = 0; t < S_LEN / 64; t++) {
        asm volatile("cp.async.wait_group 1;");
        __syncthreads();
        const uint32_t st = sb + FSTG + (uint32_t)((t & 1) * FSSTRIDE);

        // ---- S = Q K^T
        float s[8][4];
#pragma unroll
        for (int j = 0; j < 8; j++)
#pragma unroll
            for (int c = 0; c < 4; c++) s[j][c] = 0.0f;
#pragma unroll
        for (int ks = 0; ks < 4; ks++) {
#pragma unroll
            for (int ng = 0; ng < 4; ng++) {
                const uint32_t kaddr =
                    st + (uint32_t)((ng * 16 + b_n) * FPAD + (ks * 16 + b_k) * 2);
                uint32_t kh[4], kl[4];
                ldm_x4(kh, kaddr);
                ldm_x4(kl, kaddr + KVPLANE);
                mma_bf16(s[2 * ng],     qh[ks], kh);
                mma_bf16(s[2 * ng],     ql[ks], kh);
                mma_bf16(s[2 * ng],     qh[ks], kl);
                mma_bf16(s[2 * ng + 1], qh[ks], kh + 2);
                mma_bf16(s[2 * ng + 1], ql[ks], kh + 2);
                mma_bf16(s[2 * ng + 1], qh[ks], kl + 2);
            }
        }

        // ---- mask + scale + row max
        float rm0 = -INFINITY, rm1 = -INFINITY;
#pragma unroll
        for (int j = 0; j < 8; j++) {
            const int2 mk = *(const int2*)(fsm + (st - sb) + 4 * KVPLANE +
                                           (j * 8 + 2 * (lane & 3)) * 4);
            s[j][0] = mk.x ? s[j][0] * 0.125f : NEGV;
            s[j][1] = mk.y ? s[j][1] * 0.125f : NEGV;
            s[j][2] = mk.x ? s[j][2] * 0.125f : NEGV;
            s[j][3] = mk.y ? s[j][3] * 0.125f : NEGV;
            rm0 = fmaxf(rm0, fmaxf(s[j][0], s[j][1]));
            rm1 = fmaxf(rm1, fmaxf(s[j][2], s[j][3]));
        }
#pragma unroll
        for (int off = 1; off < 4; off <<= 1) {
            rm0 = fmaxf(rm0, __shfl_xor_sync(0xffffffffu, rm0, off));
            rm1 = fmaxf(rm1, __shfl_xor_sync(0xffffffffu, rm1, off));
        }

        const float mn0 = fmaxf(mrow0, rm0);
        const float mn1 = fmaxf(mrow1, rm1);
        const float cor0 = __expf(mrow0 - mn0);
        const float cor1 = __expf(mrow1 - mn1);
        mrow0 = mn0; mrow1 = mn1;

        float rs0 = 0.0f, rs1 = 0.0f;
        uint32_t ph[4][4], pl[4][4];
#pragma unroll
        for (int j = 0; j < 8; j++) {
            const float p0 = __expf(s[j][0] - mn0);
            const float p1 = __expf(s[j][1] - mn0);
            const float p2 = __expf(s[j][2] - mn1);
            const float p3 = __expf(s[j][3] - mn1);
            rs0 += p0 + p1;
            rs1 += p2 + p3;
            const __nv_bfloat16 h0 = __float2bfloat16_rn(p0);
            const __nv_bfloat16 h1 = __float2bfloat16_rn(p1);
            const __nv_bfloat16 h2 = __float2bfloat16_rn(p2);
            const __nv_bfloat16 h3 = __float2bfloat16_rn(p3);
            const __nv_bfloat16 l0 = __float2bfloat16_rn(p0 - __bfloat162float(h0));
            const __nv_bfloat16 l1 = __float2bfloat16_rn(p1 - __bfloat162float(h1));
            const __nv_bfloat16 l2 = __float2bfloat16_rn(p2 - __bfloat162float(h2));
            const __nv_bfloat16 l3 = __float2bfloat16_rn(p3 - __bfloat162float(h3));
            const int kc = j >> 1;
            const int hf = (j & 1) * 2;
            ph[kc][hf + 0] = pack2(h0, h1);
            ph[kc][hf + 1] = pack2(h2, h3);
            pl[kc][hf + 0] = pack2(l0, l1);
            pl[kc][hf + 1] = pack2(l2, l3);
        }
#pragma unroll
        for (int off = 1; off < 4; off <<= 1) {
            rs0 += __shfl_xor_sync(0xffffffffu, rs0, off);
            rs1 += __shfl_xor_sync(0xffffffffu, rs1, off);
        }
        lrow0 = lrow0 * cor0 + rs0;
        lrow1 = lrow1 * cor1 + rs1;
#pragma unroll
        for (int j = 0; j < 8; j++) {
            o[j][0] *= cor0; o[j][1] *= cor0;
            o[j][2] *= cor1; o[j][3] *= cor1;
        }

        // ---- O += P V (V via trans ldmatrix)
#pragma unroll
        for (int kc = 0; kc < 4; kc++) {
#pragma unroll
            for (int vg = 0; vg < 4; vg++) {
                const uint32_t vaddr =
                    st + (uint32_t)(2 * KVPLANE + (kc * 16 + (lane & 15)) * FPAD +
                                    (vg * 16 + a_k8) * 2);
                uint32_t vh[4], vl[4];
                ldm_x4_t(vh, vaddr);
                ldm_x4_t(vl, vaddr + KVPLANE);
                mma_bf16(o[2 * vg],     ph[kc], vh);
                mma_bf16(o[2 * vg],     pl[kc], vh);
                mma_bf16(o[2 * vg],     ph[kc], vl);
                mma_bf16(o[2 * vg + 1], ph[kc], vh + 2);
                mma_bf16(o[2 * vg + 1], pl[kc], vh + 2);
                mma_bf16(o[2 * vg + 1], ph[kc], vl + 2);
            }
        }

        __syncthreads();
        if (t + 2 < S_LEN / 64)
            prefetch_t(t + 2, sb + FSTG + (uint32_t)((t & 1) * FSSTRIDE));
        else
            asm volatile("cp.async.commit_group;");
    }

    // ---- epilogue: normalize, split to hi/lo, write row-major planes
    const float inv0 = 1.0f / lrow0;
    const float inv1 = 1.0f / lrow1;
    const int r0 = q0 + wid * 16 + (lane >> 2);
    const size_t row0 = (size_t)(b * S_LEN + r0) * DMODEL;
    const size_t row1 = (size_t)(b * S_LEN + r0 + 8) * DMODEL;
#pragma unroll
    for (int j = 0; j < 8; j++) {
        const int col = h * DKH + j * 8 + 2 * (lane & 3);
        {
            const float x0 = o[j][0] * inv0, x1 = o[j][1] * inv0;
            const __nv_bfloat16 h0 = __float2bfloat16_rn(x0);
            const __nv_bfloat16 h1 = __float2bfloat16_rn(x1);
            const __nv_bfloat16 l0 = __float2bfloat16_rn(x0 - __bfloat162float(h0));
            const __nv_bfloat16 l1 = __float2bfloat16_rn(x1 - __bfloat162float(h1));
            *(uint32_t*)(Ohi + row0 + col) = pack2(h0, h1);
            *(uint32_t*)(Olo + row0 + col) = pack2(l0, l1);
        }
        {
            const float x2 = o[j][2] * inv1, x3 = o[j][3] * inv1;
            const __nv_bfloat16 h2 = __float2bfloat16_rn(x2);
            const __nv_bfloat16 h3 = __float2bfloat16_rn(x3);
            const __nv_bfloat16 l2 = __float2bfloat16_rn(x2 - __bfloat162float(h2));
            const __nv_bfloat16 l3 = __float2bfloat16_rn(x3 - __bfloat162float(h3));
            *(uint32_t*)(Ohi + row1 + col) = pack2(h2, h3);
            *(uint32_t*)(Olo + row1 + col) = pack2(l2, l3);
        }
    }
}

// ---------------------------------------------------------------------------
extern "C" void kernel_launch(void* const* d_in, const int* in_sizes, int n_in,
                              void* d_out, int out_size)
{
    const float* query = (const float*)d_in[0];
    const float* key   = (const float*)d_in[1];
    const float* value = (const float*)d_in[2];
    const int*   mask  = (const int*)d_in[3];
    const float* Wmat[4] = {(const float*)d_in[4], (const float*)d_in[6],
                            (const float*)d_in[8], (const float*)d_in[10]};
    const float* bvec[4] = {(const float*)d_in[5], (const float*)d_in[7],
                            (const float*)d_in[9], (const float*)d_in[11]};
    float* out = (float*)d_out;

    __nv_bfloat16 *ahi, *alo, *qhi, *qlo, *khi, *klo, *vhi, *vlo, *whi, *wlo;
    cudaGetSymbolAddress((void**)&ahi, g_ahi);
    cudaGetSymbolAddress((void**)&alo, g_alo);
    cudaGetSymbolAddress((void**)&qhi, g_qhi);
    cudaGetSymbolAddress((void**)&qlo, g_qlo);
    cudaGetSymbolAddress((void**)&khi, g_khi);
    cudaGetSymbolAddress((void**)&klo, g_klo);
    cudaGetSymbolAddress((void**)&vhi, g_vhi);
    cudaGetSymbolAddress((void**)&vlo, g_vlo);
    cudaGetSymbolAddress((void**)&whi, g_whi);
    cudaGetSymbolAddress((void**)&wlo, g_wlo);

    cudaFuncSetAttribute(gemm_mma_kernel<0>,
                         cudaFuncAttributeMaxDynamicSharedMemorySize, GEMM_SMEM);
    cudaFuncSetAttribute(gemm_mma_kernel<2>,
                         cudaFuncAttributeMaxDynamicSharedMemorySize, GEMM_SMEM);
    cudaFuncSetAttribute(flash_mma_kernel,
                         cudaFuncAttributeMaxDynamicSharedMemorySize, FLASH_SMEM);

    const int nw4 = DMODEL * DMODEL / 4;
    const int na4 = MROWS * DMODEL / 4;

    for (int i = 0; i < 4; i++) {
        split_kernel<<<(nw4 + 255) / 256, 256>>>(
            (const float4*)Wmat[i], (uint2*)(whi + (size_t)i * DMODEL * DMODEL),
            (uint2*)(wlo + (size_t)i * DMODEL * DMODEL), nw4);
    }

    dim3 gg(DMODEL / 128, MROWS / 128);

    // Q projection -> bf16 planes
    split_kernel<<<(na4 + 255) / 256, 256>>>((const float4*)query, (uint2*)ahi,
                                             (uint2*)alo, na4);
    gemm_mma_kernel<2><<<gg, 512, GEMM_SMEM>>>(ahi, alo, whi, wlo, bvec[0],
                                               nullptr, qhi, qlo);
    // K projection
    split_kernel<<<(na4 + 255) / 256, 256>>>((const float4*)key, (uint2*)ahi,
                                             (uint2*)alo, na4);
    gemm_mma_kernel<2><<<gg, 512, GEMM_SMEM>>>(
        ahi, alo, whi + (size_t)1 * DMODEL * DMODEL,
        wlo + (size_t)1 * DMODEL * DMODEL, bvec[1], nullptr, khi, klo);
    // V projection
    split_kernel<<<(na4 + 255) / 256, 256>>>((const float4*)value, (uint2*)ahi,
                                             (uint2*)alo, na4);
    gemm_mma_kernel<2><<<gg, 512, GEMM_SMEM>>>(
        ahi, alo, whi + (size_t)2 * DMODEL * DMODEL,
        wlo + (size_t)2 * DMODEL * DMODEL, bvec[2], nullptr, vhi, vlo);

    // attention -> writes ahi/alo planes
    dim3 fg(S_LEN / 128, BATCH * HEADS);
    flash_mma_kernel<<<fg, 256, FLASH_SMEM>>>(qhi, qlo, khi, klo, vhi, vlo,
                                              mask, ahi, alo);

    // output projection (fp32 out)
    gemm_mma_kernel<0><<<gg, 512, GEMM_SMEM>>>(
        ahi, alo, whi + (size_t)3 * DMODEL * DMODEL,
        wlo + (size_t)3 * DMODEL * DMODEL, bvec[3], out, nullptr, nullptr);
}

// round 7
// speedup vs baseline: 4.6163x; 1.4526x over previous
#include <cuda_runtime.h>
#include <cuda_bf16.h>
#include <math.h>
#include <stdint.h>

#define S_LEN 2048
#define BATCH 4
#define HEADS 16
#define DKH 64
#define DMODEL 1024
#define MROWS (BATCH * S_LEN)  /* 8192 */
#define NEGV -1000000000.0f

// ---------------------------------------------------------------------------
// Scratch (device globals; no allocation allowed)
// ---------------------------------------------------------------------------
__device__ __nv_bfloat16 g_ahi[MROWS * DMODEL];
__device__ __nv_bfloat16 g_alo[MROWS * DMODEL];
__device__ __nv_bfloat16 g_qhi[MROWS * DMODEL];
__device__ __nv_bfloat16 g_qlo[MROWS * DMODEL];
__device__ __nv_bfloat16 g_khi[MROWS * DMODEL];
__device__ __nv_bfloat16 g_klo[MROWS * DMODEL];
__device__ __nv_bfloat16 g_vhi[MROWS * DMODEL];
__device__ __nv_bfloat16 g_vlo[MROWS * DMODEL];
__device__ __nv_bfloat16 g_whi[4][DMODEL * DMODEL];
__device__ __nv_bfloat16 g_wlo[4][DMODEL * DMODEL];
__device__ int g_idx[BATCH * S_LEN];
__device__ int g_cnt[BATCH];

__device__ __forceinline__ uint32_t smem_u32(const void* p) {
    uint32_t addr;
    asm("{ .reg .u64 tmp; cvta.to.shared.u64 tmp, %1; cvt.u32.u64 %0, tmp; }"
        : "=r"(addr) : "l"(p));
    return addr;
}

__device__ __forceinline__ uint32_t pack2(__nv_bfloat16 a, __nv_bfloat16 b) {
    return (uint32_t)__bfloat16_as_ushort(a) |
           ((uint32_t)__bfloat16_as_ushort(b) << 16);
}

__device__ __forceinline__ void ldm_x4(uint32_t* r, uint32_t addr) {
    asm volatile("ldmatrix.sync.aligned.m8n8.x4.shared.b16 {%0,%1,%2,%3}, [%4];"
                 : "=r"(r[0]), "=r"(r[1]), "=r"(r[2]), "=r"(r[3]) : "r"(addr));
}

__device__ __forceinline__ void ldm_x4_t(uint32_t* r, uint32_t addr) {
    asm volatile("ldmatrix.sync.aligned.m8n8.x4.trans.shared.b16 {%0,%1,%2,%3}, [%4];"
                 : "=r"(r[0]), "=r"(r[1]), "=r"(r[2]), "=r"(r[3]) : "r"(addr));
}

__device__ __forceinline__ void mma_bf16(float* c, const uint32_t* a, const uint32_t* b) {
    asm volatile(
        "mma.sync.aligned.m16n8k16.row.col.f32.bf16.bf16.f32 "
        "{%0,%1,%2,%3}, {%4,%5,%6,%7}, {%8,%9}, {%0,%1,%2,%3};"
        : "+f"(c[0]), "+f"(c[1]), "+f"(c[2]), "+f"(c[3])
        : "r"(a[0]), "r"(a[1]), "r"(a[2]), "r"(a[3]), "r"(b[0]), "r"(b[1]));
}

__device__ __forceinline__ void cp16(uint32_t saddr, const void* gaddr) {
    asm volatile("cp.async.cg.shared.global [%0], [%1], 16;"
                 :: "r"(saddr), "l"(gaddr));
}

// ---------------------------------------------------------------------------
// Split fp32 -> hi/lo bf16 planes (weights + query only now).
// ---------------------------------------------------------------------------
__global__ void __launch_bounds__(256)
split_kernel(const float4* __restrict__ in, uint2* __restrict__ hi,
             uint2* __restrict__ lo, int n4)
{
    int i = blockIdx.x * blockDim.x + threadIdx.x;
    if (i >= n4) return;
    float4 f = in[i];
    float fs[4] = {f.x, f.y, f.z, f.w};
    __nv_bfloat16 h[4], l[4];
#pragma unroll
    for (int j = 0; j < 4; j++) {
        h[j] = __float2bfloat16_rn(fs[j]);
        l[j] = __float2bfloat16_rn(fs[j] - __bfloat162float(h[j]));
    }
    hi[i] = make_uint2(pack2(h[0], h[1]), pack2(h[2], h[3]));
    lo[i] = make_uint2(pack2(l[0], l[1]), pack2(l[2], l[3]));
}

// ---------------------------------------------------------------------------
// Mask compaction: per-batch scan -> idx list + count.
// ---------------------------------------------------------------------------
__global__ void __launch_bounds__(1024)
mask_scan_kernel(const int* __restrict__ mask, int* __restrict__ idx,
                 int* __restrict__ cnt)
{
    __shared__ int sc[1024];
    const int b = blockIdx.x;
    const int tid = threadIdx.x;
    const int m0 = mask[b * S_LEN + 2 * tid];
    const int m1 = mask[b * S_LEN + 2 * tid + 1];
    const int c = (m0 != 0) + (m1 != 0);
    sc[tid] = c;
    __syncthreads();
    for (int off = 1; off < 1024; off <<= 1) {
        int v = (tid >= off) ? sc[tid - off] : 0;
        __syncthreads();
        sc[tid] += v;
        __syncthreads();
    }
    int pos = sc[tid] - c;
    if (m0) idx[b * S_LEN + pos++] = 2 * tid;
    if (m1) idx[b * S_LEN + pos] = 2 * tid + 1;
    if (tid == 1023) cnt[b] = sc[1023];
}

// ---------------------------------------------------------------------------
// Gather unmasked rows of an fp32 [B,S,DMODEL] tensor into compact per-batch
// segments AND split to bf16 hi/lo planes. Pad rows (j >= cnt[b]) = zeros.
// grid 1024 x block 256: 8 rows per block, 32 lanes per row.
// ---------------------------------------------------------------------------
__global__ void __launch_bounds__(256)
gather_split_kernel(const float* __restrict__ src, const int* __restrict__ idx,
                    const int* __restrict__ cnt, uint2* __restrict__ hi,
                    uint2* __restrict__ lo)
{
    const int gr = blockIdx.x * 8 + (threadIdx.x >> 5);
    const int b = gr >> 11;
    const int j = gr & 2047;
    const int lane = threadIdx.x & 31;
    const bool valid = j < cnt[b];
    const int srow = valid ? idx[b * S_LEN + j] : 0;
    const float4* s4 =
        (const float4*)(src + ((size_t)(b * S_LEN + srow)) * DMODEL);
    const size_t o4 = (size_t)gr * (DMODEL / 4);
#pragma unroll
    for (int i = 0; i < 8; i++) {
        const int c4 = lane + i * 32;
        float4 f = valid ? s4[c4] : make_float4(0.f, 0.f, 0.f, 0.f);
        float fs[4] = {f.x, f.y, f.z, f.w};
        __nv_bfloat16 h[4], l[4];
#pragma unroll
        for (int q = 0; q < 4; q++) {
            h[q] = __float2bfloat16_rn(fs[q]);
            l[q] = __float2bfloat16_rn(fs[q] - __bfloat162float(h[q]));
        }
        hi[o4 + c4] = make_uint2(pack2(h[0], h[1]), pack2(h[2], h[3]));
        lo[o4 + c4] = make_uint2(pack2(l[0], l[1]), pack2(l[2], l[3]));
    }
}

// ---------------------------------------------------------------------------
// Tensor-core GEMM: C[m,n] = sum_k A[m,k]*W[n,k] + bias[n]
// MODE 0: fp32 row-major out. MODE 2: bf16 hi/lo planes, head-split out.
// cnt != nullptr: per-batch early exit for compacted A (tiles of 128).
// 3-stage cp.async pipeline.
// ---------------------------------------------------------------------------
#define BK 32
#define PAD 40
#define TILE_E (128 * PAD)
#define STAGE_E (4 * TILE_E)
#define STAGE_B (STAGE_E * 2)        /* 40960 */
#define NSTAGE 3
#define GEMM_SMEM (NSTAGE * STAGE_B) /* 122880 */

template <int MODE>
__global__ void __launch_bounds__(512)
gemm_mma_kernel(const __nv_bfloat16* __restrict__ Ahi,
                const __nv_bfloat16* __restrict__ Alo,
                const __nv_bfloat16* __restrict__ Whi,
                const __nv_bfloat16* __restrict__ Wlo,
                const float* __restrict__ bias, float* __restrict__ C,
                __nv_bfloat16* __restrict__ Chi, __nv_bfloat16* __restrict__ Clo,
                const int* __restrict__ cnt)
{
    extern __shared__ char dsm[];
    const uint32_t sb = smem_u32(dsm);
    const int tid = threadIdx.x;
    const int wid = tid >> 5;
    const int lane = tid & 31;
    const int m0 = blockIdx.y * 128;
    const int n0 = blockIdx.x * 128;
    const int wm = wid & 3;
    const int wn = wid >> 2;

    if (cnt) {
        const int npad = (cnt[m0 >> 11] + 127) & ~127;
        if ((m0 & 2047) >= npad) return;
    }

    float acc[2][4][4];
#pragma unroll
    for (int a = 0; a < 2; a++)
#pragma unroll
        for (int b = 0; b < 4; b++)
#pragma unroll
            for (int c = 0; c < 4; c++) acc[a][b][c] = 0.0f;

    auto prefetch = [&](int iter) {
        if (iter < DMODEL / BK) {
            const int k0 = iter * BK;
            const uint32_t stage_base = sb + (uint32_t)((iter % NSTAGE) * STAGE_B);
#pragma unroll
            for (int t = 0; t < 4; t++) {
                const int c = tid + t * 512;
                const int tile = c >> 9;
                const int w = c & 511;
                const int row = w >> 2;
                const int kc = (w & 3) * 8;
                const uint32_t saddr =
                    stage_base + (uint32_t)((tile * TILE_E + row * PAD + kc) * 2);
                const __nv_bfloat16* gp;
                if (tile == 0)      gp = Ahi + (size_t)(m0 + row) * DMODEL + k0 + kc;
                else if (tile == 1) gp = Alo + (size_t)(m0 + row) * DMODEL + k0 + kc;
                else if (tile == 2) gp = Whi + (size_t)(n0 + row) * DMODEL + k0 + kc;
                else                gp = Wlo + (size_t)(n0 + row) * DMODEL + k0 + kc;
                cp16(saddr, gp);
            }
        }
        asm volatile("cp.async.commit_group;");
    };

    const int a_row = lane & 15;
    const int a_k   = (lane >> 4) << 3;
    const int b_n   = ((lane >> 4) << 3) + (lane & 7);
    const int b_k   = lane & 8;

    prefetch(0);
    prefetch(1);

    for (int iter = 0; iter < DMODEL / BK; iter++) {
        asm volatile("cp.async.wait_group 1;");
        __syncthreads();
        prefetch(iter + 2);

        const uint32_t st = sb + (uint32_t)((iter % NSTAGE) * STAGE_B);
#pragma unroll
        for (int ks = 0; ks < BK; ks += 16) {
            uint32_t ah[2][4], al[2][4];
#pragma unroll
            for (int mt = 0; mt < 2; mt++) {
                const int row = wm * 32 + mt * 16 + a_row;
                const uint32_t off = (uint32_t)((row * PAD + ks + a_k) * 2);
                ldm_x4(ah[mt], st + 0 * TILE_E * 2 + off);
                ldm_x4(al[mt], st + 1 * TILE_E * 2 + off);
            }
            uint32_t bh[4][2], bl[4][2];
#pragma unroll
            for (int np = 0; np < 2; np++) {
                const int n = wn * 32 + np * 16 + b_n;
                const uint32_t off = (uint32_t)((n * PAD + ks + b_k) * 2);
                uint32_t r[4];
                ldm_x4(r, st + 2 * TILE_E * 2 + off);
                bh[2 * np][0] = r[0]; bh[2 * np][1] = r[1];
                bh[2 * np + 1][0] = r[2]; bh[2 * np + 1][1] = r[3];
                ldm_x4(r, st + 3 * TILE_E * 2 + off);
                bl[2 * np][0] = r[0]; bl[2 * np][1] = r[1];
                bl[2 * np + 1][0] = r[2]; bl[2 * np + 1][1] = r[3];
            }
#pragma unroll
            for (int mt = 0; mt < 2; mt++)
#pragma unroll
                for (int nt = 0; nt < 4; nt++) {
                    mma_bf16(acc[mt][nt], ah[mt], bh[nt]);
                    mma_bf16(acc[mt][nt], al[mt], bh[nt]);
                    mma_bf16(acc[mt][nt], ah[mt], bl[nt]);
                }
        }
    }

    const int qrow = lane >> 2;
    const int qcol = (lane & 3) * 2;
#pragma unroll
    for (int mt = 0; mt < 2; mt++) {
#pragma unroll
        for (int nt = 0; nt < 4; nt++) {
            const int n = n0 + wn * 32 + nt * 8 + qcol;
            const float b0 = bias[n], b1 = bias[n + 1];
#pragma unroll
            for (int rp = 0; rp < 2; rp++) {
                const int m = m0 + wm * 32 + mt * 16 + qrow + rp * 8;
                float x0 = acc[mt][nt][2 * rp + 0] + b0;
                float x1 = acc[mt][nt][2 * rp + 1] + b1;
                if (MODE == 0) {
                    *(float2*)&C[(size_t)m * DMODEL + n] = make_float2(x0, x1);
                } else {
                    const int h = n >> 6, dk = n & 63;
                    const int b = m >> 11, s = m & 2047;
                    const size_t idx =
                        (((size_t)(b * HEADS + h) * S_LEN + s)) * DKH + dk;
                    __nv_bfloat16 h0 = __float2bfloat16_rn(x0);
                    __nv_bfloat16 h1 = __float2bfloat16_rn(x1);
                    __nv_bfloat16 l0 = __float2bfloat16_rn(x0 - __bfloat162float(h0));
                    __nv_bfloat16 l1 = __float2bfloat16_rn(x1 - __bfloat162float(h1));
                    *(uint32_t*)(Chi + idx) = pack2(h0, h1);
                    *(uint32_t*)(Clo + idx) = pack2(l0, l1);
                }
            }
        }
    }
}

// ---------------------------------------------------------------------------
// Tensor-core flash attention over COMPACTED keys (cnt[b] valid keys/batch).
// 8 warps, 128 q-rows per block. Tail keys (>= cnt[b]) masked to NEGV.
// ---------------------------------------------------------------------------
#define FPAD 144
#define QPLANE (128 * FPAD)            /* 18432 */
#define KVPLANE (64 * FPAD)            /* 9216  */
#define FQ_HI 0
#define FQ_LO QPLANE
#define FSTG (2 * QPLANE)              /* 36864 */
#define FSSTRIDE (4 * KVPLANE)         /* 36864 */
#define FLASH_SMEM (FSTG + 2 * FSSTRIDE)  /* 110592 */

__global__ void __launch_bounds__(256)
flash_mma_kernel(const __nv_bfloat16* __restrict__ Qh,
                 const __nv_bfloat16* __restrict__ Ql,
                 const __nv_bfloat16* __restrict__ Kh,
                 const __nv_bfloat16* __restrict__ Kl,
                 const __nv_bfloat16* __restrict__ Vh,
                 const __nv_bfloat16* __restrict__ Vl,
                 const int* __restrict__ cnt,
                 __nv_bfloat16* __restrict__ Ohi,
                 __nv_bfloat16* __restrict__ Olo)
{
    extern __shared__ char fsm[];
    const uint32_t sb = smem_u32(fsm);
    const int tid = threadIdx.x;
    const int wid = tid >> 5;
    const int lane = tid & 31;
    const int bh = blockIdx.y;
    const int b = bh >> 4;
    const int h = bh & 15;
    const int q0 = blockIdx.x * 128;

    const int nb = cnt[b];
    const int ntiles = (nb + 63) >> 6;

    auto prefetch_t = [&](int t) {
        if (t < ntiles) {
            const uint32_t stbase = sb + FSTG + (uint32_t)((t & 1) * FSSTRIDE);
            const int kb = t * 64;
#pragma unroll
            for (int i = 0; i < 8; i++) {
                const int c = tid + i * 256;
                const int pl = c >> 9;
                const int w = c & 511;
                const int row = w >> 3;
                const int col = w & 7;
                const __nv_bfloat16* base =
                    (pl == 0) ? Kh : (pl == 1) ? Kl : (pl == 2) ? Vh : Vl;
                cp16(stbase + (uint32_t)(pl * KVPLANE + row * FPAD + col * 16),
                     base + ((size_t)bh * S_LEN + kb + row) * DKH + col * 8);
            }
        }
        asm volatile("cp.async.commit_group;");
    };

    // --- Q prefetch
#pragma unroll
    for (int i = 0; i < 8; i++) {
        const int c = tid + i * 256;
        const int pl = c >> 10;
        const int w = c & 1023;
        const int row = w >> 3;
        const int col = w & 7;
        const __nv_bfloat16* base = pl ? Ql : Qh;
        cp16(sb + (uint32_t)(pl * QPLANE + row * FPAD + col * 16),
             base + ((size_t)bh * S_LEN + q0 + row) * DKH + col * 8);
    }
    asm volatile("cp.async.commit_group;");

    prefetch_t(0);

    asm volatile("cp.async.wait_group 1;");
    __syncthreads();

    const int a_row = lane & 15;
    const int a_k8  = (lane >> 4) << 3;
    uint32_t qh[4][4], ql[4][4];
#pragma unroll
    for (int ks = 0; ks < 4; ks++) {
        const uint32_t off =
            (uint32_t)((wid * 16 + a_row) * FPAD + (ks * 16 + a_k8) * 2);
        ldm_x4(qh[ks], sb + FQ_HI + off);
        ldm_x4(ql[ks], sb + FQ_LO + off);
    }

    prefetch_t(1);

    float o[8][4];
#pragma unroll
    for (int j = 0; j < 8; j++)
#pragma unroll
        for (int c = 0; c < 4; c++) o[j][c] = 0.0f;
    float mrow0 = -INFINITY, mrow1 = -INFINITY;
    float lrow0 = 0.0f, lrow1 = 0.0f;

    const int b_n = ((lane >> 4) << 3) + (lane & 7);
    const int b_k = lane & 8;

    for (int t = 0; t < ntiles; t++) {
        asm volatile("cp.async.wait_group 1;");
        __syncthreads();
        const uint32_t st = sb + FSTG + (uint32_t)((t & 1) * FSSTRIDE);
        const int kb = t * 64;

        // ---- S = Q K^T
        float s[8][4];
#pragma unroll
        for (int j = 0; j < 8; j++)
#pragma unroll
            for (int c = 0; c < 4; c++) s[j][c] = 0.0f;
#pragma unroll
        for (int ks = 0; ks < 4; ks++) {
#pragma unroll
            for (int ng = 0; ng < 4; ng++) {
                const uint32_t kaddr =
                    st + (uint32_t)((ng * 16 + b_n) * FPAD + (ks * 16 + b_k) * 2);
                uint32_t kh[4], kl[4];
                ldm_x4(kh, kaddr);
                ldm_x4(kl, kaddr + KVPLANE);
                mma_bf16(s[2 * ng],     qh[ks], kh);
                mma_bf16(s[2 * ng],     ql[ks], kh);
                mma_bf16(s[2 * ng],     qh[ks], kl);
                mma_bf16(s[2 * ng + 1], qh[ks], kh + 2);
                mma_bf16(s[2 * ng + 1], ql[ks], kh + 2);
                mma_bf16(s[2 * ng + 1], qh[ks], kl + 2);
            }
        }

        // ---- tail mask + scale + row max
        float rm0 = -INFINITY, rm1 = -INFINITY;
#pragma unroll
        for (int j = 0; j < 8; j++) {
            const int key0 = kb + j * 8 + 2 * (lane & 3);
            const bool mx = key0 < nb;
            const bool my = key0 + 1 < nb;
            s[j][0] = mx ? s[j][0] * 0.125f : NEGV;
            s[j][1] = my ? s[j][1] * 0.125f : NEGV;
            s[j][2] = mx ? s[j][2] * 0.125f : NEGV;
            s[j][3] = my ? s[j][3] * 0.125f : NEGV;
            rm0 = fmaxf(rm0, fmaxf(s[j][0], s[j][1]));
            rm1 = fmaxf(rm1, fmaxf(s[j][2], s[j][3]));
        }
#pragma unroll
        for (int off = 1; off < 4; off <<= 1) {
            rm0 = fmaxf(rm0, __shfl_xor_sync(0xffffffffu, rm0, off));
            rm1 = fmaxf(rm1, __shfl_xor_sync(0xffffffffu, rm1, off));
        }

        const float mn0 = fmaxf(mrow0, rm0);
        const float mn1 = fmaxf(mrow1, rm1);
        const float cor0 = __expf(mrow0 - mn0);
        const float cor1 = __expf(mrow1 - mn1);
        mrow0 = mn0; mrow1 = mn1;

        float rs0 = 0.0f, rs1 = 0.0f;
        uint32_t ph[4][4], pl[4][4];
#pragma unroll
        for (int j = 0; j < 8; j++) {
            const float p0 = __expf(s[j][0] - mn0);
            const float p1 = __expf(s[j][1] - mn0);
            const float p2 = __expf(s[j][2] - mn1);
            const float p3 = __expf(s[j][3] - mn1);
            rs0 += p0 + p1;
            rs1 += p2 + p3;
            const __nv_bfloat16 h0 = __float2bfloat16_rn(p0);
            const __nv_bfloat16 h1 = __float2bfloat16_rn(p1);
            const __nv_bfloat16 h2 = __float2bfloat16_rn(p2);
            const __nv_bfloat16 h3 = __float2bfloat16_rn(p3);
            const __nv_bfloat16 l0 = __float2bfloat16_rn(p0 - __bfloat162float(h0));
            const __nv_bfloat16 l1 = __float2bfloat16_rn(p1 - __bfloat162float(h1));
            const __nv_bfloat16 l2 = __float2bfloat16_rn(p2 - __bfloat162float(h2));
            const __nv_bfloat16 l3 = __float2bfloat16_rn(p3 - __bfloat162float(h3));
            const int kc = j >> 1;
            const int hf = (j & 1) * 2;
            ph[kc][hf + 0] = pack2(h0, h1);
            ph[kc][hf + 1] = pack2(h2, h3);
            pl[kc][hf + 0] = pack2(l0, l1);
            pl[kc][hf + 1] = pack2(l2, l3);
        }
#pragma unroll
        for (int off = 1; off < 4; off <<= 1) {
            rs0 += __shfl_xor_sync(0xffffffffu, rs0, off);
            rs1 += __shfl_xor_sync(0xffffffffu, rs1, off);
        }
        lrow0 = lrow0 * cor0 + rs0;
        lrow1 = lrow1 * cor1 + rs1;
#pragma unroll
        for (int j = 0; j < 8; j++) {
            o[j][0] *= cor0; o[j][1] *= cor0;
            o[j][2] *= cor1; o[j][3] *= cor1;
        }

        // ---- O += P V (V via trans ldmatrix)
#pragma unroll
        for (int kc = 0; kc < 4; kc++) {
#pragma unroll
            for (int vg = 0; vg < 4; vg++) {
                const uint32_t vaddr =
                    st + (uint32_t)(2 * KVPLANE + (kc * 16 + (lane & 15)) * FPAD +
                                    (vg * 16 + a_k8) * 2);
                uint32_t vh[4], vl[4];
                ldm_x4_t(vh, vaddr);
                ldm_x4_t(vl, vaddr + KVPLANE);
                mma_bf16(o[2 * vg],     ph[kc], vh);
                mma_bf16(o[2 * vg],     pl[kc], vh);
                mma_bf16(o[2 * vg],     ph[kc], vl);
                mma_bf16(o[2 * vg + 1], ph[kc], vh + 2);
                mma_bf16(o[2 * vg + 1], pl[kc], vh + 2);
                mma_bf16(o[2 * vg + 1], ph[kc], vl + 2);
            }
        }

        __syncthreads();
        prefetch_t(t + 2);
    }

    // ---- epilogue
    const float inv0 = 1.0f / lrow0;
    const float inv1 = 1.0f / lrow1;
    const int r0 = q0 + wid * 16 + (lane >> 2);
    const size_t row0 = (size_t)(b * S_LEN + r0) * DMODEL;
    const size_t row1 = (size_t)(b * S_LEN + r0 + 8) * DMODEL;
#pragma unroll
    for (int j = 0; j < 8; j++) {
        const int col = h * DKH + j * 8 + 2 * (lane & 3);
        {
            const float x0 = o[j][0] * inv0, x1 = o[j][1] * inv0;
            const __nv_bfloat16 h0 = __float2bfloat16_rn(x0);
            const __nv_bfloat16 h1 = __float2bfloat16_rn(x1);
            const __nv_bfloat16 l0 = __float2bfloat16_rn(x0 - __bfloat162float(h0));
            const __nv_bfloat16 l1 = __float2bfloat16_rn(x1 - __bfloat162float(h1));
            *(uint32_t*)(Ohi + row0 + col) = pack2(h0, h1);
            *(uint32_t*)(Olo + row0 + col) = pack2(l0, l1);
        }
        {
            const float x2 = o[j][2] * inv1, x3 = o[j][3] * inv1;
            const __nv_bfloat16 h2 = __float2bfloat16_rn(x2);
            const __nv_bfloat16 h3 = __float2bfloat16_rn(x3);
            const __nv_bfloat16 l2 = __float2bfloat16_rn(x2 - __bfloat162float(h2));
            const __nv_bfloat16 l3 = __float2bfloat16_rn(x3 - __bfloat162float(h3));
            *(uint32_t*)(Ohi + row1 + col) = pack2(h2, h3);
            *(uint32_t*)(Olo + row1 + col) = pack2(l2, l3);
        }
    }
}

// ---------------------------------------------------------------------------
extern "C" void kernel_launch(void* const* d_in, const int* in_sizes, int n_in,
                              void* d_out, int out_size)
{
    const float* query = (const float*)d_in[0];
    const float* key   = (const float*)d_in[1];
    const float* value = (const float*)d_in[2];
    const int*   mask  = (const int*)d_in[3];
    const float* Wmat[4] = {(const float*)d_in[4], (const float*)d_in[6],
                            (const float*)d_in[8], (const float*)d_in[10]};
    const float* bvec[4] = {(const float*)d_in[5], (const float*)d_in[7],
                            (const float*)d_in[9], (const float*)d_in[11]};
    float* out = (float*)d_out;

    __nv_bfloat16 *ahi, *alo, *qhi, *qlo, *khi, *klo, *vhi, *vlo, *whi, *wlo;
    int *idxp, *cntp;
    cudaGetSymbolAddress((void**)&ahi, g_ahi);
    cudaGetSymbolAddress((void**)&alo, g_alo);
    cudaGetSymbolAddress((void**)&qhi, g_qhi);
    cudaGetSymbolAddress((void**)&qlo, g_qlo);
    cudaGetSymbolAddress((void**)&khi, g_khi);
    cudaGetSymbolAddress((void**)&klo, g_klo);
    cudaGetSymbolAddress((void**)&vhi, g_vhi);
    cudaGetSymbolAddress((void**)&vlo, g_vlo);
    cudaGetSymbolAddress((void**)&whi, g_whi);
    cudaGetSymbolAddress((void**)&wlo, g_wlo);
    cudaGetSymbolAddress((void**)&idxp, g_idx);
    cudaGetSymbolAddress((void**)&cntp, g_cnt);

    cudaFuncSetAttribute(gemm_mma_kernel<0>,
                         cudaFuncAttributeMaxDynamicSharedMemorySize, GEMM_SMEM);
    cudaFuncSetAttribute(gemm_mma_kernel<2>,
                         cudaFuncAttributeMaxDynamicSharedMemorySize, GEMM_SMEM);
    cudaFuncSetAttribute(flash_mma_kernel,
                         cudaFuncAttributeMaxDynamicSharedMemorySize, FLASH_SMEM);

    const int nw4 = DMODEL * DMODEL / 4;
    const int na4 = MROWS * DMODEL / 4;

    // mask compaction
    mask_scan_kernel<<<BATCH, 1024>>>(mask, idxp, cntp);

    for (int i = 0; i < 4; i++) {
        split_kernel<<<(nw4 + 255) / 256, 256>>>(
            (const float4*)Wmat[i], (uint2*)(whi + (size_t)i * DMODEL * DMODEL),
            (uint2*)(wlo + (size_t)i * DMODEL * DMODEL), nw4);
    }

    dim3 gg(DMODEL / 128, MROWS / 128);

    // Q projection (full rows)
    split_kernel<<<(na4 + 255) / 256, 256>>>((const float4*)query, (uint2*)ahi,
                                             (uint2*)alo, na4);
    gemm_mma_kernel<2><<<gg, 512, GEMM_SMEM>>>(ahi, alo, whi, wlo, bvec[0],
                                               nullptr, qhi, qlo, nullptr);
    // K projection (compacted rows)
    gather_split_kernel<<<MROWS / 8, 256>>>(key, idxp, cntp, (uint2*)ahi,
                                            (uint2*)alo);
    gemm_mma_kernel<2><<<gg, 512, GEMM_SMEM>>>(
        ahi, alo, whi + (size_t)1 * DMODEL * DMODEL,
        wlo + (size_t)1 * DMODEL * DMODEL, bvec[1], nullptr, khi, klo, cntp);
    // V projection (compacted rows)
    gather_split_kernel<<<MROWS / 8, 256>>>(value, idxp, cntp, (uint2*)ahi,
                                            (uint2*)alo);
    gemm_mma_kernel<2><<<gg, 512, GEMM_SMEM>>>(
        ahi, alo, whi + (size_t)2 * DMODEL * DMODEL,
        wlo + (size_t)2 * DMODEL * DMODEL, bvec[2], nullptr, vhi, vlo, cntp);

    // attention over compacted keys -> writes ahi/alo planes
    dim3 fg(S_LEN / 128, BATCH * HEADS);
    flash_mma_kernel<<<fg, 256, FLASH_SMEM>>>(qhi, qlo, khi, klo, vhi, vlo,
                                              cntp, ahi, alo);

    // output projection (full rows, fp32 out)
    gemm_mma_kernel<0><<<gg, 512, GEMM_SMEM>>>(
        ahi, alo, whi + (size_t)3 * DMODEL * DMODEL,
        wlo + (size_t)3 * DMODEL * DMODEL, bvec[3], out, nullptr, nullptr,
        nullptr);
}

// round 8
// speedup vs baseline: 5.7223x; 1.2396x over previous
#include <cuda_runtime.h>
#include <cuda_bf16.h>
#include <cuda_fp16.h>
#include <math.h>
#include <stdint.h>

#define S_LEN 2048
#define BATCH 4
#define HEADS 16
#define DKH 64
#define DMODEL 1024
#define MROWS (BATCH * S_LEN)  /* 8192 */
#define NEGV -1000000000.0f
#define LO_SCALE 2048.0f
#define LO_INV (1.0f / 2048.0f)

// ---------------------------------------------------------------------------
// Scratch (device globals; no allocation allowed)
// ---------------------------------------------------------------------------
__device__ __half g_ahi[MROWS * DMODEL];          // GEMM A hi (fp16)
__device__ __half g_alo[MROWS * DMODEL];          // GEMM A lo*2^11 (fp16)
__device__ __nv_bfloat16 g_qhi[MROWS * DMODEL];   // flash operands (bf16)
__device__ __nv_bfloat16 g_qlo[MROWS * DMODEL];
__device__ __nv_bfloat16 g_khi[MROWS * DMODEL];
__device__ __nv_bfloat16 g_klo[MROWS * DMODEL];
__device__ __nv_bfloat16 g_vhi[MROWS * DMODEL];
__device__ __nv_bfloat16 g_vlo[MROWS * DMODEL];
__device__ __half g_wh[4][DMODEL * DMODEL];       // W hi only (fp16)
__device__ int g_idx[BATCH * S_LEN];
__device__ int g_cnt[BATCH];

__device__ __forceinline__ uint32_t smem_u32(const void* p) {
    uint32_t addr;
    asm("{ .reg .u64 tmp; cvta.to.shared.u64 tmp, %1; cvt.u32.u64 %0, tmp; }"
        : "=r"(addr) : "l"(p));
    return addr;
}

__device__ __forceinline__ uint32_t pack2(__nv_bfloat16 a, __nv_bfloat16 b) {
    return (uint32_t)__bfloat16_as_ushort(a) |
           ((uint32_t)__bfloat16_as_ushort(b) << 16);
}

__device__ __forceinline__ uint32_t pack2h(__half a, __half b) {
    return (uint32_t)__half_as_ushort(a) |
           ((uint32_t)__half_as_ushort(b) << 16);
}

__device__ __forceinline__ void ldm_x4(uint32_t* r, uint32_t addr) {
    asm volatile("ldmatrix.sync.aligned.m8n8.x4.shared.b16 {%0,%1,%2,%3}, [%4];"
                 : "=r"(r[0]), "=r"(r[1]), "=r"(r[2]), "=r"(r[3]) : "r"(addr));
}

__device__ __forceinline__ void ldm_x4_t(uint32_t* r, uint32_t addr) {
    asm volatile("ldmatrix.sync.aligned.m8n8.x4.trans.shared.b16 {%0,%1,%2,%3}, [%4];"
                 : "=r"(r[0]), "=r"(r[1]), "=r"(r[2]), "=r"(r[3]) : "r"(addr));
}

__device__ __forceinline__ void mma_bf16(float* c, const uint32_t* a, const uint32_t* b) {
    asm volatile(
        "mma.sync.aligned.m16n8k16.row.col.f32.bf16.bf16.f32 "
        "{%0,%1,%2,%3}, {%4,%5,%6,%7}, {%8,%9}, {%0,%1,%2,%3};"
        : "+f"(c[0]), "+f"(c[1]), "+f"(c[2]), "+f"(c[3])
        : "r"(a[0]), "r"(a[1]), "r"(a[2]), "r"(a[3]), "r"(b[0]), "r"(b[1]));
}

__device__ __forceinline__ void mma_f16(float* c, const uint32_t* a, const uint32_t* b) {
    asm volatile(
        "mma.sync.aligned.m16n8k16.row.col.f32.f16.f16.f32 "
        "{%0,%1,%2,%3}, {%4,%5,%6,%7}, {%8,%9}, {%0,%1,%2,%3};"
        : "+f"(c[0]), "+f"(c[1]), "+f"(c[2]), "+f"(c[3])
        : "r"(a[0]), "r"(a[1]), "r"(a[2]), "r"(a[3]), "r"(b[0]), "r"(b[1]));
}

__device__ __forceinline__ void cp16(uint32_t saddr, const void* gaddr) {
    asm volatile("cp.async.cg.shared.global [%0], [%1], 16;"
                 :: "r"(saddr), "l"(gaddr));
}

// ---------------------------------------------------------------------------
// fp16 A-operand split: hi = fp16(x), lo = fp16((x-hi)*2^11)
// ---------------------------------------------------------------------------
__device__ __forceinline__ void split_h(float x, __half& h, __half& l) {
    h = __float2half_rn(x);
    l = __float2half_rn((x - __half2float(h)) * LO_SCALE);
}

__global__ void __launch_bounds__(256)
split_a_kernel(const float4* __restrict__ in, uint2* __restrict__ hi,
               uint2* __restrict__ lo, int n4)
{
    int i = blockIdx.x * blockDim.x + threadIdx.x;
    if (i >= n4) return;
    float4 f = in[i];
    float fs[4] = {f.x, f.y, f.z, f.w};
    __half h[4], l[4];
#pragma unroll
    for (int j = 0; j < 4; j++) split_h(fs[j], h[j], l[j]);
    hi[i] = make_uint2(pack2h(h[0], h[1]), pack2h(h[2], h[3]));
    lo[i] = make_uint2(pack2h(l[0], l[1]), pack2h(l[2], l[3]));
}

// All 4 weight matrices -> fp16 hi planes, one launch.
__global__ void __launch_bounds__(256)
split_w_kernel(const float4* __restrict__ w0, const float4* __restrict__ w1,
               const float4* __restrict__ w2, const float4* __restrict__ w3,
               uint2* __restrict__ out)
{
    const int n4 = DMODEL * DMODEL / 4;
    int i = blockIdx.x * blockDim.x + threadIdx.x;
    if (i >= 4 * n4) return;
    const int m = i / n4;
    const int j = i - m * n4;
    const float4* w = (m == 0) ? w0 : (m == 1) ? w1 : (m == 2) ? w2 : w3;
    float4 f = w[j];
    out[i] = make_uint2(
        pack2h(__float2half_rn(f.x), __float2half_rn(f.y)),
        pack2h(__float2half_rn(f.z), __float2half_rn(f.w)));
}

// ---------------------------------------------------------------------------
// Mask compaction: per-batch scan -> idx list + count.
// ---------------------------------------------------------------------------
__global__ void __launch_bounds__(1024)
mask_scan_kernel(const int* __restrict__ mask, int* __restrict__ idx,
                 int* __restrict__ cnt)
{
    __shared__ int sc[1024];
    const int b = blockIdx.x;
    const int tid = threadIdx.x;
    const int m0 = mask[b * S_LEN + 2 * tid];
    const int m1 = mask[b * S_LEN + 2 * tid + 1];
    const int c = (m0 != 0) + (m1 != 0);
    sc[tid] = c;
    __syncthreads();
    for (int off = 1; off < 1024; off <<= 1) {
        int v = (tid >= off) ? sc[tid - off] : 0;
        __syncthreads();
        sc[tid] += v;
        __syncthreads();
    }
    int pos = sc[tid] - c;
    if (m0) idx[b * S_LEN + pos++] = 2 * tid;
    if (m1) idx[b * S_LEN + pos] = 2 * tid + 1;
    if (tid == 1023) cnt[b] = sc[1023];
}

// ---------------------------------------------------------------------------
// Gather unmasked rows -> compact fp16 hi/lo planes. Pads = zeros.
// ---------------------------------------------------------------------------
__global__ void __launch_bounds__(256)
gather_split_kernel(const float* __restrict__ src, const int* __restrict__ idx,
                    const int* __restrict__ cnt, uint2* __restrict__ hi,
                    uint2* __restrict__ lo)
{
    const int gr = blockIdx.x * 8 + (threadIdx.x >> 5);
    const int b = gr >> 11;
    const int j = gr & 2047;
    const int lane = threadIdx.x & 31;
    const bool valid = j < cnt[b];
    const int srow = valid ? idx[b * S_LEN + j] : 0;
    const float4* s4 =
        (const float4*)(src + ((size_t)(b * S_LEN + srow)) * DMODEL);
    const size_t o4 = (size_t)gr * (DMODEL / 4);
#pragma unroll
    for (int i = 0; i < 8; i++) {
        const int c4 = lane + i * 32;
        float4 f = valid ? s4[c4] : make_float4(0.f, 0.f, 0.f, 0.f);
        float fs[4] = {f.x, f.y, f.z, f.w};
        __half h[4], l[4];
#pragma unroll
        for (int q = 0; q < 4; q++) split_h(fs[q], h[q], l[q]);
        hi[o4 + c4] = make_uint2(pack2h(h[0], h[1]), pack2h(h[2], h[3]));
        lo[o4 + c4] = make_uint2(pack2h(l[0], l[1]), pack2h(l[2], l[3]));
    }
}

// ---------------------------------------------------------------------------
// fp16 tensor-core GEMM: C[m,n] = sum_k A[m,k]*W[n,k] + bias[n]
// A = Ahi + Alo*2^-11 (fp16 planes), W = fp16 hi only.
// Two accumulators: acc (ah*bh), acc2 (al'*bh); x = acc + acc2/2048 + bias.
// MODE 0: fp32 row-major out. MODE 2: bf16 hi/lo head-split out (for flash).
// 4-stage cp.async pipeline, 3 planes/stage.
// ---------------------------------------------------------------------------
#define BK 32
#define PAD 40
#define TILE_E (128 * PAD)           /* 5120 elems */
#define TILE_B (TILE_E * 2)          /* 10240 B */
#define STAGE_B (3 * TILE_B)         /* 30720 B */
#define NSTAGE 4
#define GEMM_SMEM (NSTAGE * STAGE_B) /* 122880 */

template <int MODE>
__global__ void __launch_bounds__(512)
gemm_mma_kernel(const __half* __restrict__ Ahi,
                const __half* __restrict__ Alo,
                const __half* __restrict__ Wh,
                const float* __restrict__ bias, float* __restrict__ C,
                __nv_bfloat16* __restrict__ Chi, __nv_bfloat16* __restrict__ Clo,
                const int* __restrict__ cnt)
{
    extern __shared__ char dsm[];
    const uint32_t sb = smem_u32(dsm);
    const int tid = threadIdx.x;
    const int wid = tid >> 5;
    const int lane = tid & 31;
    const int m0 = blockIdx.y * 128;
    const int n0 = blockIdx.x * 128;
    const int wm = wid & 3;
    const int wn = wid >> 2;

    if (cnt) {
        const int npad = (cnt[m0 >> 11] + 127) & ~127;
        if ((m0 & 2047) >= npad) return;
    }

    float acc[2][4][4], acc2[2][4][4];
#pragma unroll
    for (int a = 0; a < 2; a++)
#pragma unroll
        for (int b = 0; b < 4; b++)
#pragma unroll
            for (int c = 0; c < 4; c++) { acc[a][b][c] = 0.0f; acc2[a][b][c] = 0.0f; }

    // 1536 16B-chunks per stage (3 tiles x 512), 3 per thread.
    auto prefetch = [&](int iter) {
        if (iter < DMODEL / BK) {
            const int k0 = iter * BK;
            const uint32_t stage_base = sb + (uint32_t)((iter % NSTAGE) * STAGE_B);
#pragma unroll
            for (int t = 0; t < 3; t++) {
                const int c = tid + t * 512;        // 0..1535
                const int tile = c >> 9;            // 0..2
                const int w = c & 511;
                const int row = w >> 2;
                const int kc = (w & 3) * 8;
                const uint32_t saddr =
                    stage_base + (uint32_t)(tile * TILE_B + (row * PAD + kc) * 2);
                const __half* gp;
                if (tile == 0)      gp = Ahi + (size_t)(m0 + row) * DMODEL + k0 + kc;
                else if (tile == 1) gp = Alo + (size_t)(m0 + row) * DMODEL + k0 + kc;
                else                gp = Wh + (size_t)(n0 + row) * DMODEL + k0 + kc;
                cp16(saddr, gp);
            }
        }
        asm volatile("cp.async.commit_group;");
    };

    const int a_row = lane & 15;
    const int a_k   = (lane >> 4) << 3;
    const int b_n   = ((lane >> 4) << 3) + (lane & 7);
    const int b_k   = lane & 8;

    prefetch(0);
    prefetch(1);
    prefetch(2);

    for (int iter = 0; iter < DMODEL / BK; iter++) {
        asm volatile("cp.async.wait_group 2;");
        __syncthreads();
        prefetch(iter + 3);

        const uint32_t st = sb + (uint32_t)((iter % NSTAGE) * STAGE_B);
#pragma unroll
        for (int ks = 0; ks < BK; ks += 16) {
            uint32_t ah[2][4], al[2][4];
#pragma unroll
            for (int mt = 0; mt < 2; mt++) {
                const int row = wm * 32 + mt * 16 + a_row;
                const uint32_t off = (uint32_t)((row * PAD + ks + a_k) * 2);
                ldm_x4(ah[mt], st + 0 * TILE_B + off);
                ldm_x4(al[mt], st + 1 * TILE_B + off);
            }
            uint32_t bh[4][2];
#pragma unroll
            for (int np = 0; np < 2; np++) {
                const int n = wn * 32 + np * 16 + b_n;
                const uint32_t off = (uint32_t)((n * PAD + ks + b_k) * 2);
                uint32_t r[4];
                ldm_x4(r, st + 2 * TILE_B + off);
                bh[2 * np][0] = r[0]; bh[2 * np][1] = r[1];
                bh[2 * np + 1][0] = r[2]; bh[2 * np + 1][1] = r[3];
            }
#pragma unroll
            for (int mt = 0; mt < 2; mt++)
#pragma unroll
                for (int nt = 0; nt < 4; nt++) {
                    mma_f16(acc[mt][nt],  ah[mt], bh[nt]);
                    mma_f16(acc2[mt][nt], al[mt], bh[nt]);
                }
        }
    }

    const int qrow = lane >> 2;
    const int qcol = (lane & 3) * 2;
#pragma unroll
    for (int mt = 0; mt < 2; mt++) {
#pragma unroll
        for (int nt = 0; nt < 4; nt++) {
            const int n = n0 + wn * 32 + nt * 8 + qcol;
            const float b0 = bias[n], b1 = bias[n + 1];
#pragma unroll
            for (int rp = 0; rp < 2; rp++) {
                const int m = m0 + wm * 32 + mt * 16 + qrow + rp * 8;
                float x0 = acc[mt][nt][2 * rp + 0] + acc2[mt][nt][2 * rp + 0] * LO_INV + b0;
                float x1 = acc[mt][nt][2 * rp + 1] + acc2[mt][nt][2 * rp + 1] * LO_INV + b1;
                if (MODE == 0) {
                    *(float2*)&C[(size_t)m * DMODEL + n] = make_float2(x0, x1);
                } else {
                    const int h = n >> 6, dk = n & 63;
                    const int b = m >> 11, s = m & 2047;
                    const size_t idx =
                        (((size_t)(b * HEADS + h) * S_LEN + s)) * DKH + dk;
                    __nv_bfloat16 h0 = __float2bfloat16_rn(x0);
                    __nv_bfloat16 h1 = __float2bfloat16_rn(x1);
                    __nv_bfloat16 l0 = __float2bfloat16_rn(x0 - __bfloat162float(h0));
                    __nv_bfloat16 l1 = __float2bfloat16_rn(x1 - __bfloat162float(h1));
                    *(uint32_t*)(Chi + idx) = pack2(h0, h1);
                    *(uint32_t*)(Clo + idx) = pack2(l0, l1);
                }
            }
        }
    }
}

// ---------------------------------------------------------------------------
// Tensor-core flash attention over COMPACTED keys (bf16 3-term, unchanged),
// epilogue now emits fp16 hi / scaled-lo planes for the out-projection.
// ---------------------------------------------------------------------------
#define FPAD 144
#define QPLANE (128 * FPAD)
#define KVPLANE (64 * FPAD)
#define FQ_HI 0
#define FQ_LO QPLANE
#define FSTG (2 * QPLANE)
#define FSSTRIDE (4 * KVPLANE)
#define FLASH_SMEM (FSTG + 2 * FSSTRIDE)

__global__ void __launch_bounds__(256)
flash_mma_kernel(const __nv_bfloat16* __restrict__ Qh,
                 const __nv_bfloat16* __restrict__ Ql,
                 const __nv_bfloat16* __restrict__ Kh,
                 const __nv_bfloat16* __restrict__ Kl,
                 const __nv_bfloat16* __restrict__ Vh,
                 const __nv_bfloat16* __restrict__ Vl,
                 const int* __restrict__ cnt,
                 __half* __restrict__ Ohi,
                 __half* __restrict__ Olo)
{
    extern __shared__ char fsm[];
    const uint32_t sb = smem_u32(fsm);
    const int tid = threadIdx.x;
    const int wid = tid >> 5;
    const int lane = tid & 31;
    const int bh = blockIdx.y;
    const int b = bh >> 4;
    const int h = bh & 15;
    const int q0 = blockIdx.x * 128;

    const int nb = cnt[b];
    const int ntiles = (nb + 63) >> 6;

    auto prefetch_t = [&](int t) {
        if (t < ntiles) {
            const uint32_t stbase = sb + FSTG + (uint32_t)((t & 1) * FSSTRIDE);
            const int kb = t * 64;
#pragma unroll
            for (int i = 0; i < 8; i++) {
                const int c = tid + i * 256;
                const int pl = c >> 9;
                const int w = c & 511;
                const int row = w >> 3;
                const int col = w & 7;
                const __nv_bfloat16* base =
                    (pl == 0) ? Kh : (pl == 1) ? Kl : (pl == 2) ? Vh : Vl;
                cp16(stbase + (uint32_t)(pl * KVPLANE + row * FPAD + col * 16),
                     base + ((size_t)bh * S_LEN + kb + row) * DKH + col * 8);
            }
        }
        asm volatile("cp.async.commit_group;");
    };

#pragma unroll
    for (int i = 0; i < 8; i++) {
        const int c = tid + i * 256;
        const int pl = c >> 10;
        const int w = c & 1023;
        const int row = w >> 3;
        const int col = w & 7;
        const __nv_bfloat16* base = pl ? Ql : Qh;
        cp16(sb + (uint32_t)(pl * QPLANE + row * FPAD + col * 16),
             base + ((size_t)bh * S_LEN + q0 + row) * DKH + col * 8);
    }
    asm volatile("cp.async.commit_group;");

    prefetch_t(0);

    asm volatile("cp.async.wait_group 1;");
    __syncthreads();

    const int a_row = lane & 15;
    const int a_k8  = (lane >> 4) << 3;
    uint32_t qh[4][4], ql[4][4];
#pragma unroll
    for (int ks = 0; ks < 4; ks++) {
        const uint32_t off =
            (uint32_t)((wid * 16 + a_row) * FPAD + (ks * 16 + a_k8) * 2);
        ldm_x4(qh[ks], sb + FQ_HI + off);
        ldm_x4(ql[ks], sb + FQ_LO + off);
    }

    prefetch_t(1);

    float o[8][4];
#pragma unroll
    for (int j = 0; j < 8; j++)
#pragma unroll
        for (int c = 0; c < 4; c++) o[j][c] = 0.0f;
    float mrow0 = -INFINITY, mrow1 = -INFINITY;
    float lrow0 = 0.0f, lrow1 = 0.0f;

    const int b_n = ((lane >> 4) << 3) + (lane & 7);
    const int b_k = lane & 8;

    for (int t = 0; t < ntiles; t++) {
        asm volatile("cp.async.wait_group 1;");
        __syncthreads();
        const uint32_t st = sb + FSTG + (uint32_t)((t & 1) * FSSTRIDE);
        const int kb = t * 64;

        float s[8][4];
#pragma unroll
        for (int j = 0; j < 8; j++)
#pragma unroll
            for (int c = 0; c < 4; c++) s[j][c] = 0.0f;
#pragma unroll
        for (int ks = 0; ks < 4; ks++) {
#pragma unroll
            for (int ng = 0; ng < 4; ng++) {
                const uint32_t kaddr =
                    st + (uint32_t)((ng * 16 + b_n) * FPAD + (ks * 16 + b_k) * 2);
                uint32_t kh[4], kl[4];
                ldm_x4(kh, kaddr);
                ldm_x4(kl, kaddr + KVPLANE);
                mma_bf16(s[2 * ng],     qh[ks], kh);
                mma_bf16(s[2 * ng],     ql[ks], kh);
                mma_bf16(s[2 * ng],     qh[ks], kl);
                mma_bf16(s[2 * ng + 1], qh[ks], kh + 2);
                mma_bf16(s[2 * ng + 1], ql[ks], kh + 2);
                mma_bf16(s[2 * ng + 1], qh[ks], kl + 2);
            }
        }

        float rm0 = -INFINITY, rm1 = -INFINITY;
#pragma unroll
        for (int j = 0; j < 8; j++) {
            const int key0 = kb + j * 8 + 2 * (lane & 3);
            const bool mx = key0 < nb;
            const bool my = key0 + 1 < nb;
            s[j][0] = mx ? s[j][0] * 0.125f : NEGV;
            s[j][1] = my ? s[j][1] * 0.125f : NEGV;
            s[j][2] = mx ? s[j][2] * 0.125f : NEGV;
            s[j][3] = my ? s[j][3] * 0.125f : NEGV;
            rm0 = fmaxf(rm0, fmaxf(s[j][0], s[j][1]));
            rm1 = fmaxf(rm1, fmaxf(s[j][2], s[j][3]));
        }
#pragma unroll
        for (int off = 1; off < 4; off <<= 1) {
            rm0 = fmaxf(rm0, __shfl_xor_sync(0xffffffffu, rm0, off));
            rm1 = fmaxf(rm1, __shfl_xor_sync(0xffffffffu, rm1, off));
        }

        const float mn0 = fmaxf(mrow0, rm0);
        const float mn1 = fmaxf(mrow1, rm1);
        const float cor0 = __expf(mrow0 - mn0);
        const float cor1 = __expf(mrow1 - mn1);
        mrow0 = mn0; mrow1 = mn1;

        float rs0 = 0.0f, rs1 = 0.0f;
        uint32_t ph[4][4], pl[4][4];
#pragma unroll
        for (int j = 0; j < 8; j++) {
            const float p0 = __expf(s[j][0] - mn0);
            const float p1 = __expf(s[j][1] - mn0);
            const float p2 = __expf(s[j][2] - mn1);
            const float p3 = __expf(s[j][3] - mn1);
            rs0 += p0 + p1;
            rs1 += p2 + p3;
            const __nv_bfloat16 h0 = __float2bfloat16_rn(p0);
            const __nv_bfloat16 h1 = __float2bfloat16_rn(p1);
            const __nv_bfloat16 h2 = __float2bfloat16_rn(p2);
            const __nv_bfloat16 h3 = __float2bfloat16_rn(p3);
            const __nv_bfloat16 l0 = __float2bfloat16_rn(p0 - __bfloat162float(h0));
            const __nv_bfloat16 l1 = __float2bfloat16_rn(p1 - __bfloat162float(h1));
            const __nv_bfloat16 l2 = __float2bfloat16_rn(p2 - __bfloat162float(h2));
            const __nv_bfloat16 l3 = __float2bfloat16_rn(p3 - __bfloat162float(h3));
            const int kc = j >> 1;
            const int hf = (j & 1) * 2;
            ph[kc][hf + 0] = pack2(h0, h1);
            ph[kc][hf + 1] = pack2(h2, h3);
            pl[kc][hf + 0] = pack2(l0, l1);
            pl[kc][hf + 1] = pack2(l2, l3);
        }
#pragma unroll
        for (int off = 1; off < 4; off <<= 1) {
            rs0 += __shfl_xor_sync(0xffffffffu, rs0, off);
            rs1 += __shfl_xor_sync(0xffffffffu, rs1, off);
        }
        lrow0 = lrow0 * cor0 + rs0;
        lrow1 = lrow1 * cor1 + rs1;
#pragma unroll
        for (int j = 0; j < 8; j++) {
            o[j][0] *= cor0; o[j][1] *= cor0;
            o[j][2] *= cor1; o[j][3] *= cor1;
        }

#pragma unroll
        for (int kc = 0; kc < 4; kc++) {
#pragma unroll
            for (int vg = 0; vg < 4; vg++) {
                const uint32_t vaddr =
                    st + (uint32_t)(2 * KVPLANE + (kc * 16 + (lane & 15)) * FPAD +
                                    (vg * 16 + a_k8) * 2);
                uint32_t vh[4], vl[4];
                ldm_x4_t(vh, vaddr);
                ldm_x4_t(vl, vaddr + KVPLANE);
                mma_bf16(o[2 * vg],     ph[kc], vh);
                mma_bf16(o[2 * vg],     pl[kc], vh);
                mma_bf16(o[2 * vg],     ph[kc], vl);
                mma_bf16(o[2 * vg + 1], ph[kc], vh + 2);
                mma_bf16(o[2 * vg + 1], pl[kc], vh + 2);
                mma_bf16(o[2 * vg + 1], ph[kc], vl + 2);
            }
        }

        __syncthreads();
        prefetch_t(t + 2);
    }

    // epilogue -> fp16 hi / scaled lo planes (row-major)
    const float inv0 = 1.0f / lrow0;
    const float inv1 = 1.0f / lrow1;
    const int r0 = q0 + wid * 16 + (lane >> 2);
    const size_t row0 = (size_t)(b * S_LEN + r0) * DMODEL;
    const size_t row1 = (size_t)(b * S_LEN + r0 + 8) * DMODEL;
#pragma unroll
    for (int j = 0; j < 8; j++) {
        const int col = h * DKH + j * 8 + 2 * (lane & 3);
        {
            const float x0 = o[j][0] * inv0, x1 = o[j][1] * inv0;
            __half h0, l0, h1, l1;
            split_h(x0, h0, l0);
            split_h(x1, h1, l1);
            *(uint32_t*)(Ohi + row0 + col) = pack2h(h0, h1);
            *(uint32_t*)(Olo + row0 + col) = pack2h(l0, l1);
        }
        {
            const float x2 = o[j][2] * inv1, x3 = o[j][3] * inv1;
            __half h2, l2, h3, l3;
            split_h(x2, h2, l2);
            split_h(x3, h3, l3);
            *(uint32_t*)(Ohi + row1 + col) = pack2h(h2, h3);
            *(uint32_t*)(Olo + row1 + col) = pack2h(l2, l3);
        }
    }
}

// ---------------------------------------------------------------------------
extern "C" void kernel_launch(void* const* d_in, const int* in_sizes, int n_in,
                              void* d_out, int out_size)
{
    const float* query = (const float*)d_in[0];
    const float* key   = (const float*)d_in[1];
    const float* value = (const float*)d_in[2];
    const int*   mask  = (const int*)d_in[3];
    const float* Wmat[4] = {(const float*)d_in[4], (const float*)d_in[6],
                            (const float*)d_in[8], (const float*)d_in[10]};
    const float* bvec[4] = {(const float*)d_in[5], (const float*)d_in[7],
                            (const float*)d_in[9], (const float*)d_in[11]};
    float* out = (float*)d_out;

    __half *ahi, *alo, *wh;
    __nv_bfloat16 *qhi, *qlo, *khi, *klo, *vhi, *vlo;
    int *idxp, *cntp;
    cudaGetSymbolAddress((void**)&ahi, g_ahi);
    cudaGetSymbolAddress((void**)&alo, g_alo);
    cudaGetSymbolAddress((void**)&qhi, g_qhi);
    cudaGetSymbolAddress((void**)&qlo, g_qlo);
    cudaGetSymbolAddress((void**)&khi, g_khi);
    cudaGetSymbolAddress((void**)&klo, g_klo);
    cudaGetSymbolAddress((void**)&vhi, g_vhi);
    cudaGetSymbolAddress((void**)&vlo, g_vlo);
    cudaGetSymbolAddress((void**)&wh, g_wh);
    cudaGetSymbolAddress((void**)&idxp, g_idx);
    cudaGetSymbolAddress((void**)&cntp, g_cnt);

    cudaFuncSetAttribute(gemm_mma_kernel<0>,
                         cudaFuncAttributeMaxDynamicSharedMemorySize, GEMM_SMEM);
    cudaFuncSetAttribute(gemm_mma_kernel<2>,
                         cudaFuncAttributeMaxDynamicSharedMemorySize, GEMM_SMEM);
    cudaFuncSetAttribute(flash_mma_kernel,
                         cudaFuncAttributeMaxDynamicSharedMemorySize, FLASH_SMEM);

    const int na4 = MROWS * DMODEL / 4;
    const int nwAll4 = 4 * DMODEL * DMODEL / 4;

    mask_scan_kernel<<<BATCH, 1024>>>(mask, idxp, cntp);
    split_w_kernel<<<(nwAll4 + 255) / 256, 256>>>(
        (const float4*)Wmat[0], (const float4*)Wmat[1],
        (const float4*)Wmat[2], (const float4*)Wmat[3], (uint2*)wh);

    dim3 gg(DMODEL / 128, MROWS / 128);

    // Q projection
    split_a_kernel<<<(na4 + 255) / 256, 256>>>((const float4*)query,
                                               (uint2*)ahi, (uint2*)alo, na4);
    gemm_mma_kernel<2><<<gg, 512, GEMM_SMEM>>>(
        ahi, alo, wh + 0 * (size_t)DMODEL * DMODEL, bvec[0],
        nullptr, qhi, qlo, nullptr);
    // K projection (compacted)
    gather_split_kernel<<<MROWS / 8, 256>>>(key, idxp, cntp, (uint2*)ahi,
                                            (uint2*)alo);
    gemm_mma_kernel<2><<<gg, 512, GEMM_SMEM>>>(
        ahi, alo, wh + 1 * (size_t)DMODEL * DMODEL, bvec[1],
        nullptr, khi, klo, cntp);
    // V projection (compacted)
    gather_split_kernel<<<MROWS / 8, 256>>>(value, idxp, cntp, (uint2*)ahi,
                                            (uint2*)alo);
    gemm_mma_kernel<2><<<gg, 512, GEMM_SMEM>>>(
        ahi, alo, wh + 2 * (size_t)DMODEL * DMODEL, bvec[2],
        nullptr, vhi, vlo, cntp);

    // attention (bf16 3-term) -> fp16 planes for out-projection
    dim3 fg(S_LEN / 128, BATCH * HEADS);
    flash_mma_kernel<<<fg, 256, FLASH_SMEM>>>(qhi, qlo, khi, klo, vhi, vlo,
                                              cntp, ahi, alo);

    // output projection (fp32 out)
    gemm_mma_kernel<0><<<gg, 512, GEMM_SMEM>>>(
        ahi, alo, wh + 3 * (size_t)DMODEL * DMODEL, bvec[3],
        out, nullptr, nullptr, nullptr);
}

// round 9
// speedup vs baseline: 6.6582x; 1.1636x over previous
#include <cuda_runtime.h>
#include <cuda_bf16.h>
#include <cuda_fp16.h>
#include <math.h>
#include <stdint.h>

#define S_LEN 2048
#define BATCH 4
#define HEADS 16
#define DKH 64
#define DMODEL 1024
#define MROWS (BATCH * S_LEN)  /* 8192 */
#define NEGV -1000000000.0f
#define LO_SCALE 2048.0f
#define LO_INV (1.0f / 2048.0f)

// ---------------------------------------------------------------------------
// Scratch (device globals; no allocation allowed)
// ---------------------------------------------------------------------------
__device__ __half g_aq_h[MROWS * DMODEL];   // Q-input planes; reused as flash out
__device__ __half g_aq_l[MROWS * DMODEL];
__device__ __half g_ak_h[MROWS * DMODEL];
__device__ __half g_ak_l[MROWS * DMODEL];
__device__ __half g_av_h[MROWS * DMODEL];
__device__ __half g_av_l[MROWS * DMODEL];
__device__ __nv_bfloat16 g_qhi[MROWS * DMODEL];   // flash Q/K operands (bf16)
__device__ __nv_bfloat16 g_qlo[MROWS * DMODEL];
__device__ __nv_bfloat16 g_khi[MROWS * DMODEL];
__device__ __nv_bfloat16 g_klo[MROWS * DMODEL];
__device__ __half g_vh[MROWS * DMODEL];           // flash V operand (fp16)
__device__ __half g_wh[4][DMODEL * DMODEL];       // W fp16 hi planes
__device__ int g_idx[BATCH * S_LEN];
__device__ int g_cnt[BATCH];

__device__ __forceinline__ uint32_t smem_u32(const void* p) {
    uint32_t addr;
    asm("{ .reg .u64 tmp; cvta.to.shared.u64 tmp, %1; cvt.u32.u64 %0, tmp; }"
        : "=r"(addr) : "l"(p));
    return addr;
}

__device__ __forceinline__ uint32_t pack2(__nv_bfloat16 a, __nv_bfloat16 b) {
    return (uint32_t)__bfloat16_as_ushort(a) |
           ((uint32_t)__bfloat16_as_ushort(b) << 16);
}

__device__ __forceinline__ uint32_t pack2h(__half a, __half b) {
    return (uint32_t)__half_as_ushort(a) |
           ((uint32_t)__half_as_ushort(b) << 16);
}

__device__ __forceinline__ void ldm_x4(uint32_t* r, uint32_t addr) {
    asm volatile("ldmatrix.sync.aligned.m8n8.x4.shared.b16 {%0,%1,%2,%3}, [%4];"
                 : "=r"(r[0]), "=r"(r[1]), "=r"(r[2]), "=r"(r[3]) : "r"(addr));
}

__device__ __forceinline__ void ldm_x4_t(uint32_t* r, uint32_t addr) {
    asm volatile("ldmatrix.sync.aligned.m8n8.x4.trans.shared.b16 {%0,%1,%2,%3}, [%4];"
                 : "=r"(r[0]), "=r"(r[1]), "=r"(r[2]), "=r"(r[3]) : "r"(addr));
}

__device__ __forceinline__ void mma_bf16(float* c, const uint32_t* a, const uint32_t* b) {
    asm volatile(
        "mma.sync.aligned.m16n8k16.row.col.f32.bf16.bf16.f32 "
        "{%0,%1,%2,%3}, {%4,%5,%6,%7}, {%8,%9}, {%0,%1,%2,%3};"
        : "+f"(c[0]), "+f"(c[1]), "+f"(c[2]), "+f"(c[3])
        : "r"(a[0]), "r"(a[1]), "r"(a[2]), "r"(a[3]), "r"(b[0]), "r"(b[1]));
}

__device__ __forceinline__ void mma_f16(float* c, const uint32_t* a, const uint32_t* b) {
    asm volatile(
        "mma.sync.aligned.m16n8k16.row.col.f32.f16.f16.f32 "
        "{%0,%1,%2,%3}, {%4,%5,%6,%7}, {%8,%9}, {%0,%1,%2,%3};"
        : "+f"(c[0]), "+f"(c[1]), "+f"(c[2]), "+f"(c[3])
        : "r"(a[0]), "r"(a[1]), "r"(a[2]), "r"(a[3]), "r"(b[0]), "r"(b[1]));
}

__device__ __forceinline__ void cp16(uint32_t saddr, const void* gaddr) {
    asm volatile("cp.async.cg.shared.global [%0], [%1], 16;"
                 :: "r"(saddr), "l"(gaddr));
}

__device__ __forceinline__ void split_h(float x, __half& h, __half& l) {
    h = __float2half_rn(x);
    l = __float2half_rn((x - __half2float(h)) * LO_SCALE);
}

// ---------------------------------------------------------------------------
// Weights -> fp16 hi planes, one launch.
// ---------------------------------------------------------------------------
__global__ void __launch_bounds__(256)
split_w_kernel(const float4* __restrict__ w0, const float4* __restrict__ w1,
               const float4* __restrict__ w2, const float4* __restrict__ w3,
               uint2* __restrict__ out)
{
    const int n4 = DMODEL * DMODEL / 4;
    int i = blockIdx.x * blockDim.x + threadIdx.x;
    if (i >= 4 * n4) return;
    const int m = i / n4;
    const int j = i - m * n4;
    const float4* w = (m == 0) ? w0 : (m == 1) ? w1 : (m == 2) ? w2 : w3;
    float4 f = w[j];
    out[i] = make_uint2(
        pack2h(__float2half_rn(f.x), __float2half_rn(f.y)),
        pack2h(__float2half_rn(f.z), __float2half_rn(f.w)));
}

// ---------------------------------------------------------------------------
// Mask compaction.
// ---------------------------------------------------------------------------
__global__ void __launch_bounds__(1024)
mask_scan_kernel(const int* __restrict__ mask, int* __restrict__ idx,
                 int* __restrict__ cnt)
{
    __shared__ int sc[1024];
    const int b = blockIdx.x;
    const int tid = threadIdx.x;
    const int m0 = mask[b * S_LEN + 2 * tid];
    const int m1 = mask[b * S_LEN + 2 * tid + 1];
    const int c = (m0 != 0) + (m1 != 0);
    sc[tid] = c;
    __syncthreads();
    for (int off = 1; off < 1024; off <<= 1) {
        int v = (tid >= off) ? sc[tid - off] : 0;
        __syncthreads();
        sc[tid] += v;
        __syncthreads();
    }
    int pos = sc[tid] - c;
    if (m0) idx[b * S_LEN + pos++] = 2 * tid;
    if (m1) idx[b * S_LEN + pos] = 2 * tid + 1;
    if (tid == 1023) cnt[b] = sc[1023];
}

// ---------------------------------------------------------------------------
// Fused prep: z=0 split query rows (identity), z=1/2 gather+split key/value.
// grid (1024, 3) x 256 threads.
// ---------------------------------------------------------------------------
__global__ void __launch_bounds__(256)
prep_kernel(const float* __restrict__ q, const float* __restrict__ k,
            const float* __restrict__ v, const int* __restrict__ idx,
            const int* __restrict__ cnt,
            uint2* __restrict__ qh_, uint2* __restrict__ ql_,
            uint2* __restrict__ kh_, uint2* __restrict__ kl_,
            uint2* __restrict__ vh_, uint2* __restrict__ vl_)
{
    const int z = blockIdx.y;
    const int gr = blockIdx.x * 8 + (threadIdx.x >> 5);
    const int b = gr >> 11;
    const int j = gr & 2047;
    const int lane = threadIdx.x & 31;

    const float* src;
    uint2 *hi, *lo;
    bool valid;
    int srow;
    if (z == 0) {
        src = q; hi = qh_; lo = ql_; valid = true; srow = j;
    } else {
        valid = j < cnt[b];
        srow = valid ? idx[b * S_LEN + j] : 0;
        if (z == 1) { src = k; hi = kh_; lo = kl_; }
        else        { src = v; hi = vh_; lo = vl_; }
    }

    const float4* s4 =
        (const float4*)(src + ((size_t)(b * S_LEN + srow)) * DMODEL);
    const size_t o4 = (size_t)gr * (DMODEL / 4);
#pragma unroll
    for (int i = 0; i < 8; i++) {
        const int c4 = lane + i * 32;
        float4 f = valid ? s4[c4] : make_float4(0.f, 0.f, 0.f, 0.f);
        float fs[4] = {f.x, f.y, f.z, f.w};
        __half h[4], l[4];
#pragma unroll
        for (int qd = 0; qd < 4; qd++) split_h(fs[qd], h[qd], l[qd]);
        hi[o4 + c4] = make_uint2(pack2h(h[0], h[1]), pack2h(h[2], h[3]));
        lo[o4 + c4] = make_uint2(pack2h(l[0], l[1]), pack2h(l[2], l[3]));
    }
}

// ---------------------------------------------------------------------------
// GEMM common tile params
// ---------------------------------------------------------------------------
#define BK 32
#define PAD 40
#define TILE_E (128 * PAD)
#define TILE_B (TILE_E * 2)          /* 10240 B */
#define STAGE_B (3 * TILE_B)         /* 30720 B */
#define NSTAGE 4
#define GEMM_SMEM (NSTAGE * STAGE_B) /* 122880 */

// Mainloop shared by both GEMM kernels (A = Ahi + Alo*2^-11, W fp16 hi).
// Produces acc, acc2 per thread.
#define GEMM_MAINLOOP(Ahi, Alo, Wh)                                            \
    auto prefetch = [&](int iter) {                                            \
        if (iter < DMODEL / BK) {                                              \
            const int k0 = iter * BK;                                          \
            const uint32_t stage_base =                                        \
                sb + (uint32_t)((iter % NSTAGE) * STAGE_B);                    \
            _Pragma("unroll")                                                  \
            for (int t = 0; t < 3; t++) {                                      \
                const int c = tid + t * 512;                                   \
                const int tile = c >> 9;                                       \
                const int w = c & 511;                                         \
                const int row = w >> 2;                                        \
                const int kc = (w & 3) * 8;                                    \
                const uint32_t saddr = stage_base +                            \
                    (uint32_t)(tile * TILE_B + (row * PAD + kc) * 2);          \
                const __half* gp;                                              \
                if (tile == 0)      gp = Ahi + (size_t)(m0 + row) * DMODEL + k0 + kc; \
                else if (tile == 1) gp = Alo + (size_t)(m0 + row) * DMODEL + k0 + kc; \
                else                gp = Wh + (size_t)(n0 + row) * DMODEL + k0 + kc;  \
                cp16(saddr, gp);                                               \
            }                                                                  \
        }                                                                      \
        asm volatile("cp.async.commit_group;");                                \
    };                                                                         \
    const int a_row = lane & 15;                                               \
    const int a_k   = (lane >> 4) << 3;                                        \
    const int b_n   = ((lane >> 4) << 3) + (lane & 7);                         \
    const int b_k   = lane & 8;                                                \
    prefetch(0); prefetch(1); prefetch(2);                                     \
    for (int iter = 0; iter < DMODEL / BK; iter++) {                           \
        asm volatile("cp.async.wait_group 2;");                                \
        __syncthreads();                                                       \
        prefetch(iter + 3);                                                    \
        const uint32_t st = sb + (uint32_t)((iter % NSTAGE) * STAGE_B);        \
        _Pragma("unroll")                                                      \
        for (int ks = 0; ks < BK; ks += 16) {                                  \
            uint32_t ah[2][4], al[2][4];                                       \
            _Pragma("unroll")                                                  \
            for (int mt = 0; mt < 2; mt++) {                                   \
                const int row = wm * 32 + mt * 16 + a_row;                     \
                const uint32_t off = (uint32_t)((row * PAD + ks + a_k) * 2);   \
                ldm_x4(ah[mt], st + 0 * TILE_B + off);                         \
                ldm_x4(al[mt], st + 1 * TILE_B + off);                         \
            }                                                                  \
            uint32_t bh[4][2];                                                 \
            _Pragma("unroll")                                                  \
            for (int np = 0; np < 2; np++) {                                   \
                const int n = wn * 32 + np * 16 + b_n;                         \
                const uint32_t off = (uint32_t)((n * PAD + ks + b_k) * 2);     \
                uint32_t r[4];                                                 \
                ldm_x4(r, st + 2 * TILE_B + off);                              \
                bh[2 * np][0] = r[0]; bh[2 * np][1] = r[1];                    \
                bh[2 * np + 1][0] = r[2]; bh[2 * np + 1][1] = r[3];            \
            }                                                                  \
            _Pragma("unroll")                                                  \
            for (int mt = 0; mt < 2; mt++)                                     \
                _Pragma("unroll")                                              \
                for (int nt = 0; nt < 4; nt++) {                               \
                    mma_f16(acc[mt][nt],  ah[mt], bh[nt]);                     \
                    mma_f16(acc2[mt][nt], al[mt], bh[nt]);                     \
                }                                                              \
        }                                                                      \
    }

// ---------------------------------------------------------------------------
// Fused QKV projection GEMM. grid (8, 64, 3); z selects operand.
// z=0: Q -> bf16 hi/lo head-split. z=1: K -> bf16 hi/lo head-split (cnt exit).
// z=2: V -> fp16 single head-split (cnt exit).
// ---------------------------------------------------------------------------
__global__ void __launch_bounds__(512)
gemm_qkv_kernel(const __half* __restrict__ Aq_h, const __half* __restrict__ Aq_l,
                const __half* __restrict__ Ak_h, const __half* __restrict__ Ak_l,
                const __half* __restrict__ Av_h, const __half* __restrict__ Av_l,
                const __half* __restrict__ Wall,
                const float* __restrict__ bq, const float* __restrict__ bk,
                const float* __restrict__ bv,
                __nv_bfloat16* __restrict__ Qhi, __nv_bfloat16* __restrict__ Qlo,
                __nv_bfloat16* __restrict__ Khi, __nv_bfloat16* __restrict__ Klo,
                __half* __restrict__ Vh,
                const int* __restrict__ cnt)
{
    extern __shared__ char dsm[];
    const uint32_t sb = smem_u32(dsm);
    const int tid = threadIdx.x;
    const int wid = tid >> 5;
    const int lane = tid & 31;
    const int z = blockIdx.z;
    const int m0 = blockIdx.y * 128;
    const int n0 = blockIdx.x * 128;
    const int wm = wid & 3;
    const int wn = wid >> 2;

    if (z > 0) {
        const int npad = (cnt[m0 >> 11] + 127) & ~127;
        if ((m0 & 2047) >= npad) return;
    }

    const __half* Ahi = (z == 0) ? Aq_h : (z == 1) ? Ak_h : Av_h;
    const __half* Alo = (z == 0) ? Aq_l : (z == 1) ? Ak_l : Av_l;
    const __half* Wh = Wall + (size_t)z * DMODEL * DMODEL;
    const float* bias = (z == 0) ? bq : (z == 1) ? bk : bv;

    float acc[2][4][4], acc2[2][4][4];
#pragma unroll
    for (int a = 0; a < 2; a++)
#pragma unroll
        for (int b = 0; b < 4; b++)
#pragma unroll
            for (int c = 0; c < 4; c++) { acc[a][b][c] = 0.0f; acc2[a][b][c] = 0.0f; }

    GEMM_MAINLOOP(Ahi, Alo, Wh)

    const int qrow = lane >> 2;
    const int qcol = (lane & 3) * 2;
#pragma unroll
    for (int mt = 0; mt < 2; mt++) {
#pragma unroll
        for (int nt = 0; nt < 4; nt++) {
            const int n = n0 + wn * 32 + nt * 8 + qcol;
            const float b0 = bias[n], b1 = bias[n + 1];
#pragma unroll
            for (int rp = 0; rp < 2; rp++) {
                const int m = m0 + wm * 32 + mt * 16 + qrow + rp * 8;
                float x0 = acc[mt][nt][2 * rp + 0] + acc2[mt][nt][2 * rp + 0] * LO_INV + b0;
                float x1 = acc[mt][nt][2 * rp + 1] + acc2[mt][nt][2 * rp + 1] * LO_INV + b1;
                const int h = n >> 6, dk = n & 63;
                const int b = m >> 11, s = m & 2047;
                const size_t idx =
                    (((size_t)(b * HEADS + h) * S_LEN + s)) * DKH + dk;
                if (z == 2) {
                    *(uint32_t*)(Vh + idx) =
                        pack2h(__float2half_rn(x0), __float2half_rn(x1));
                } else {
                    __nv_bfloat16 h0 = __float2bfloat16_rn(x0);
                    __nv_bfloat16 h1 = __float2bfloat16_rn(x1);
                    __nv_bfloat16 l0 = __float2bfloat16_rn(x0 - __bfloat162float(h0));
                    __nv_bfloat16 l1 = __float2bfloat16_rn(x1 - __bfloat162float(h1));
                    __nv_bfloat16* Chi = (z == 0) ? Qhi : Khi;
                    __nv_bfloat16* Clo = (z == 0) ? Qlo : Klo;
                    *(uint32_t*)(Chi + idx) = pack2(h0, h1);
                    *(uint32_t*)(Clo + idx) = pack2(l0, l1);
                }
            }
        }
    }
}

// ---------------------------------------------------------------------------
// Output projection GEMM (fp32 out).
// ---------------------------------------------------------------------------
__global__ void __launch_bounds__(512)
gemm_out_kernel(const __half* __restrict__ Ah, const __half* __restrict__ Al,
                const __half* __restrict__ Wh, const float* __restrict__ bias,
                float* __restrict__ C)
{
    extern __shared__ char dsm[];
    const uint32_t sb = smem_u32(dsm);
    const int tid = threadIdx.x;
    const int wid = tid >> 5;
    const int lane = tid & 31;
    const int m0 = blockIdx.y * 128;
    const int n0 = blockIdx.x * 128;
    const int wm = wid & 3;
    const int wn = wid >> 2;

    float acc[2][4][4], acc2[2][4][4];
#pragma unroll
    for (int a = 0; a < 2; a++)
#pragma unroll
        for (int b = 0; b < 4; b++)
#pragma unroll
            for (int c = 0; c < 4; c++) { acc[a][b][c] = 0.0f; acc2[a][b][c] = 0.0f; }

    GEMM_MAINLOOP(Ah, Al, Wh)

    const int qrow = lane >> 2;
    const int qcol = (lane & 3) * 2;
#pragma unroll
    for (int mt = 0; mt < 2; mt++) {
#pragma unroll
        for (int nt = 0; nt < 4; nt++) {
            const int n = n0 + wn * 32 + nt * 8 + qcol;
            const float b0 = bias[n], b1 = bias[n + 1];
#pragma unroll
            for (int rp = 0; rp < 2; rp++) {
                const int m = m0 + wm * 32 + mt * 16 + qrow + rp * 8;
                float x0 = acc[mt][nt][2 * rp + 0] + acc2[mt][nt][2 * rp + 0] * LO_INV + b0;
                float x1 = acc[mt][nt][2 * rp + 1] + acc2[mt][nt][2 * rp + 1] * LO_INV + b1;
                *(float2*)&C[(size_t)m * DMODEL + n] = make_float2(x0, x1);
            }
        }
    }
}

// ---------------------------------------------------------------------------
// Flash attention over compacted keys.
// QK^T: bf16 3-term (Qhi+Qlo, Khi+Klo). PV: fp16 single-term (P~ fp16, V fp16),
// row-sum computed from the SAME fp16-rounded P~ so normalization cancels
// the rounding (exact softmax of perturbed scores).
// KV stage planes: kh(bf16), kl(bf16), vh(fp16).
// ---------------------------------------------------------------------------
#define FPAD 144
#define QPLANE (128 * FPAD)
#define KVPLANE (64 * FPAD)
#define FQ_HI 0
#define FQ_LO QPLANE
#define FSTG (2 * QPLANE)
#define FSSTRIDE (3 * KVPLANE)            /* 27648 */
#define FLASH_SMEM (FSTG + 2 * FSSTRIDE)  /* 92160 */

__global__ void __launch_bounds__(256)
flash_mma_kernel(const __nv_bfloat16* __restrict__ Qh,
                 const __nv_bfloat16* __restrict__ Ql,
                 const __nv_bfloat16* __restrict__ Kh,
                 const __nv_bfloat16* __restrict__ Kl,
                 const __half* __restrict__ Vh,
                 const int* __restrict__ cnt,
                 __half* __restrict__ Ohi,
                 __half* __restrict__ Olo)
{
    extern __shared__ char fsm[];
    const uint32_t sb = smem_u32(fsm);
    const int tid = threadIdx.x;
    const int wid = tid >> 5;
    const int lane = tid & 31;
    const int bh = blockIdx.y;
    const int b = bh >> 4;
    const int h = bh & 15;
    const int q0 = blockIdx.x * 128;

    const int nb = cnt[b];
    const int ntiles = (nb + 63) >> 6;

    auto prefetch_t = [&](int t) {
        if (t < ntiles) {
            const uint32_t stbase = sb + FSTG + (uint32_t)((t & 1) * FSSTRIDE);
            const int kb = t * 64;
#pragma unroll
            for (int i = 0; i < 6; i++) {
                const int c = tid + i * 256;     // 0..1535
                const int pl = c >> 9;           // 0..2
                const int w = c & 511;
                const int row = w >> 3;
                const int col = w & 7;
                const void* gp;
                if (pl == 0)
                    gp = Kh + ((size_t)bh * S_LEN + kb + row) * DKH + col * 8;
                else if (pl == 1)
                    gp = Kl + ((size_t)bh * S_LEN + kb + row) * DKH + col * 8;
                else
                    gp = Vh + ((size_t)bh * S_LEN + kb + row) * DKH + col * 8;
                cp16(stbase + (uint32_t)(pl * KVPLANE + row * FPAD + col * 16), gp);
            }
        }
        asm volatile("cp.async.commit_group;");
    };

    // Q prefetch (2 bf16 planes x 128 rows)
#pragma unroll
    for (int i = 0; i < 8; i++) {
        const int c = tid + i * 256;
        const int pl = c >> 10;
        const int w = c & 1023;
        const int row = w >> 3;
        const int col = w & 7;
        const __nv_bfloat16* base = pl ? Ql : Qh;
        cp16(sb + (uint32_t)(pl * QPLANE + row * FPAD + col * 16),
             base + ((size_t)bh * S_LEN + q0 + row) * DKH + col * 8);
    }
    asm volatile("cp.async.commit_group;");

    prefetch_t(0);

    asm volatile("cp.async.wait_group 1;");
    __syncthreads();

    const int a_row = lane & 15;
    const int a_k8  = (lane >> 4) << 3;
    uint32_t qh[4][4], ql[4][4];
#pragma unroll
    for (int ks = 0; ks < 4; ks++) {
        const uint32_t off =
            (uint32_t)((wid * 16 + a_row) * FPAD + (ks * 16 + a_k8) * 2);
        ldm_x4(qh[ks], sb + FQ_HI + off);
        ldm_x4(ql[ks], sb + FQ_LO + off);
    }

    prefetch_t(1);

    float o[8][4];
#pragma unroll
    for (int j = 0; j < 8; j++)
#pragma unroll
        for (int c = 0; c < 4; c++) o[j][c] = 0.0f;
    float mrow0 = -INFINITY, mrow1 = -INFINITY;
    float lrow0 = 0.0f, lrow1 = 0.0f;

    const int b_n = ((lane >> 4) << 3) + (lane & 7);
    const int b_k = lane & 8;

    for (int t = 0; t < ntiles; t++) {
        asm volatile("cp.async.wait_group 1;");
        __syncthreads();
        const uint32_t st = sb + FSTG + (uint32_t)((t & 1) * FSSTRIDE);
        const int kb = t * 64;

        // ---- S = Q K^T (bf16 3-term)
        float s[8][4];
#pragma unroll
        for (int j = 0; j < 8; j++)
#pragma unroll
            for (int c = 0; c < 4; c++) s[j][c] = 0.0f;
#pragma unroll
        for (int ks = 0; ks < 4; ks++) {
#pragma unroll
            for (int ng = 0; ng < 4; ng++) {
                const uint32_t kaddr =
                    st + (uint32_t)((ng * 16 + b_n) * FPAD + (ks * 16 + b_k) * 2);
                uint32_t kh[4], kl[4];
                ldm_x4(kh, kaddr);
                ldm_x4(kl, kaddr + KVPLANE);
                mma_bf16(s[2 * ng],     qh[ks], kh);
                mma_bf16(s[2 * ng],     ql[ks], kh);
                mma_bf16(s[2 * ng],     qh[ks], kl);
                mma_bf16(s[2 * ng + 1], qh[ks], kh + 2);
                mma_bf16(s[2 * ng + 1], ql[ks], kh + 2);
                mma_bf16(s[2 * ng + 1], qh[ks], kl + 2);
            }
        }

        // ---- tail mask + scale + row max
        float rm0 = -INFINITY, rm1 = -INFINITY;
#pragma unroll
        for (int j = 0; j < 8; j++) {
            const int key0 = kb + j * 8 + 2 * (lane & 3);
            const bool mx = key0 < nb;
            const bool my = key0 + 1 < nb;
            s[j][0] = mx ? s[j][0] * 0.125f : NEGV;
            s[j][1] = my ? s[j][1] * 0.125f : NEGV;
            s[j][2] = mx ? s[j][2] * 0.125f : NEGV;
            s[j][3] = my ? s[j][3] * 0.125f : NEGV;
            rm0 = fmaxf(rm0, fmaxf(s[j][0], s[j][1]));
            rm1 = fmaxf(rm1, fmaxf(s[j][2], s[j][3]));
        }
#pragma unroll
        for (int off = 1; off < 4; off <<= 1) {
            rm0 = fmaxf(rm0, __shfl_xor_sync(0xffffffffu, rm0, off));
            rm1 = fmaxf(rm1, __shfl_xor_sync(0xffffffffu, rm1, off));
        }

        const float mn0 = fmaxf(mrow0, rm0);
        const float mn1 = fmaxf(mrow1, rm1);
        const float cor0 = __expf(mrow0 - mn0);
        const float cor1 = __expf(mrow1 - mn1);
        mrow0 = mn0; mrow1 = mn1;

        // ---- P~ = fp16(exp(s - mn)); row-sum over P~ (not raw p!)
        float rs0 = 0.0f, rs1 = 0.0f;
        uint32_t ph[4][4];
#pragma unroll
        for (int j = 0; j < 8; j++) {
            const __half h0 = __float2half_rn(__expf(s[j][0] - mn0));
            const __half h1 = __float2half_rn(__expf(s[j][1] - mn0));
            const __half h2 = __float2half_rn(__expf(s[j][2] - mn1));
            const __half h3 = __float2half_rn(__expf(s[j][3] - mn1));
            rs0 += __half2float(h0) + __half2float(h1);
            rs1 += __half2float(h2) + __half2float(h3);
            const int kc = j >> 1;
            const int hf = (j & 1) * 2;
            ph[kc][hf + 0] = pack2h(h0, h1);
            ph[kc][hf + 1] = pack2h(h2, h3);
        }
#pragma unroll
        for (int off = 1; off < 4; off <<= 1) {
            rs0 += __shfl_xor_sync(0xffffffffu, rs0, off);
            rs1 += __shfl_xor_sync(0xffffffffu, rs1, off);
        }
        lrow0 = lrow0 * cor0 + rs0;
        lrow1 = lrow1 * cor1 + rs1;
#pragma unroll
        for (int j = 0; j < 8; j++) {
            o[j][0] *= cor0; o[j][1] *= cor0;
            o[j][2] *= cor1; o[j][3] *= cor1;
        }

        // ---- O += P~ V (single fp16 term)
#pragma unroll
        for (int kc = 0; kc < 4; kc++) {
#pragma unroll
            for (int vg = 0; vg < 4; vg++) {
                const uint32_t vaddr =
                    st + (uint32_t)(2 * KVPLANE + (kc * 16 + (lane & 15)) * FPAD +
                                    (vg * 16 + a_k8) * 2);
                uint32_t vf[4];
                ldm_x4_t(vf, vaddr);
                mma_f16(o[2 * vg],     ph[kc], vf);
                mma_f16(o[2 * vg + 1], ph[kc], vf + 2);
            }
        }

        __syncthreads();
        prefetch_t(t + 2);
    }

    // ---- epilogue -> fp16 hi / scaled-lo planes (row-major)
    const float inv0 = 1.0f / lrow0;
    const float inv1 = 1.0f / lrow1;
    const int r0 = q0 + wid * 16 + (lane >> 2);
    const size_t row0 = (size_t)(b * S_LEN + r0) * DMODEL;
    const size_t row1 = (size_t)(b * S_LEN + r0 + 8) * DMODEL;
#pragma unroll
    for (int j = 0; j < 8; j++) {
        const int col = h * DKH + j * 8 + 2 * (lane & 3);
        {
            const float x0 = o[j][0] * inv0, x1 = o[j][1] * inv0;
            __half h0, l0, h1, l1;
            split_h(x0, h0, l0);
            split_h(x1, h1, l1);
            *(uint32_t*)(Ohi + row0 + col) = pack2h(h0, h1);
            *(uint32_t*)(Olo + row0 + col) = pack2h(l0, l1);
        }
        {
            const float x2 = o[j][2] * inv1, x3 = o[j][3] * inv1;
            __half h2, l2, h3, l3;
            split_h(x2, h2, l2);
            split_h(x3, h3, l3);
            *(uint32_t*)(Ohi + row1 + col) = pack2h(h2, h3);
            *(uint32_t*)(Olo + row1 + col) = pack2h(l2, l3);
        }
    }
}

// ---------------------------------------------------------------------------
extern "C" void kernel_launch(void* const* d_in, const int* in_sizes, int n_in,
                              void* d_out, int out_size)
{
    const float* query = (const float*)d_in[0];
    const float* key   = (const float*)d_in[1];
    const float* value = (const float*)d_in[2];
    const int*   mask  = (const int*)d_in[3];
    const float* Wmat[4] = {(const float*)d_in[4], (const float*)d_in[6],
                            (const float*)d_in[8], (const float*)d_in[10]};
    const float* bvec[4] = {(const float*)d_in[5], (const float*)d_in[7],
                            (const float*)d_in[9], (const float*)d_in[11]};
    float* out = (float*)d_out;

    __half *aqh, *aql, *akh, *akl, *avh, *avl, *wh, *vh;
    __nv_bfloat16 *qhi, *qlo, *khi, *klo;
    int *idxp, *cntp;
    cudaGetSymbolAddress((void**)&aqh, g_aq_h);
    cudaGetSymbolAddress((void**)&aql, g_aq_l);
    cudaGetSymbolAddress((void**)&akh, g_ak_h);
    cudaGetSymbolAddress((void**)&akl, g_ak_l);
    cudaGetSymbolAddress((void**)&avh, g_av_h);
    cudaGetSymbolAddress((void**)&avl, g_av_l);
    cudaGetSymbolAddress((void**)&qhi, g_qhi);
    cudaGetSymbolAddress((void**)&qlo, g_qlo);
    cudaGetSymbolAddress((void**)&khi, g_khi);
    cudaGetSymbolAddress((void**)&klo, g_klo);
    cudaGetSymbolAddress((void**)&vh, g_vh);
    cudaGetSymbolAddress((void**)&wh, g_wh);
    cudaGetSymbolAddress((void**)&idxp, g_idx);
    cudaGetSymbolAddress((void**)&cntp, g_cnt);

    cudaFuncSetAttribute(gemm_qkv_kernel,
                         cudaFuncAttributeMaxDynamicSharedMemorySize, GEMM_SMEM);
    cudaFuncSetAttribute(gemm_out_kernel,
                         cudaFuncAttributeMaxDynamicSharedMemorySize, GEMM_SMEM);
    cudaFuncSetAttribute(flash_mma_kernel,
                         cudaFuncAttributeMaxDynamicSharedMemorySize, FLASH_SMEM);

    const int nwAll4 = 4 * DMODEL * DMODEL / 4;

    mask_scan_kernel<<<BATCH, 1024>>>(mask, idxp, cntp);
    split_w_kernel<<<(nwAll4 + 255) / 256, 256>>>(
        (const float4*)Wmat[0], (const float4*)Wmat[1],
        (const float4*)Wmat[2], (const float4*)Wmat[3], (uint2*)wh);

    // fused prep: split query + gather/split key,value
    dim3 pg(MROWS / 8, 3);
    prep_kernel<<<pg, 256>>>(query, key, value, idxp, cntp,
                             (uint2*)aqh, (uint2*)aql, (uint2*)akh,
                             (uint2*)akl, (uint2*)avh, (uint2*)avl);

    // fused QKV projections
    dim3 gq(DMODEL / 128, MROWS / 128, 3);
    gemm_qkv_kernel<<<gq, 512, GEMM_SMEM>>>(
        aqh, aql, akh, akl, avh, avl, wh,
        bvec[0], bvec[1], bvec[2],
        qhi, qlo, khi, klo, vh, cntp);

    // attention (writes fp16 hi/lo planes into aqh/aql, consumed below)
    dim3 fg(S_LEN / 128, BATCH * HEADS);
    flash_mma_kernel<<<fg, 256, FLASH_SMEM>>>(qhi, qlo, khi, klo, vh,
                                              cntp, aqh, aql);

    // output projection
    dim3 gg(DMODEL / 128, MROWS / 128);
    gemm_out_kernel<<<gg, 512, GEMM_SMEM>>>(
        aqh, aql, wh + 3 * (size_t)DMODEL * DMODEL, bvec[3], out);
}

// round 10
// speedup vs baseline: 11.5654x; 1.7370x over previous
#include <cuda_runtime.h>
#include <cuda_bf16.h>
#include <cuda_fp16.h>
#include <math.h>
#include <stdint.h>

#define S_LEN 2048
#define BATCH 4
#define HEADS 16
#define DKH 64
#define DMODEL 1024
#define MROWS (BATCH * S_LEN)  /* 8192 */
#define NEGV -1000000000.0f

// ---------------------------------------------------------------------------
// Scratch (device globals; no allocation allowed)
// ---------------------------------------------------------------------------
__device__ __half g_a[3][MROWS * DMODEL];   // fp16 input planes q/k/v; [0] reused as flash out
__device__ __half g_wh[4][DMODEL * DMODEL]; // W fp16 planes
__device__ __half g_qf[MROWS * DMODEL];     // flash Q operand (fp16, head-split)
__device__ __half g_kf[MROWS * DMODEL];     // flash K operand
__device__ __half g_vf[MROWS * DMODEL];     // flash V operand
__device__ int g_idx[BATCH * S_LEN];
__device__ int g_cnt[BATCH];

__device__ __forceinline__ uint32_t smem_u32(const void* p) {
    uint32_t addr;
    asm("{ .reg .u64 tmp; cvta.to.shared.u64 tmp, %1; cvt.u32.u64 %0, tmp; }"
        : "=r"(addr) : "l"(p));
    return addr;
}

__device__ __forceinline__ uint32_t pack2h(__half a, __half b) {
    return (uint32_t)__half_as_ushort(a) |
           ((uint32_t)__half_as_ushort(b) << 16);
}

__device__ __forceinline__ void ldm_x4(uint32_t* r, uint32_t addr) {
    asm volatile("ldmatrix.sync.aligned.m8n8.x4.shared.b16 {%0,%1,%2,%3}, [%4];"
                 : "=r"(r[0]), "=r"(r[1]), "=r"(r[2]), "=r"(r[3]) : "r"(addr));
}

__device__ __forceinline__ void ldm_x4_t(uint32_t* r, uint32_t addr) {
    asm volatile("ldmatrix.sync.aligned.m8n8.x4.trans.shared.b16 {%0,%1,%2,%3}, [%4];"
                 : "=r"(r[0]), "=r"(r[1]), "=r"(r[2]), "=r"(r[3]) : "r"(addr));
}

__device__ __forceinline__ void mma_f16(float* c, const uint32_t* a, const uint32_t* b) {
    asm volatile(
        "mma.sync.aligned.m16n8k16.row.col.f32.f16.f16.f32 "
        "{%0,%1,%2,%3}, {%4,%5,%6,%7}, {%8,%9}, {%0,%1,%2,%3};"
        : "+f"(c[0]), "+f"(c[1]), "+f"(c[2]), "+f"(c[3])
        : "r"(a[0]), "r"(a[1]), "r"(a[2]), "r"(a[3]), "r"(b[0]), "r"(b[1]));
}

__device__ __forceinline__ void cp16(uint32_t saddr, const void* gaddr) {
    asm volatile("cp.async.cg.shared.global [%0], [%1], 16;"
                 :: "r"(saddr), "l"(gaddr));
}

// ---------------------------------------------------------------------------
// Weights -> fp16 planes, one launch.
// ---------------------------------------------------------------------------
__global__ void __launch_bounds__(256)
split_w_kernel(const float4* __restrict__ w0, const float4* __restrict__ w1,
               const float4* __restrict__ w2, const float4* __restrict__ w3,
               uint2* __restrict__ out)
{
    const int n4 = DMODEL * DMODEL / 4;
    int i = blockIdx.x * blockDim.x + threadIdx.x;
    if (i >= 4 * n4) return;
    const int m = i / n4;
    const int j = i - m * n4;
    const float4* w = (m == 0) ? w0 : (m == 1) ? w1 : (m == 2) ? w2 : w3;
    float4 f = w[j];
    out[i] = make_uint2(
        pack2h(__float2half_rn(f.x), __float2half_rn(f.y)),
        pack2h(__float2half_rn(f.z), __float2half_rn(f.w)));
}

// ---------------------------------------------------------------------------
// Mask compaction.
// ---------------------------------------------------------------------------
__global__ void __launch_bounds__(1024)
mask_scan_kernel(const int* __restrict__ mask, int* __restrict__ idx,
                 int* __restrict__ cnt)
{
    __shared__ int sc[1024];
    const int b = blockIdx.x;
    const int tid = threadIdx.x;
    const int m0 = mask[b * S_LEN + 2 * tid];
    const int m1 = mask[b * S_LEN + 2 * tid + 1];
    const int c = (m0 != 0) + (m1 != 0);
    sc[tid] = c;
    __syncthreads();
    for (int off = 1; off < 1024; off <<= 1) {
        int v = (tid >= off) ? sc[tid - off] : 0;
        __syncthreads();
        sc[tid] += v;
        __syncthreads();
    }
    int pos = sc[tid] - c;
    if (m0) idx[b * S_LEN + pos++] = 2 * tid;
    if (m1) idx[b * S_LEN + pos] = 2 * tid + 1;
    if (tid == 1023) cnt[b] = sc[1023];
}

// ---------------------------------------------------------------------------
// Fused prep: z=0 convert query rows; z=1/2 gather+convert key/value rows.
// Single fp16 plane per operand. grid (1024, 3) x 256 threads.
// ---------------------------------------------------------------------------
__global__ void __launch_bounds__(256)
prep_kernel(const float* __restrict__ q, const float* __restrict__ k,
            const float* __restrict__ v, const int* __restrict__ idx,
            const int* __restrict__ cnt,
            uint2* __restrict__ aq, uint2* __restrict__ ak,
            uint2* __restrict__ av)
{
    const int z = blockIdx.y;
    const int gr = blockIdx.x * 8 + (threadIdx.x >> 5);
    const int b = gr >> 11;
    const int j = gr & 2047;
    const int lane = threadIdx.x & 31;

    const float* src;
    uint2* dst;
    bool valid;
    int srow;
    if (z == 0) {
        src = q; dst = aq; valid = true; srow = j;
    } else {
        valid = j < cnt[b];
        srow = valid ? idx[b * S_LEN + j] : 0;
        if (z == 1) { src = k; dst = ak; }
        else        { src = v; dst = av; }
    }

    const float4* s4 =
        (const float4*)(src + ((size_t)(b * S_LEN + srow)) * DMODEL);
    const size_t o4 = (size_t)gr * (DMODEL / 4);
#pragma unroll
    for (int i = 0; i < 8; i++) {
        const int c4 = lane + i * 32;
        float4 f = valid ? s4[c4] : make_float4(0.f, 0.f, 0.f, 0.f);
        dst[o4 + c4] = make_uint2(
            pack2h(__float2half_rn(f.x), __float2half_rn(f.y)),
            pack2h(__float2half_rn(f.z), __float2half_rn(f.w)));
    }
}

// ---------------------------------------------------------------------------
// GEMM tile params: 2 planes/stage, 5-stage pipeline.
// ---------------------------------------------------------------------------
#define BK 32
#define PAD 40
#define TILE_E (128 * PAD)
#define TILE_B (TILE_E * 2)          /* 10240 B */
#define STAGE_B (2 * TILE_B)         /* 20480 B */
#define NSTAGE 5
#define GEMM_SMEM (NSTAGE * STAGE_B) /* 102400 */

// Mainloop: single fp16 A plane x single fp16 W plane -> acc.
#define GEMM_MAINLOOP(Ah, Wh)                                                  \
    auto prefetch = [&](int iter) {                                            \
        if (iter < DMODEL / BK) {                                              \
            const int k0 = iter * BK;                                          \
            const uint32_t stage_base =                                        \
                sb + (uint32_t)((iter % NSTAGE) * STAGE_B);                    \
            _Pragma("unroll")                                                  \
            for (int t = 0; t < 2; t++) {                                      \
                const int c = tid + t * 512;                                   \
                const int tile = c >> 9;                                       \
                const int w = c & 511;                                         \
                const int row = w >> 2;                                        \
                const int kc = (w & 3) * 8;                                    \
                const uint32_t saddr = stage_base +                            \
                    (uint32_t)(tile * TILE_B + (row * PAD + kc) * 2);          \
                const __half* gp = (tile == 0)                                 \
                    ? Ah + (size_t)(m0 + row) * DMODEL + k0 + kc               \
                    : Wh + (size_t)(n0 + row) * DMODEL + k0 + kc;              \
                cp16(saddr, gp);                                               \
            }                                                                  \
        }                                                                      \
        asm volatile("cp.async.commit_group;");                                \
    };                                                                         \
    const int a_row = lane & 15;                                               \
    const int a_k   = (lane >> 4) << 3;                                        \
    const int b_n   = ((lane >> 4) << 3) + (lane & 7);                         \
    const int b_k   = lane & 8;                                                \
    prefetch(0); prefetch(1); prefetch(2); prefetch(3);                        \
    for (int iter = 0; iter < DMODEL / BK; iter++) {                           \
        asm volatile("cp.async.wait_group 3;");                                \
        __syncthreads();                                                       \
        prefetch(iter + 4);                                                    \
        const uint32_t st = sb + (uint32_t)((iter % NSTAGE) * STAGE_B);        \
        _Pragma("unroll")                                                      \
        for (int ks = 0; ks < BK; ks += 16) {                                  \
            uint32_t ah[2][4];                                                 \
            _Pragma("unroll")                                                  \
            for (int mt = 0; mt < 2; mt++) {                                   \
                const int row = wm * 32 + mt * 16 + a_row;                     \
                ldm_x4(ah[mt], st + (uint32_t)((row * PAD + ks + a_k) * 2));   \
            }                                                                  \
            uint32_t bh[4][2];                                                 \
            _Pragma("unroll")                                                  \
            for (int np = 0; np < 2; np++) {                                   \
                const int n = wn * 32 + np * 16 + b_n;                         \
                uint32_t r[4];                                                 \
                ldm_x4(r, st + TILE_B + (uint32_t)((n * PAD + ks + b_k) * 2)); \
                bh[2 * np][0] = r[0]; bh[2 * np][1] = r[1];                    \
                bh[2 * np + 1][0] = r[2]; bh[2 * np + 1][1] = r[3];            \
            }                                                                  \
            _Pragma("unroll")                                                  \
            for (int mt = 0; mt < 2; mt++)                                     \
                _Pragma("unroll")                                              \
                for (int nt = 0; nt < 4; nt++)                                 \
                    mma_f16(acc[mt][nt], ah[mt], bh[nt]);                      \
        }                                                                      \
    }

// ---------------------------------------------------------------------------
// Fused QKV projection GEMM. grid (8, 64, 3); z selects operand.
// All outputs: single fp16 plane, head-split layout. z>0 uses cnt early-exit.
// ---------------------------------------------------------------------------
__global__ void __launch_bounds__(512)
gemm_qkv_kernel(const __half* __restrict__ Aall, const __half* __restrict__ Wall,
                const float* __restrict__ bq, const float* __restrict__ bk,
                const float* __restrict__ bv,
                __half* __restrict__ Qf, __half* __restrict__ Kf,
                __half* __restrict__ Vf,
                const int* __restrict__ cnt)
{
    extern __shared__ char dsm[];
    const uint32_t sb = smem_u32(dsm);
    const int tid = threadIdx.x;
    const int wid = tid >> 5;
    const int lane = tid & 31;
    const int z = blockIdx.z;
    const int m0 = blockIdx.y * 128;
    const int n0 = blockIdx.x * 128;
    const int wm = wid & 3;
    const int wn = wid >> 2;

    if (z > 0) {
        const int npad = (cnt[m0 >> 11] + 127) & ~127;
        if ((m0 & 2047) >= npad) return;
    }

    const __half* Ah = Aall + (size_t)z * MROWS * DMODEL;
    const __half* Wh = Wall + (size_t)z * DMODEL * DMODEL;
    const float* bias = (z == 0) ? bq : (z == 1) ? bk : bv;
    __half* Of = (z == 0) ? Qf : (z == 1) ? Kf : Vf;

    float acc[2][4][4];
#pragma unroll
    for (int a = 0; a < 2; a++)
#pragma unroll
        for (int b = 0; b < 4; b++)
#pragma unroll
            for (int c = 0; c < 4; c++) acc[a][b][c] = 0.0f;

    GEMM_MAINLOOP(Ah, Wh)

    const int qrow = lane >> 2;
    const int qcol = (lane & 3) * 2;
#pragma unroll
    for (int mt = 0; mt < 2; mt++) {
#pragma unroll
        for (int nt = 0; nt < 4; nt++) {
            const int n = n0 + wn * 32 + nt * 8 + qcol;
            const float b0 = bias[n], b1 = bias[n + 1];
            const int h = n >> 6, dk = n & 63;
#pragma unroll
            for (int rp = 0; rp < 2; rp++) {
                const int m = m0 + wm * 32 + mt * 16 + qrow + rp * 8;
                const float x0 = acc[mt][nt][2 * rp + 0] + b0;
                const float x1 = acc[mt][nt][2 * rp + 1] + b1;
                const int b = m >> 11, s = m & 2047;
                const size_t idx =
                    (((size_t)(b * HEADS + h) * S_LEN + s)) * DKH + dk;
                *(uint32_t*)(Of + idx) =
                    pack2h(__float2half_rn(x0), __float2half_rn(x1));
            }
        }
    }
}

// ---------------------------------------------------------------------------
// Output projection GEMM (fp32 out).
// ---------------------------------------------------------------------------
__global__ void __launch_bounds__(512)
gemm_out_kernel(const __half* __restrict__ Ah, const __half* __restrict__ Wh,
                const float* __restrict__ bias, float* __restrict__ C)
{
    extern __shared__ char dsm[];
    const uint32_t sb = smem_u32(dsm);
    const int tid = threadIdx.x;
    const int wid = tid >> 5;
    const int lane = tid & 31;
    const int m0 = blockIdx.y * 128;
    const int n0 = blockIdx.x * 128;
    const int wm = wid & 3;
    const int wn = wid >> 2;

    float acc[2][4][4];
#pragma unroll
    for (int a = 0; a < 2; a++)
#pragma unroll
        for (int b = 0; b < 4; b++)
#pragma unroll
            for (int c = 0; c < 4; c++) acc[a][b][c] = 0.0f;

    GEMM_MAINLOOP(Ah, Wh)

    const int qrow = lane >> 2;
    const int qcol = (lane & 3) * 2;
#pragma unroll
    for (int mt = 0; mt < 2; mt++) {
#pragma unroll
        for (int nt = 0; nt < 4; nt++) {
            const int n = n0 + wn * 32 + nt * 8 + qcol;
            const float b0 = bias[n], b1 = bias[n + 1];
#pragma unroll
            for (int rp = 0; rp < 2; rp++) {
                const int m = m0 + wm * 32 + mt * 16 + qrow + rp * 8;
                *(float2*)&C[(size_t)m * DMODEL + n] =
                    make_float2(acc[mt][nt][2 * rp + 0] + b0,
                                acc[mt][nt][2 * rp + 1] + b1);
            }
        }
    }
}

// ---------------------------------------------------------------------------
// Flash attention over compacted keys. All-fp16 operands:
// QK^T: 1 MMA (Qf x Kf). PV: 1 MMA (P~ fp16 x Vf), row-sum over the SAME
// fp16-rounded P~ so normalization cancels P-rounding.
// smem: Q plane (18432) + 2-stage KV (2 planes each) = 55296 B.
// ---------------------------------------------------------------------------
#define FPAD 144
#define QPLANE (128 * FPAD)
#define KVPLANE (64 * FPAD)
#define FSTG QPLANE
#define FSSTRIDE (2 * KVPLANE)            /* 18432 */
#define FLASH_SMEM (FSTG + 2 * FSSTRIDE)  /* 55296 */

__global__ void __launch_bounds__(256)
flash_mma_kernel(const __half* __restrict__ Qf,
                 const __half* __restrict__ Kf,
                 const __half* __restrict__ Vf,
                 const int* __restrict__ cnt,
                 __half* __restrict__ Of)
{
    extern __shared__ char fsm[];
    const uint32_t sb = smem_u32(fsm);
    const int tid = threadIdx.x;
    const int wid = tid >> 5;
    const int lane = tid & 31;
    const int bh = blockIdx.y;
    const int b = bh >> 4;
    const int h = bh & 15;
    const int q0 = blockIdx.x * 128;

    const int nb = cnt[b];
    const int ntiles = (nb + 63) >> 6;

    auto prefetch_t = [&](int t) {
        if (t < ntiles) {
            const uint32_t stbase = sb + FSTG + (uint32_t)((t & 1) * FSSTRIDE);
            const int kb = t * 64;
#pragma unroll
            for (int i = 0; i < 4; i++) {
                const int c = tid + i * 256;     // 0..1023
                const int pl = c >> 9;           // 0..1
                const int w = c & 511;
                const int row = w >> 3;
                const int col = w & 7;
                const __half* base = pl ? Vf : Kf;
                cp16(stbase + (uint32_t)(pl * KVPLANE + row * FPAD + col * 16),
                     base + ((size_t)bh * S_LEN + kb + row) * DKH + col * 8);
            }
        }
        asm volatile("cp.async.commit_group;");
    };

    // Q prefetch (1 fp16 plane x 128 rows)
#pragma unroll
    for (int i = 0; i < 4; i++) {
        const int c = tid + i * 256;      // 0..1023
        const int row = c >> 3;
        const int col = c & 7;
        cp16(sb + (uint32_t)(row * FPAD + col * 16),
             Qf + ((size_t)bh * S_LEN + q0 + row) * DKH + col * 8);
    }
    asm volatile("cp.async.commit_group;");

    prefetch_t(0);

    asm volatile("cp.async.wait_group 1;");
    __syncthreads();

    const int a_row = lane & 15;
    const int a_k8  = (lane >> 4) << 3;
    uint32_t qh[4][4];
#pragma unroll
    for (int ks = 0; ks < 4; ks++) {
        ldm_x4(qh[ks], sb + (uint32_t)((wid * 16 + a_row) * FPAD +
                                       (ks * 16 + a_k8) * 2));
    }

    prefetch_t(1);

    float o[8][4];
#pragma unroll
    for (int j = 0; j < 8; j++)
#pragma unroll
        for (int c = 0; c < 4; c++) o[j][c] = 0.0f;
    float mrow0 = -INFINITY, mrow1 = -INFINITY;
    float lrow0 = 0.0f, lrow1 = 0.0f;

    const int b_n = ((lane >> 4) << 3) + (lane & 7);
    const int b_k = lane & 8;

    for (int t = 0; t < ntiles; t++) {
        asm volatile("cp.async.wait_group 1;");
        __syncthreads();
        const uint32_t st = sb + FSTG + (uint32_t)((t & 1) * FSSTRIDE);
        const int kb = t * 64;

        // ---- S = Q K^T (single fp16 term)
        float s[8][4];
#pragma unroll
        for (int j = 0; j < 8; j++)
#pragma unroll
            for (int c = 0; c < 4; c++) s[j][c] = 0.0f;
#pragma unroll
        for (int ks = 0; ks < 4; ks++) {
#pragma unroll
            for (int ng = 0; ng < 4; ng++) {
                uint32_t kh[4];
                ldm_x4(kh, st + (uint32_t)((ng * 16 + b_n) * FPAD +
                                           (ks * 16 + b_k) * 2));
                mma_f16(s[2 * ng],     qh[ks], kh);
                mma_f16(s[2 * ng + 1], qh[ks], kh + 2);
            }
        }

        // ---- tail mask + scale + row max
        float rm0 = -INFINITY, rm1 = -INFINITY;
#pragma unroll
        for (int j = 0; j < 8; j++) {
            const int key0 = kb + j * 8 + 2 * (lane & 3);
            const bool mx = key0 < nb;
            const bool my = key0 + 1 < nb;
            s[j][0] = mx ? s[j][0] * 0.125f : NEGV;
            s[j][1] = my ? s[j][1] * 0.125f : NEGV;
            s[j][2] = mx ? s[j][2] * 0.125f : NEGV;
            s[j][3] = my ? s[j][3] * 0.125f : NEGV;
            rm0 = fmaxf(rm0, fmaxf(s[j][0], s[j][1]));
            rm1 = fmaxf(rm1, fmaxf(s[j][2], s[j][3]));
        }
#pragma unroll
        for (int off = 1; off < 4; off <<= 1) {
            rm0 = fmaxf(rm0, __shfl_xor_sync(0xffffffffu, rm0, off));
            rm1 = fmaxf(rm1, __shfl_xor_sync(0xffffffffu, rm1, off));
        }

        const float mn0 = fmaxf(mrow0, rm0);
        const float mn1 = fmaxf(mrow1, rm1);
        const float cor0 = __expf(mrow0 - mn0);
        const float cor1 = __expf(mrow1 - mn1);
        mrow0 = mn0; mrow1 = mn1;

        // ---- P~ = fp16(exp(s - mn)); row-sum over P~
        float rs0 = 0.0f, rs1 = 0.0f;
        uint32_t ph[4][4];
#pragma unroll
        for (int j = 0; j < 8; j++) {
            const __half h0 = __float2half_rn(__expf(s[j][0] - mn0));
            const __half h1 = __float2half_rn(__expf(s[j][1] - mn0));
            const __half h2 = __float2half_rn(__expf(s[j][2] - mn1));
            const __half h3 = __float2half_rn(__expf(s[j][3] - mn1));
            rs0 += __half2float(h0) + __half2float(h1);
            rs1 += __half2float(h2) + __half2float(h3);
            const int kc = j >> 1;
            const int hf = (j & 1) * 2;
            ph[kc][hf + 0] = pack2h(h0, h1);
            ph[kc][hf + 1] = pack2h(h2, h3);
        }
#pragma unroll
        for (int off = 1; off < 4; off <<= 1) {
            rs0 += __shfl_xor_sync(0xffffffffu, rs0, off);
            rs1 += __shfl_xor_sync(0xffffffffu, rs1, off);
        }
        lrow0 = lrow0 * cor0 + rs0;
        lrow1 = lrow1 * cor1 + rs1;
#pragma unroll
        for (int j = 0; j < 8; j++) {
            o[j][0] *= cor0; o[j][1] *= cor0;
            o[j][2] *= cor1; o[j][3] *= cor1;
        }

        // ---- O += P~ V
#pragma unroll
        for (int kc = 0; kc < 4; kc++) {
#pragma unroll
            for (int vg = 0; vg < 4; vg++) {
                uint32_t vf[4];
                ldm_x4_t(vf, st + (uint32_t)(KVPLANE +
                         (kc * 16 + (lane & 15)) * FPAD +
                         (vg * 16 + a_k8) * 2));
                mma_f16(o[2 * vg],     ph[kc], vf);
                mma_f16(o[2 * vg + 1], ph[kc], vf + 2);
            }
        }

        __syncthreads();
        prefetch_t(t + 2);
    }

    // ---- epilogue -> single fp16 plane (row-major)
    const float inv0 = 1.0f / lrow0;
    const float inv1 = 1.0f / lrow1;
    const int r0 = q0 + wid * 16 + (lane >> 2);
    const size_t row0 = (size_t)(b * S_LEN + r0) * DMODEL;
    const size_t row1 = (size_t)(b * S_LEN + r0 + 8) * DMODEL;
#pragma unroll
    for (int j = 0; j < 8; j++) {
        const int col = h * DKH + j * 8 + 2 * (lane & 3);
        *(uint32_t*)(Of + row0 + col) =
            pack2h(__float2half_rn(o[j][0] * inv0),
                   __float2half_rn(o[j][1] * inv0));
        *(uint32_t*)(Of + row1 + col) =
            pack2h(__float2half_rn(o[j][2] * inv1),
                   __float2half_rn(o[j][3] * inv1));
    }
}

// ---------------------------------------------------------------------------
extern "C" void kernel_launch(void* const* d_in, const int* in_sizes, int n_in,
                              void* d_out, int out_size)
{
    const float* query = (const float*)d_in[0];
    const float* key   = (const float*)d_in[1];
    const float* value = (const float*)d_in[2];
    const int*   mask  = (const int*)d_in[3];
    const float* Wmat[4] = {(const float*)d_in[4], (const float*)d_in[6],
                            (const float*)d_in[8], (const float*)d_in[10]};
    const float* bvec[4] = {(const float*)d_in[5], (const float*)d_in[7],
                            (const float*)d_in[9], (const float*)d_in[11]};
    float* out = (float*)d_out;

    __half *aall, *wh, *qf, *kf, *vf;
    int *idxp, *cntp;
    cudaGetSymbolAddress((void**)&aall, g_a);
    cudaGetSymbolAddress((void**)&wh, g_wh);
    cudaGetSymbolAddress((void**)&qf, g_qf);
    cudaGetSymbolAddress((void**)&kf, g_kf);
    cudaGetSymbolAddress((void**)&vf, g_vf);
    cudaGetSymbolAddress((void**)&idxp, g_idx);
    cudaGetSymbolAddress((void**)&cntp, g_cnt);

    cudaFuncSetAttribute(gemm_qkv_kernel,
                         cudaFuncAttributeMaxDynamicSharedMemorySize, GEMM_SMEM);
    cudaFuncSetAttribute(gemm_out_kernel,
                         cudaFuncAttributeMaxDynamicSharedMemorySize, GEMM_SMEM);
    cudaFuncSetAttribute(flash_mma_kernel,
                         cudaFuncAttributeMaxDynamicSharedMemorySize, FLASH_SMEM);

    const int nwAll4 = 4 * DMODEL * DMODEL / 4;

    mask_scan_kernel<<<BATCH, 1024>>>(mask, idxp, cntp);
    split_w_kernel<<<(nwAll4 + 255) / 256, 256>>>(
        (const float4*)Wmat[0], (const float4*)Wmat[1],
        (const float4*)Wmat[2], (const float4*)Wmat[3], (uint2*)wh);

    // fused prep: convert query + gather/convert key,value (fp16 planes)
    dim3 pg(MROWS / 8, 3);
    prep_kernel<<<pg, 256>>>(query, key, value, idxp, cntp,
                             (uint2*)(aall + 0 * (size_t)MROWS * DMODEL),
                             (uint2*)(aall + 1 * (size_t)MROWS * DMODEL),
                             (uint2*)(aall + 2 * (size_t)MROWS * DMODEL));

    // fused QKV projections -> fp16 head-split operands
    dim3 gq(DMODEL / 128, MROWS / 128, 3);
    gemm_qkv_kernel<<<gq, 512, GEMM_SMEM>>>(
        aall, wh, bvec[0], bvec[1], bvec[2], qf, kf, vf, cntp);

    // attention (writes fp16 plane into aall[0], consumed by out-projection)
    dim3 fg(S_LEN / 128, BATCH * HEADS);
    flash_mma_kernel<<<fg, 256, FLASH_SMEM>>>(qf, kf, vf, cntp, aall);

    // output projection
    dim3 gg(DMODEL / 128, MROWS / 128);
    gemm_out_kernel<<<gg, 512, GEMM_SMEM>>>(
        aall, wh + 3 * (size_t)DMODEL * DMODEL, bvec[3], out);
}